// round 9
// baseline (speedup 1.0000x reference)
#include <cuda_runtime.h>
#include <cuda_fp16.h>
#include <math.h>
#include <stdint.h>

#define HH 16
#define NN 4096
#define DD 64
#define MM 256
#define ROWS (HH * NN)          // 65536

#define NORMALIZER 0.35355339059327373f  // 64^-0.25
#define DIAG_COEF  0.0625f               // 0.5 * 64^-0.5
#define RATIO      0.0625f               // 256^-0.5
#define FEPS       1e-4f
#define HSCALE     2048.0f               // lift fp16 features out of subnormals
#define HUNSCALE   (1.0f / 4194304.0f)   // 2^-22

// ---------------- scratch (device globals; no allocation allowed) -------------
__device__ float  g_qp[(size_t)ROWS * MM];
__device__ float  g_kp[(size_t)ROWS * MM];
__device__ __half g_qph[(size_t)ROWS * MM];
__device__ __half g_kph[(size_t)ROWS * MM];
__device__ float  g_qdiag[ROWS];
__device__ float  g_kdiag[ROWS];
__device__ float  g_ksum[HH * MM];
__device__ float  g_dinv[ROWS];
__device__ float  g_ctx[HH * MM * DD];
__device__ float  g_kpart[1024];
__device__ float  g_kmax[1];

__device__ __forceinline__ float to_tf32(float x) {
    uint32_t r;
    asm("cvt.rna.tf32.f32 %0, %1;" : "=r"(r) : "f"(x));
    return __uint_as_float(r);
}
__device__ __forceinline__ uint32_t to_tf32_u(float x) {
    uint32_t r;
    asm("cvt.rna.tf32.f32 %0, %1;" : "=r"(r) : "f"(x));
    return r;
}
__device__ __forceinline__ uint32_t smem_u32(const void* p) {
    uint32_t a;
    asm("{ .reg .u64 t; cvta.to.shared.u64 t, %1; cvt.u32.u64 %0, t; }" : "=r"(a) : "l"(p));
    return a;
}
__device__ __forceinline__ void cp_async16(uint32_t dst, const void* src) {
    asm volatile("cp.async.ca.shared.global [%0], [%1], 16;" :: "r"(dst), "l"(src) : "memory");
}
__device__ __forceinline__ void cp_commit() {
    asm volatile("cp.async.commit_group;" ::: "memory");
}
template <int N> __device__ __forceinline__ void cp_wait() {
    asm volatile("cp.async.wait_group %0;" :: "n"(N) : "memory");
}
__device__ __forceinline__ void mma_tf32_16x8x8(float* d, const uint32_t* a, const uint32_t* b) {
    asm volatile(
        "mma.sync.aligned.m16n8k8.row.col.f32.tf32.tf32.f32 "
        "{%0,%1,%2,%3}, {%4,%5,%6,%7}, {%8,%9}, {%0,%1,%2,%3};"
        : "+f"(d[0]), "+f"(d[1]), "+f"(d[2]), "+f"(d[3])
        : "r"(a[0]), "r"(a[1]), "r"(a[2]), "r"(a[3]), "r"(b[0]), "r"(b[1]));
}
__device__ __forceinline__ void mma_f16_16x8x16(float* d, const uint32_t* a, const uint32_t* b) {
    asm volatile(
        "mma.sync.aligned.m16n8k16.row.col.f32.f16.f16.f32 "
        "{%0,%1,%2,%3}, {%4,%5,%6,%7}, {%8,%9}, {%0,%1,%2,%3};"
        : "+f"(d[0]), "+f"(d[1]), "+f"(d[2]), "+f"(d[3])
        : "r"(a[0]), "r"(a[1]), "r"(a[2]), "r"(a[3]), "r"(b[0]), "r"(b[1]));
}
#define LDSM_X4(r0, r1, r2, r3, addr) \
    asm volatile("ldmatrix.sync.aligned.m8n8.x4.shared.b16 {%0,%1,%2,%3}, [%4];" \
                 : "=r"(r0), "=r"(r1), "=r"(r2), "=r"(r3) : "r"(addr))

// ---------------- zero accumulated scratch -------------------------------------
__global__ void zero_kernel() {
    int i = blockIdx.x * 256 + threadIdx.x;
    if (i < HH * MM) g_ksum[i] = 0.f;
    g_ctx[i] = 0.f;
}

// ========== projections via 3xTF32 split: dash = alpha * X @ proj^T ===========
#define PJ_PITCH 36
#define PJ_TILE  (128 * PJ_PITCH)
#define PJ_SMEM  (4 * PJ_TILE * 4)     // Ah, Al, Bh, Bl

__global__ __launch_bounds__(256) void proj_mma(
    const float* __restrict__ X, const float* __restrict__ P, float* __restrict__ C)
{
    extern __shared__ float sm[];
    float* Ah = sm;
    float* Al = sm + PJ_TILE;
    float* Bh = sm + 2 * PJ_TILE;
    float* Bl = sm + 3 * PJ_TILE;

    const int t    = threadIdx.x;
    const int lane = t & 31;
    const int w    = t >> 5;
    const int wm   = w & 3;
    const int wn   = w >> 2;
    const int grp  = lane >> 2;
    const int tig  = lane & 3;

    const long i0 = (long)blockIdx.x * 128;
    const int  j0 = blockIdx.y * 128;

    const int lrow = t >> 3;
    const int lcol = (t & 7) * 4;

    float acc[2][8][4];
#pragma unroll
    for (int mi = 0; mi < 2; ++mi)
#pragma unroll
        for (int ni = 0; ni < 8; ++ni)
#pragma unroll
            for (int r = 0; r < 4; ++r) acc[mi][ni][r] = 0.f;

#pragma unroll
    for (int c = 0; c < 2; ++c) {
        const int kof = c * 32;
#pragma unroll
        for (int i = 0; i < 4; ++i) {
            int row = i * 32 + lrow;
            float4 va = *(const float4*)(X + (i0 + row) * DD + kof + lcol);
            float4 vb = *(const float4*)(P + (long)(j0 + row) * DD + kof + lcol);
            float4 ah, al, bh, bl;
            ah.x = to_tf32(va.x); al.x = to_tf32(va.x - ah.x);
            ah.y = to_tf32(va.y); al.y = to_tf32(va.y - ah.y);
            ah.z = to_tf32(va.z); al.z = to_tf32(va.z - ah.z);
            ah.w = to_tf32(va.w); al.w = to_tf32(va.w - ah.w);
            bh.x = to_tf32(vb.x); bl.x = to_tf32(vb.x - bh.x);
            bh.y = to_tf32(vb.y); bl.y = to_tf32(vb.y - bh.y);
            bh.z = to_tf32(vb.z); bl.z = to_tf32(vb.z - bh.z);
            bh.w = to_tf32(vb.w); bl.w = to_tf32(vb.w - bh.w);
            *(float4*)&Ah[row * PJ_PITCH + lcol] = ah;
            *(float4*)&Al[row * PJ_PITCH + lcol] = al;
            *(float4*)&Bh[row * PJ_PITCH + lcol] = bh;
            *(float4*)&Bl[row * PJ_PITCH + lcol] = bl;
        }
        __syncthreads();

#pragma unroll
        for (int ks = 0; ks < 4; ++ks) {
            const int k0 = ks * 8;
            uint32_t ahr[2][4], alr[2][4];
#pragma unroll
            for (int mi = 0; mi < 2; ++mi) {
                int m = wm * 32 + mi * 16 + grp;
                ahr[mi][0] = __float_as_uint(Ah[m * PJ_PITCH + k0 + tig]);
                ahr[mi][1] = __float_as_uint(Ah[(m + 8) * PJ_PITCH + k0 + tig]);
                ahr[mi][2] = __float_as_uint(Ah[m * PJ_PITCH + k0 + tig + 4]);
                ahr[mi][3] = __float_as_uint(Ah[(m + 8) * PJ_PITCH + k0 + tig + 4]);
                alr[mi][0] = __float_as_uint(Al[m * PJ_PITCH + k0 + tig]);
                alr[mi][1] = __float_as_uint(Al[(m + 8) * PJ_PITCH + k0 + tig]);
                alr[mi][2] = __float_as_uint(Al[m * PJ_PITCH + k0 + tig + 4]);
                alr[mi][3] = __float_as_uint(Al[(m + 8) * PJ_PITCH + k0 + tig + 4]);
            }
#pragma unroll
            for (int ni = 0; ni < 8; ++ni) {
                int n = wn * 64 + ni * 8 + grp;
                uint32_t bhr[2], blr[2];
                bhr[0] = __float_as_uint(Bh[n * PJ_PITCH + k0 + tig]);
                bhr[1] = __float_as_uint(Bh[n * PJ_PITCH + k0 + tig + 4]);
                blr[0] = __float_as_uint(Bl[n * PJ_PITCH + k0 + tig]);
                blr[1] = __float_as_uint(Bl[n * PJ_PITCH + k0 + tig + 4]);
#pragma unroll
                for (int mi = 0; mi < 2; ++mi) {
                    mma_tf32_16x8x8(acc[mi][ni], ahr[mi], blr);
                    mma_tf32_16x8x8(acc[mi][ni], alr[mi], bhr);
                    mma_tf32_16x8x8(acc[mi][ni], ahr[mi], bhr);
                }
            }
        }
        __syncthreads();
    }

#pragma unroll
    for (int mi = 0; mi < 2; ++mi) {
        long row = i0 + wm * 32 + mi * 16 + grp;
#pragma unroll
        for (int ni = 0; ni < 8; ++ni) {
            long col = j0 + wn * 64 + ni * 8 + tig * 2;
            *(float2*)(C + row * MM + col) =
                make_float2(acc[mi][ni][0] * NORMALIZER, acc[mi][ni][1] * NORMALIZER);
            *(float2*)(C + (row + 8) * MM + col) =
                make_float2(acc[mi][ni][2] * NORMALIZER, acc[mi][ni][3] * NORMALIZER);
        }
    }
}

// ============ weights[h] = qp[h] @ kp[h]^T via mma.sync fp16 + ldmatrix ========
#define WF_PITCH 40
#define WF_ABUF  (256 * WF_PITCH)       // halves per A stage
#define WF_BBUF  (128 * WF_PITCH)       // halves per B stage
#define WF_SMEM  ((2 * WF_ABUF + 2 * WF_BBUF) * 2)   // 61440 B

__global__ __launch_bounds__(256) void weights_mma(
    const __half* __restrict__ qp, const __half* __restrict__ kp, float* __restrict__ outw)
{
    extern __shared__ __half smh[];
    __half* As = smh;                   // [2][256][40]
    __half* Bs = smh + 2 * WF_ABUF;     // [2][128][40]

    const int t    = threadIdx.x;
    const int lane = t & 31;
    const int w    = t >> 5;
    const int wm   = w & 3;             // 4 warps in M (64 rows each)
    const int wn   = w >> 2;            // 2 warps in N (64 cols each)
    const int grp  = lane >> 2;
    const int tig  = lane & 3;

    // ldmatrix per-lane address decomposition: matrix idx g = lane>>3, row r = lane&7
    const int lr8     = lane & 7;
    const int lg      = lane >> 3;
    const int rowOff  = (lg & 1) * 8 + lr8;   // row within 16-row fragment
    const int colOff  = (lg >> 1) * 8;        // k offset (0 or 8)

    const int h   = blockIdx.z;
    const long i0 = (long)blockIdx.y * 256;
    const long j0 = (long)blockIdx.x * 128;

    const __half* Ag = qp + ((long)h * NN + i0) * MM;
    const __half* Bg = kp + ((long)h * NN + j0) * MM;

    const int arow = t >> 2;            // 0..63
    const int ac8  = (t & 3) * 8;       // halves offset (8 halves = 16B)

    float acc[4][8][4];
#pragma unroll
    for (int mi = 0; mi < 4; ++mi)
#pragma unroll
        for (int ni = 0; ni < 8; ++ni)
#pragma unroll
            for (int r = 0; r < 4; ++r) acc[mi][ni][r] = 0.f;

    uint32_t As_u = smem_u32(As);
    uint32_t Bs_u = smem_u32(Bs);

    // prologue: chunk 0 -> buffer 0
#pragma unroll
    for (int i = 0; i < 4; ++i) {
        int row = i * 64 + arow;
        cp_async16(As_u + (row * WF_PITCH + ac8) * 2, Ag + (long)row * MM + ac8);
    }
#pragma unroll
    for (int i = 0; i < 2; ++i) {
        int row = i * 64 + arow;
        cp_async16(Bs_u + (row * WF_PITCH + ac8) * 2, Bg + (long)row * MM + ac8);
    }
    cp_commit();

#pragma unroll 1
    for (int c = 0; c < 8; ++c) {
        cp_wait<0>();
        __syncthreads();
        if (c < 7) {
            const int kof = (c + 1) * 32;
            const uint32_t ab = ((c + 1) & 1) * WF_ABUF * 2;
            const uint32_t bb = ((c + 1) & 1) * WF_BBUF * 2;
#pragma unroll
            for (int i = 0; i < 4; ++i) {
                int row = i * 64 + arow;
                cp_async16(As_u + ab + (row * WF_PITCH + ac8) * 2,
                           Ag + (long)row * MM + kof + ac8);
            }
#pragma unroll
            for (int i = 0; i < 2; ++i) {
                int row = i * 64 + arow;
                cp_async16(Bs_u + bb + (row * WF_PITCH + ac8) * 2,
                           Bg + (long)row * MM + kof + ac8);
            }
            cp_commit();
        }

        const uint32_t AbU = As_u + (c & 1) * WF_ABUF * 2;
        const uint32_t BbU = Bs_u + (c & 1) * WF_BBUF * 2;

#pragma unroll
        for (int ks = 0; ks < 2; ++ks) {
            const int k0 = ks * 16;
            uint32_t a[4][4];
#pragma unroll
            for (int mi = 0; mi < 4; ++mi) {
                int m = wm * 64 + mi * 16 + rowOff;
                uint32_t addr = AbU + (uint32_t)(m * WF_PITCH + k0 + colOff) * 2;
                LDSM_X4(a[mi][0], a[mi][1], a[mi][2], a[mi][3], addr);
            }
            uint32_t b[8][2];
#pragma unroll
            for (int p = 0; p < 4; ++p) {
                int n = wn * 64 + p * 16 + rowOff;
                uint32_t addr = BbU + (uint32_t)(n * WF_PITCH + k0 + colOff) * 2;
                uint32_t r0, r1, r2, r3;
                LDSM_X4(r0, r1, r2, r3, addr);
                b[2 * p][0]     = r0;   // rows n..n+7,   k0-7
                b[2 * p + 1][0] = r1;   // rows n+8..15,  k0-7
                b[2 * p][1]     = r2;   // rows n..n+7,   k8-15
                b[2 * p + 1][1] = r3;   // rows n+8..15,  k8-15
            }
#pragma unroll
            for (int mi = 0; mi < 4; ++mi)
#pragma unroll
                for (int ni = 0; ni < 8; ++ni)
                    mma_f16_16x8x16(acc[mi][ni], a[mi], b[ni]);
        }
    }

    float* Cp = outw + (long)h * NN * NN;
#pragma unroll
    for (int mi = 0; mi < 4; ++mi) {
        long row = i0 + wm * 64 + mi * 16 + grp;
#pragma unroll
        for (int ni = 0; ni < 8; ++ni) {
            long col = j0 + wn * 64 + ni * 8 + tig * 2;
            *(float2*)(Cp + row * NN + col) =
                make_float2(acc[mi][ni][0] * HUNSCALE, acc[mi][ni][1] * HUNSCALE);
            *(float2*)(Cp + (row + 8) * NN + col) =
                make_float2(acc[mi][ni][2] * HUNSCALE, acc[mi][ni][3] * HUNSCALE);
        }
    }
}

// ======= ctx[h][m][e] = sum_n kp[h][n][m] * v[h][n][e]  via mma tf32 ==========
#define CTX_KSPLIT 16
#define CTX_KC     32
#define KS_PITCH   260
#define VS_PITCH   68
#define KS_BUF     (CTX_KC * KS_PITCH)
#define VS_BUF     (CTX_KC * VS_PITCH)
#define CTX_SMEM   ((2 * KS_BUF + 2 * VS_BUF) * 4)

__global__ __launch_bounds__(256) void ctx_mma(
    const float* __restrict__ kp, const float* __restrict__ v, float* __restrict__ ctx)
{
    extern __shared__ float sm[];
    float* Ks = sm;                    // [2][32][260]
    float* Vs = sm + 2 * KS_BUF;       // [2][32][68]

    const int t    = threadIdx.x;
    const int lane = t & 31;
    const int w    = t >> 5;
    const int wm   = w & 3;
    const int we   = w >> 2;
    const int grp  = lane >> 2;
    const int tig  = lane & 3;

    const int h     = blockIdx.z;
    const int nbase = blockIdx.y * (NN / CTX_KSPLIT);

    const float* Kg = kp + ((long)h * NN + nbase) * MM;
    const float* Vg = v  + ((long)h * NN + nbase) * DD;

    const int krow = t >> 3;
    const int c4   = t & 7;

    float acc[4][4][4];
#pragma unroll
    for (int mi = 0; mi < 4; ++mi)
#pragma unroll
        for (int ni = 0; ni < 4; ++ni)
#pragma unroll
            for (int r = 0; r < 4; ++r) acc[mi][ni][r] = 0.f;

    uint32_t Ks_u = smem_u32(Ks);
    uint32_t Vs_u = smem_u32(Vs);

#pragma unroll
    for (int i = 0; i < 8; ++i)
        cp_async16(Ks_u + (krow * KS_PITCH + (c4 + i * 8) * 4) * 4,
                   Kg + (long)krow * MM + (c4 + i * 8) * 4);
#pragma unroll
    for (int i = 0; i < 2; ++i)
        cp_async16(Vs_u + (krow * VS_PITCH + (c4 + i * 8) * 4) * 4,
                   Vg + (long)krow * DD + (c4 + i * 8) * 4);
    cp_commit();

#pragma unroll 1
    for (int c = 0; c < 8; ++c) {
        cp_wait<0>();
        __syncthreads();
        if (c < 7) {
            const int nof = (c + 1) * CTX_KC;
            const uint32_t kb = ((c + 1) & 1) * KS_BUF * 4;
            const uint32_t vb = ((c + 1) & 1) * VS_BUF * 4;
#pragma unroll
            for (int i = 0; i < 8; ++i)
                cp_async16(Ks_u + kb + (krow * KS_PITCH + (c4 + i * 8) * 4) * 4,
                           Kg + (long)(nof + krow) * MM + (c4 + i * 8) * 4);
#pragma unroll
            for (int i = 0; i < 2; ++i)
                cp_async16(Vs_u + vb + (krow * VS_PITCH + (c4 + i * 8) * 4) * 4,
                           Vg + (long)(nof + krow) * DD + (c4 + i * 8) * 4);
            cp_commit();
        }

        const float* Kb = Ks + (c & 1) * KS_BUF;
        const float* Vb = Vs + (c & 1) * VS_BUF;

#pragma unroll
        for (int ks = 0; ks < 4; ++ks) {
            const int k0 = ks * 8;
            uint32_t a[4][4];
#pragma unroll
            for (int mi = 0; mi < 4; ++mi) {
                int m = wm * 64 + mi * 16 + grp;
                a[mi][0] = __float_as_uint(Kb[(k0 + tig) * KS_PITCH + m]);
                a[mi][1] = __float_as_uint(Kb[(k0 + tig) * KS_PITCH + m + 8]);
                a[mi][2] = __float_as_uint(Kb[(k0 + tig + 4) * KS_PITCH + m]);
                a[mi][3] = __float_as_uint(Kb[(k0 + tig + 4) * KS_PITCH + m + 8]);
            }
            uint32_t b[4][2];
#pragma unroll
            for (int ni = 0; ni < 4; ++ni) {
                int e = we * 32 + ni * 8 + grp;
                b[ni][0] = to_tf32_u(Vb[(k0 + tig) * VS_PITCH + e]);
                b[ni][1] = to_tf32_u(Vb[(k0 + tig + 4) * VS_PITCH + e]);
            }
#pragma unroll
            for (int mi = 0; mi < 4; ++mi)
#pragma unroll
                for (int ni = 0; ni < 4; ++ni)
                    mma_tf32_16x8x8(acc[mi][ni], a[mi], b[ni]);
        }
    }

#pragma unroll
    for (int mi = 0; mi < 4; ++mi) {
        int m = wm * 64 + mi * 16 + grp;
#pragma unroll
        for (int ni = 0; ni < 4; ++ni) {
            int e = we * 32 + ni * 8 + tig * 2;
            float* p0 = &ctx[((long)h * MM + m) * DD + e];
            float* p1 = &ctx[((long)h * MM + m + 8) * DD + e];
            atomicAdd(p0,     acc[mi][ni][0]);
            atomicAdd(p0 + 1, acc[mi][ni][1]);
            atomicAdd(p1,     acc[mi][ni][2]);
            atomicAdd(p1 + 1, acc[mi][ni][3]);
        }
    }
}

// ======= out[h][n][e] = dinv[n] * sum_m qp[h][n][m] * ctx[h][m][e]  (mma) =====
#define OQ_PITCH 36
#define OC_PITCH 68
#define OQ_BUF   (128 * OQ_PITCH)
#define OC_BUF   (32 * OC_PITCH)
#define OUT_SMEM ((2 * OQ_BUF + 2 * OC_BUF) * 4)

__global__ __launch_bounds__(256) void out_mma(
    const float* __restrict__ qp, const float* __restrict__ ctx,
    const float* __restrict__ dinv, float* __restrict__ out)
{
    extern __shared__ float sm[];
    float* Qs = sm;                    // [2][128][36]
    float* Cs = sm + 2 * OQ_BUF;       // [2][32][68]

    const int t    = threadIdx.x;
    const int lane = t & 31;
    const int w    = t >> 5;
    const int wn   = w & 3;
    const int we   = w >> 2;
    const int grp  = lane >> 2;
    const int tig  = lane & 3;

    const int h  = blockIdx.y;
    const long n0 = (long)blockIdx.x * 128;

    const float* Qg = qp  + ((long)h * NN + n0) * MM;
    const float* Cg = ctx + (long)h * MM * DD;

    const int lrow = t >> 3;
    const int lcol = (t & 7) * 4;
    const int crow = t >> 3;
    const int cc4  = t & 7;

    float acc[2][4][4];
#pragma unroll
    for (int mi = 0; mi < 2; ++mi)
#pragma unroll
        for (int ni = 0; ni < 4; ++ni)
#pragma unroll
            for (int r = 0; r < 4; ++r) acc[mi][ni][r] = 0.f;

    uint32_t Qs_u = smem_u32(Qs);
    uint32_t Cs_u = smem_u32(Cs);

#pragma unroll
    for (int i = 0; i < 4; ++i) {
        int row = i * 32 + lrow;
        cp_async16(Qs_u + (row * OQ_PITCH + lcol) * 4, Qg + (long)row * MM + lcol);
    }
#pragma unroll
    for (int i = 0; i < 2; ++i)
        cp_async16(Cs_u + (crow * OC_PITCH + (cc4 + i * 8) * 4) * 4,
                   Cg + (long)crow * DD + (cc4 + i * 8) * 4);
    cp_commit();

#pragma unroll 1
    for (int c = 0; c < 8; ++c) {
        cp_wait<0>();
        __syncthreads();
        if (c < 7) {
            const int kof = (c + 1) * 32;
            const uint32_t qb = ((c + 1) & 1) * OQ_BUF * 4;
            const uint32_t cb = ((c + 1) & 1) * OC_BUF * 4;
#pragma unroll
            for (int i = 0; i < 4; ++i) {
                int row = i * 32 + lrow;
                cp_async16(Qs_u + qb + (row * OQ_PITCH + lcol) * 4,
                           Qg + (long)row * MM + kof + lcol);
            }
#pragma unroll
            for (int i = 0; i < 2; ++i)
                cp_async16(Cs_u + cb + (crow * OC_PITCH + (cc4 + i * 8) * 4) * 4,
                           Cg + (long)(kof + crow) * DD + (cc4 + i * 8) * 4);
            cp_commit();
        }

        const float* Qb = Qs + (c & 1) * OQ_BUF;
        const float* Cb = Cs + (c & 1) * OC_BUF;

#pragma unroll
        for (int ks = 0; ks < 4; ++ks) {
            const int k0 = ks * 8;
            uint32_t a[2][4];
#pragma unroll
            for (int mi = 0; mi < 2; ++mi) {
                int n = wn * 32 + mi * 16 + grp;
                a[mi][0] = __float_as_uint(Qb[n * OQ_PITCH + k0 + tig]);
                a[mi][1] = __float_as_uint(Qb[(n + 8) * OQ_PITCH + k0 + tig]);
                a[mi][2] = __float_as_uint(Qb[n * OQ_PITCH + k0 + tig + 4]);
                a[mi][3] = __float_as_uint(Qb[(n + 8) * OQ_PITCH + k0 + tig + 4]);
            }
            uint32_t b[4][2];
#pragma unroll
            for (int ni = 0; ni < 4; ++ni) {
                int e = we * 32 + ni * 8 + grp;
                b[ni][0] = to_tf32_u(Cb[(k0 + tig) * OC_PITCH + e]);
                b[ni][1] = to_tf32_u(Cb[(k0 + tig + 4) * OC_PITCH + e]);
            }
#pragma unroll
            for (int mi = 0; mi < 2; ++mi)
#pragma unroll
                for (int ni = 0; ni < 4; ++ni)
                    mma_tf32_16x8x8(acc[mi][ni], a[mi], b[ni]);
        }
    }

#pragma unroll
    for (int mi = 0; mi < 2; ++mi) {
        long n = n0 + wn * 32 + mi * 16 + grp;
        float dv0 = dinv[(long)h * NN + n];
        float dv1 = dinv[(long)h * NN + n + 8];
#pragma unroll
        for (int ni = 0; ni < 4; ++ni) {
            int e = we * 32 + ni * 8 + tig * 2;
            *(float2*)(out + ((long)h * NN + n) * DD + e) =
                make_float2(acc[mi][ni][0] * dv0, acc[mi][ni][1] * dv0);
            *(float2*)(out + ((long)h * NN + n + 8) * DD + e) =
                make_float2(acc[mi][ni][2] * dv1, acc[mi][ni][3] * dv1);
        }
    }
}

// ---------------- diag / kmax / exp / dinv -------------------------------------
__global__ void diag_kernel(const float* __restrict__ x, float* __restrict__ out) {
    int row  = blockIdx.x * 8 + (threadIdx.x >> 5);
    int lane = threadIdx.x & 31;
    const float* p = x + (long)row * DD;
    float a = p[lane], b = p[lane + 32];
    float s = a * a + b * b;
#pragma unroll
    for (int o = 16; o; o >>= 1) s += __shfl_xor_sync(0xffffffffu, s, o);
    if (!lane) out[row] = s * DIAG_COEF;
}

__global__ void kmax1_kernel(const float* __restrict__ d, float* __restrict__ part, int n) {
    float m = -3.4e38f;
    for (int i = blockIdx.x * blockDim.x + threadIdx.x; i < n; i += gridDim.x * blockDim.x)
        m = fmaxf(m, d[i]);
    __shared__ float sm[8];
#pragma unroll
    for (int o = 16; o; o >>= 1) m = fmaxf(m, __shfl_xor_sync(0xffffffffu, m, o));
    if ((threadIdx.x & 31) == 0) sm[threadIdx.x >> 5] = m;
    __syncthreads();
    if (threadIdx.x == 0) {
        float b = sm[0];
#pragma unroll
        for (int w = 1; w < 8; ++w) b = fmaxf(b, sm[w]);
        part[blockIdx.x] = b;
    }
}

__global__ void kmax2_kernel(const float* __restrict__ part, float* __restrict__ out, int n) {
    float m = -3.4e38f;
    for (int i = threadIdx.x; i < n; i += 256) m = fmaxf(m, part[i]);
    __shared__ float sm[8];
#pragma unroll
    for (int o = 16; o; o >>= 1) m = fmaxf(m, __shfl_xor_sync(0xffffffffu, m, o));
    if ((threadIdx.x & 31) == 0) sm[threadIdx.x >> 5] = m;
    __syncthreads();
    if (threadIdx.x == 0) {
        float b = sm[0];
#pragma unroll
        for (int w = 1; w < 8; ++w) b = fmaxf(b, sm[w]);
        out[0] = b;
    }
}

// exp kernels also emit scaled-fp16 copies of the features for the weights GEMM
__global__ void expq_kernel(float* __restrict__ dash, const float* __restrict__ diag,
                            __half* __restrict__ dash_h) {
    long row = blockIdx.x;
    int  t   = threadIdx.x;
    long idx = row * MM + t;
    float x = dash[idx];
    float m = x;
#pragma unroll
    for (int o = 16; o; o >>= 1) m = fmaxf(m, __shfl_xor_sync(0xffffffffu, m, o));
    __shared__ float sm[8];
    if ((t & 31) == 0) sm[t >> 5] = m;
    __syncthreads();
    float bm = sm[0];
#pragma unroll
    for (int w = 1; w < 8; ++w) bm = fmaxf(bm, sm[w]);
    float v = RATIO * (expf(x - diag[row] - bm) + FEPS);
    dash[idx]   = to_tf32(v);
    dash_h[idx] = __float2half_rn(v * HSCALE);
}

__global__ void expk_kernel(float* __restrict__ dash, const float* __restrict__ diag,
                            const float* __restrict__ kmax, float* __restrict__ ksum,
                            __half* __restrict__ dash_h) {
    int t    = threadIdx.x;
    int row0 = blockIdx.x * 64;
    int h    = row0 >> 12;
    float stab  = kmax[0];
    float local = 0.f;
    for (int r = 0; r < 64; ++r) {
        long idx = (long)(row0 + r) * MM + t;
        float vfull = RATIO * (expf(dash[idx] - diag[row0 + r] - stab) + FEPS);
        float vv = to_tf32(vfull);
        dash[idx]   = vv;
        dash_h[idx] = __float2half_rn(vfull * HSCALE);
        local += vv;
    }
    atomicAdd(&ksum[h * MM + t], local);
}

__global__ void dinv_kernel(const float* __restrict__ qp, const float* __restrict__ ksum,
                            float* __restrict__ dinv) {
    int row  = blockIdx.x * 8 + (threadIdx.x >> 5);
    int lane = threadIdx.x & 31;
    int h    = row >> 12;
    const float* qr = qp + (long)row * MM;
    const float* ks = ksum + h * MM;
    float s = 0.f;
#pragma unroll
    for (int i = 0; i < 8; ++i) {
        int m = lane + i * 32;
        s += qr[m] * ks[m];
    }
#pragma unroll
    for (int o = 16; o; o >>= 1) s += __shfl_xor_sync(0xffffffffu, s, o);
    if (!lane) dinv[row] = 1.f / s;
}

// -------------------------------------------------------------------------------
extern "C" void kernel_launch(void* const* d_in, const int* in_sizes, int n_in,
                              void* d_out, int out_size)
{
    const float* q    = (const float*)d_in[0];
    const float* k    = (const float*)d_in[1];
    const float* v    = (const float*)d_in[2];
    const float* proj = (const float*)d_in[3];

    float* out_align = (float*)d_out;                       // [H,N,D]
    float* out_w     = out_align + (long)HH * NN * DD;      // [H,N,N]

    float *qp, *kp, *qdiag, *kdiag, *ksum, *dinv, *ctx, *kpart, *kmax;
    __half *qph, *kph;
    cudaGetSymbolAddress((void**)&qp,    g_qp);
    cudaGetSymbolAddress((void**)&kp,    g_kp);
    cudaGetSymbolAddress((void**)&qph,   g_qph);
    cudaGetSymbolAddress((void**)&kph,   g_kph);
    cudaGetSymbolAddress((void**)&qdiag, g_qdiag);
    cudaGetSymbolAddress((void**)&kdiag, g_kdiag);
    cudaGetSymbolAddress((void**)&ksum,  g_ksum);
    cudaGetSymbolAddress((void**)&dinv,  g_dinv);
    cudaGetSymbolAddress((void**)&ctx,   g_ctx);
    cudaGetSymbolAddress((void**)&kpart, g_kpart);
    cudaGetSymbolAddress((void**)&kmax,  g_kmax);

    static cudaStream_t s2 = nullptr;
    static cudaEvent_t  ev1, ev2;
    static bool attr_done = false;
    if (!attr_done) {
        cudaFuncSetAttribute(weights_mma, cudaFuncAttributeMaxDynamicSharedMemorySize, WF_SMEM);
        cudaFuncSetAttribute(proj_mma,    cudaFuncAttributeMaxDynamicSharedMemorySize, PJ_SMEM);
        cudaFuncSetAttribute(ctx_mma,     cudaFuncAttributeMaxDynamicSharedMemorySize, CTX_SMEM);
        cudaFuncSetAttribute(out_mma,     cudaFuncAttributeMaxDynamicSharedMemorySize, OUT_SMEM);
        cudaStreamCreateWithFlags(&s2, cudaStreamNonBlocking);
        cudaEventCreateWithFlags(&ev1, cudaEventDisableTiming);
        cudaEventCreateWithFlags(&ev2, cudaEventDisableTiming);
        attr_done = true;
    }

    zero_kernel<<<HH * MM * DD / 256, 256>>>();

    proj_mma<<<dim3(ROWS / 128, MM / 128), 256, PJ_SMEM>>>(q, proj, qp);
    proj_mma<<<dim3(ROWS / 128, MM / 128), 256, PJ_SMEM>>>(k, proj, kp);

    diag_kernel<<<ROWS / 8, 256>>>(q, qdiag);
    diag_kernel<<<ROWS / 8, 256>>>(k, kdiag);

    kmax1_kernel<<<1024, 256>>>(kp, kpart, ROWS * MM);
    kmax2_kernel<<<1, 256>>>(kpart, kmax, 1024);

    expq_kernel<<<ROWS, 256>>>(qp, qdiag, qph);
    expk_kernel<<<ROWS / 64, 256>>>(kp, kdiag, kmax, ksum, kph);

    // fork: side stream runs the small ctx->dinv->out chain concurrently with
    // the dominant weights GEMM on the main (capture) stream.
    cudaEventRecord(ev1, 0);
    cudaStreamWaitEvent(s2, ev1, 0);

    weights_mma<<<dim3(NN / 128, NN / 256, HH), 256, WF_SMEM>>>(qph, kph, out_w);

    ctx_mma<<<dim3(1, CTX_KSPLIT, HH), 256, CTX_SMEM, s2>>>(kp, v, ctx);
    dinv_kernel<<<ROWS / 8, 256, 0, s2>>>(qp, ksum, dinv);
    out_mma<<<dim3(NN / 128, HH), 256, OUT_SMEM, s2>>>(qp, ctx, dinv, out_align);

    cudaEventRecord(ev2, s2);
    cudaStreamWaitEvent(0, ev2, 0);
}

// round 10
// speedup vs baseline: 1.0391x; 1.0391x over previous
#include <cuda_runtime.h>
#include <cuda_fp16.h>
#include <math.h>
#include <stdint.h>

#define HH 16
#define NN 4096
#define DD 64
#define MM 256
#define ROWS (HH * NN)          // 65536

#define NORMALIZER 0.35355339059327373f  // 64^-0.25
#define DIAG_COEF  0.0625f               // 0.5 * 64^-0.5
#define RATIO      0.0625f               // 256^-0.5
#define FEPS       1e-4f
#define HSCALE     2048.0f               // lift fp16 features out of subnormals
#define HUNSCALE   (1.0f / 4194304.0f)   // 2^-22

// ---------------- scratch (device globals; no allocation allowed) -------------
__device__ float    g_qp[(size_t)ROWS * MM];
__device__ float    g_kp[(size_t)ROWS * MM];
__device__ __half   g_qph[(size_t)ROWS * MM];
__device__ __half   g_kph[(size_t)ROWS * MM];
__device__ float    g_qdiag[ROWS];
__device__ float    g_kdiag[ROWS];
__device__ float    g_ksum[HH * MM];
__device__ float    g_dinv[ROWS];
__device__ float    g_ctx[HH * MM * DD];
__device__ unsigned g_kmax_enc[1];

__device__ __forceinline__ float to_tf32(float x) {
    uint32_t r;
    asm("cvt.rna.tf32.f32 %0, %1;" : "=r"(r) : "f"(x));
    return __uint_as_float(r);
}
__device__ __forceinline__ uint32_t to_tf32_u(float x) {
    uint32_t r;
    asm("cvt.rna.tf32.f32 %0, %1;" : "=r"(r) : "f"(x));
    return r;
}
__device__ __forceinline__ uint32_t smem_u32(const void* p) {
    uint32_t a;
    asm("{ .reg .u64 t; cvta.to.shared.u64 t, %1; cvt.u32.u64 %0, t; }" : "=r"(a) : "l"(p));
    return a;
}
__device__ __forceinline__ void cp_async16(uint32_t dst, const void* src) {
    asm volatile("cp.async.ca.shared.global [%0], [%1], 16;" :: "r"(dst), "l"(src) : "memory");
}
__device__ __forceinline__ void cp_commit() {
    asm volatile("cp.async.commit_group;" ::: "memory");
}
template <int N> __device__ __forceinline__ void cp_wait() {
    asm volatile("cp.async.wait_group %0;" :: "n"(N) : "memory");
}
__device__ __forceinline__ void mma_tf32_16x8x8(float* d, const uint32_t* a, const uint32_t* b) {
    asm volatile(
        "mma.sync.aligned.m16n8k8.row.col.f32.tf32.tf32.f32 "
        "{%0,%1,%2,%3}, {%4,%5,%6,%7}, {%8,%9}, {%0,%1,%2,%3};"
        : "+f"(d[0]), "+f"(d[1]), "+f"(d[2]), "+f"(d[3])
        : "r"(a[0]), "r"(a[1]), "r"(a[2]), "r"(a[3]), "r"(b[0]), "r"(b[1]));
}
__device__ __forceinline__ void mma_f16_16x8x16(float* d, const uint32_t* a, const uint32_t* b) {
    asm volatile(
        "mma.sync.aligned.m16n8k16.row.col.f32.f16.f16.f32 "
        "{%0,%1,%2,%3}, {%4,%5,%6,%7}, {%8,%9}, {%0,%1,%2,%3};"
        : "+f"(d[0]), "+f"(d[1]), "+f"(d[2]), "+f"(d[3])
        : "r"(a[0]), "r"(a[1]), "r"(a[2]), "r"(a[3]), "r"(b[0]), "r"(b[1]));
}
#define LDSM_X4(r0, r1, r2, r3, addr) \
    asm volatile("ldmatrix.sync.aligned.m8n8.x4.shared.b16 {%0,%1,%2,%3}, [%4];" \
                 : "=r"(r0), "=r"(r1), "=r"(r2), "=r"(r3) : "r"(addr))

// monotonic float<->uint encoding for order-invariant atomic max (init = 0)
__device__ __forceinline__ unsigned enc_f(float f) {
    unsigned u = __float_as_uint(f);
    return (u & 0x80000000u) ? ~u : (u | 0x80000000u);
}
__device__ __forceinline__ float dec_f(unsigned u) {
    return (u & 0x80000000u) ? __uint_as_float(u ^ 0x80000000u) : __uint_as_float(~u);
}

// ---------------- zero accumulated scratch -------------------------------------
__global__ void zero_kernel() {
    int i = blockIdx.x * 256 + threadIdx.x;
    if (i < HH * MM) g_ksum[i] = 0.f;
    if (i == 0) g_kmax_enc[0] = 0u;
    g_ctx[i] = 0.f;
}

// ========== projections via 3xTF32 split: dash = alpha * X @ proj^T ===========
// If kmax_enc != null, also folds the global max of the dash into *kmax_enc.
#define PJ_PITCH 36
#define PJ_TILE  (128 * PJ_PITCH)
#define PJ_SMEM  (4 * PJ_TILE * 4)     // Ah, Al, Bh, Bl

__global__ __launch_bounds__(256) void proj_mma(
    const float* __restrict__ X, const float* __restrict__ P, float* __restrict__ C,
    unsigned* kmax_enc)
{
    extern __shared__ float sm[];
    float* Ah = sm;
    float* Al = sm + PJ_TILE;
    float* Bh = sm + 2 * PJ_TILE;
    float* Bl = sm + 3 * PJ_TILE;

    const int t    = threadIdx.x;
    const int lane = t & 31;
    const int w    = t >> 5;
    const int wm   = w & 3;
    const int wn   = w >> 2;
    const int grp  = lane >> 2;
    const int tig  = lane & 3;

    const long i0 = (long)blockIdx.x * 128;
    const int  j0 = blockIdx.y * 128;

    const int lrow = t >> 3;
    const int lcol = (t & 7) * 4;

    float acc[2][8][4];
#pragma unroll
    for (int mi = 0; mi < 2; ++mi)
#pragma unroll
        for (int ni = 0; ni < 8; ++ni)
#pragma unroll
            for (int r = 0; r < 4; ++r) acc[mi][ni][r] = 0.f;

#pragma unroll
    for (int c = 0; c < 2; ++c) {
        const int kof = c * 32;
#pragma unroll
        for (int i = 0; i < 4; ++i) {
            int row = i * 32 + lrow;
            float4 va = *(const float4*)(X + (i0 + row) * DD + kof + lcol);
            float4 vb = *(const float4*)(P + (long)(j0 + row) * DD + kof + lcol);
            float4 ah, al, bh, bl;
            ah.x = to_tf32(va.x); al.x = to_tf32(va.x - ah.x);
            ah.y = to_tf32(va.y); al.y = to_tf32(va.y - ah.y);
            ah.z = to_tf32(va.z); al.z = to_tf32(va.z - ah.z);
            ah.w = to_tf32(va.w); al.w = to_tf32(va.w - ah.w);
            bh.x = to_tf32(vb.x); bl.x = to_tf32(vb.x - bh.x);
            bh.y = to_tf32(vb.y); bl.y = to_tf32(vb.y - bh.y);
            bh.z = to_tf32(vb.z); bl.z = to_tf32(vb.z - bh.z);
            bh.w = to_tf32(vb.w); bl.w = to_tf32(vb.w - bh.w);
            *(float4*)&Ah[row * PJ_PITCH + lcol] = ah;
            *(float4*)&Al[row * PJ_PITCH + lcol] = al;
            *(float4*)&Bh[row * PJ_PITCH + lcol] = bh;
            *(float4*)&Bl[row * PJ_PITCH + lcol] = bl;
        }
        __syncthreads();

#pragma unroll
        for (int ks = 0; ks < 4; ++ks) {
            const int k0 = ks * 8;
            uint32_t ahr[2][4], alr[2][4];
#pragma unroll
            for (int mi = 0; mi < 2; ++mi) {
                int m = wm * 32 + mi * 16 + grp;
                ahr[mi][0] = __float_as_uint(Ah[m * PJ_PITCH + k0 + tig]);
                ahr[mi][1] = __float_as_uint(Ah[(m + 8) * PJ_PITCH + k0 + tig]);
                ahr[mi][2] = __float_as_uint(Ah[m * PJ_PITCH + k0 + tig + 4]);
                ahr[mi][3] = __float_as_uint(Ah[(m + 8) * PJ_PITCH + k0 + tig + 4]);
                alr[mi][0] = __float_as_uint(Al[m * PJ_PITCH + k0 + tig]);
                alr[mi][1] = __float_as_uint(Al[(m + 8) * PJ_PITCH + k0 + tig]);
                alr[mi][2] = __float_as_uint(Al[m * PJ_PITCH + k0 + tig + 4]);
                alr[mi][3] = __float_as_uint(Al[(m + 8) * PJ_PITCH + k0 + tig + 4]);
            }
#pragma unroll
            for (int ni = 0; ni < 8; ++ni) {
                int n = wn * 64 + ni * 8 + grp;
                uint32_t bhr[2], blr[2];
                bhr[0] = __float_as_uint(Bh[n * PJ_PITCH + k0 + tig]);
                bhr[1] = __float_as_uint(Bh[n * PJ_PITCH + k0 + tig + 4]);
                blr[0] = __float_as_uint(Bl[n * PJ_PITCH + k0 + tig]);
                blr[1] = __float_as_uint(Bl[n * PJ_PITCH + k0 + tig + 4]);
#pragma unroll
                for (int mi = 0; mi < 2; ++mi) {
                    mma_tf32_16x8x8(acc[mi][ni], ahr[mi], blr);
                    mma_tf32_16x8x8(acc[mi][ni], alr[mi], bhr);
                    mma_tf32_16x8x8(acc[mi][ni], ahr[mi], bhr);
                }
            }
        }
        __syncthreads();
    }

    float lmax = -3.4e38f;
#pragma unroll
    for (int mi = 0; mi < 2; ++mi) {
        long row = i0 + wm * 32 + mi * 16 + grp;
#pragma unroll
        for (int ni = 0; ni < 8; ++ni) {
            long col = j0 + wn * 64 + ni * 8 + tig * 2;
            float2 v0 = make_float2(acc[mi][ni][0] * NORMALIZER, acc[mi][ni][1] * NORMALIZER);
            float2 v1 = make_float2(acc[mi][ni][2] * NORMALIZER, acc[mi][ni][3] * NORMALIZER);
            *(float2*)(C + row * MM + col)       = v0;
            *(float2*)(C + (row + 8) * MM + col) = v1;
            lmax = fmaxf(lmax, fmaxf(fmaxf(v0.x, v0.y), fmaxf(v1.x, v1.y)));
        }
    }
    if (kmax_enc) {
#pragma unroll
        for (int o = 16; o; o >>= 1) lmax = fmaxf(lmax, __shfl_xor_sync(0xffffffffu, lmax, o));
        if (lane == 0) atomicMax(kmax_enc, enc_f(lmax));
    }
}

// ============ weights[h] = qp[h] @ kp[h]^T via mma.sync fp16 + ldmatrix ========
#define WF_PITCH 40
#define WF_ABUF  (256 * WF_PITCH)       // halves per A stage
#define WF_BBUF  (128 * WF_PITCH)       // halves per B stage
#define WF_SMEM  ((2 * WF_ABUF + 2 * WF_BBUF) * 2)   // 61440 B

__global__ __launch_bounds__(256) void weights_mma(
    const __half* __restrict__ qp, const __half* __restrict__ kp, float* __restrict__ outw)
{
    extern __shared__ __half smh[];
    __half* As = smh;                   // [2][256][40]
    __half* Bs = smh + 2 * WF_ABUF;     // [2][128][40]

    const int t    = threadIdx.x;
    const int lane = t & 31;
    const int w    = t >> 5;
    const int wm   = w & 3;             // 4 warps in M (64 rows each)
    const int wn   = w >> 2;            // 2 warps in N (64 cols each)
    const int grp  = lane >> 2;
    const int tig  = lane & 3;

    const int lr8     = lane & 7;
    const int lg      = lane >> 3;
    const int rowOff  = (lg & 1) * 8 + lr8;
    const int colOff  = (lg >> 1) * 8;

    const int h   = blockIdx.z;
    const long i0 = (long)blockIdx.y * 256;
    const long j0 = (long)blockIdx.x * 128;

    const __half* Ag = qp + ((long)h * NN + i0) * MM;
    const __half* Bg = kp + ((long)h * NN + j0) * MM;

    const int arow = t >> 2;            // 0..63
    const int ac8  = (t & 3) * 8;

    float acc[4][8][4];
#pragma unroll
    for (int mi = 0; mi < 4; ++mi)
#pragma unroll
        for (int ni = 0; ni < 8; ++ni)
#pragma unroll
            for (int r = 0; r < 4; ++r) acc[mi][ni][r] = 0.f;

    uint32_t As_u = smem_u32(As);
    uint32_t Bs_u = smem_u32(Bs);

#pragma unroll
    for (int i = 0; i < 4; ++i) {
        int row = i * 64 + arow;
        cp_async16(As_u + (row * WF_PITCH + ac8) * 2, Ag + (long)row * MM + ac8);
    }
#pragma unroll
    for (int i = 0; i < 2; ++i) {
        int row = i * 64 + arow;
        cp_async16(Bs_u + (row * WF_PITCH + ac8) * 2, Bg + (long)row * MM + ac8);
    }
    cp_commit();

#pragma unroll 1
    for (int c = 0; c < 8; ++c) {
        cp_wait<0>();
        __syncthreads();
        if (c < 7) {
            const int kof = (c + 1) * 32;
            const uint32_t ab = ((c + 1) & 1) * WF_ABUF * 2;
            const uint32_t bb = ((c + 1) & 1) * WF_BBUF * 2;
#pragma unroll
            for (int i = 0; i < 4; ++i) {
                int row = i * 64 + arow;
                cp_async16(As_u + ab + (row * WF_PITCH + ac8) * 2,
                           Ag + (long)row * MM + kof + ac8);
            }
#pragma unroll
            for (int i = 0; i < 2; ++i) {
                int row = i * 64 + arow;
                cp_async16(Bs_u + bb + (row * WF_PITCH + ac8) * 2,
                           Bg + (long)row * MM + kof + ac8);
            }
            cp_commit();
        }

        const uint32_t AbU = As_u + (c & 1) * WF_ABUF * 2;
        const uint32_t BbU = Bs_u + (c & 1) * WF_BBUF * 2;

#pragma unroll
        for (int ks = 0; ks < 2; ++ks) {
            const int k0 = ks * 16;
            uint32_t a[4][4];
#pragma unroll
            for (int mi = 0; mi < 4; ++mi) {
                int m = wm * 64 + mi * 16 + rowOff;
                uint32_t addr = AbU + (uint32_t)(m * WF_PITCH + k0 + colOff) * 2;
                LDSM_X4(a[mi][0], a[mi][1], a[mi][2], a[mi][3], addr);
            }
            uint32_t b[8][2];
#pragma unroll
            for (int p = 0; p < 4; ++p) {
                int n = wn * 64 + p * 16 + rowOff;
                uint32_t addr = BbU + (uint32_t)(n * WF_PITCH + k0 + colOff) * 2;
                uint32_t r0, r1, r2, r3;
                LDSM_X4(r0, r1, r2, r3, addr);
                b[2 * p][0]     = r0;
                b[2 * p + 1][0] = r1;
                b[2 * p][1]     = r2;
                b[2 * p + 1][1] = r3;
            }
#pragma unroll
            for (int mi = 0; mi < 4; ++mi)
#pragma unroll
                for (int ni = 0; ni < 8; ++ni)
                    mma_f16_16x8x16(acc[mi][ni], a[mi], b[ni]);
        }
    }

    float* Cp = outw + (long)h * NN * NN;
#pragma unroll
    for (int mi = 0; mi < 4; ++mi) {
        long row = i0 + wm * 64 + mi * 16 + grp;
#pragma unroll
        for (int ni = 0; ni < 8; ++ni) {
            long col = j0 + wn * 64 + ni * 8 + tig * 2;
            *(float2*)(Cp + row * NN + col) =
                make_float2(acc[mi][ni][0] * HUNSCALE, acc[mi][ni][1] * HUNSCALE);
            *(float2*)(Cp + (row + 8) * NN + col) =
                make_float2(acc[mi][ni][2] * HUNSCALE, acc[mi][ni][3] * HUNSCALE);
        }
    }
}

// ======= ctx[h][m][e] = sum_n kp[h][n][m] * v[h][n][e]  via mma tf32 ==========
#define CTX_KSPLIT 16
#define CTX_KC     32
#define KS_PITCH   260
#define VS_PITCH   68
#define KS_BUF     (CTX_KC * KS_PITCH)
#define VS_BUF     (CTX_KC * VS_PITCH)
#define CTX_SMEM   ((2 * KS_BUF + 2 * VS_BUF) * 4)

__global__ __launch_bounds__(256) void ctx_mma(
    const float* __restrict__ kp, const float* __restrict__ v, float* __restrict__ ctx)
{
    extern __shared__ float sm[];
    float* Ks = sm;
    float* Vs = sm + 2 * KS_BUF;

    const int t    = threadIdx.x;
    const int lane = t & 31;
    const int w    = t >> 5;
    const int wm   = w & 3;
    const int we   = w >> 2;
    const int grp  = lane >> 2;
    const int tig  = lane & 3;

    const int h     = blockIdx.z;
    const int nbase = blockIdx.y * (NN / CTX_KSPLIT);

    const float* Kg = kp + ((long)h * NN + nbase) * MM;
    const float* Vg = v  + ((long)h * NN + nbase) * DD;

    const int krow = t >> 3;
    const int c4   = t & 7;

    float acc[4][4][4];
#pragma unroll
    for (int mi = 0; mi < 4; ++mi)
#pragma unroll
        for (int ni = 0; ni < 4; ++ni)
#pragma unroll
            for (int r = 0; r < 4; ++r) acc[mi][ni][r] = 0.f;

    uint32_t Ks_u = smem_u32(Ks);
    uint32_t Vs_u = smem_u32(Vs);

#pragma unroll
    for (int i = 0; i < 8; ++i)
        cp_async16(Ks_u + (krow * KS_PITCH + (c4 + i * 8) * 4) * 4,
                   Kg + (long)krow * MM + (c4 + i * 8) * 4);
#pragma unroll
    for (int i = 0; i < 2; ++i)
        cp_async16(Vs_u + (krow * VS_PITCH + (c4 + i * 8) * 4) * 4,
                   Vg + (long)krow * DD + (c4 + i * 8) * 4);
    cp_commit();

#pragma unroll 1
    for (int c = 0; c < 8; ++c) {
        cp_wait<0>();
        __syncthreads();
        if (c < 7) {
            const int nof = (c + 1) * CTX_KC;
            const uint32_t kb = ((c + 1) & 1) * KS_BUF * 4;
            const uint32_t vb = ((c + 1) & 1) * VS_BUF * 4;
#pragma unroll
            for (int i = 0; i < 8; ++i)
                cp_async16(Ks_u + kb + (krow * KS_PITCH + (c4 + i * 8) * 4) * 4,
                           Kg + (long)(nof + krow) * MM + (c4 + i * 8) * 4);
#pragma unroll
            for (int i = 0; i < 2; ++i)
                cp_async16(Vs_u + vb + (krow * VS_PITCH + (c4 + i * 8) * 4) * 4,
                           Vg + (long)(nof + krow) * DD + (c4 + i * 8) * 4);
            cp_commit();
        }

        const float* Kb = Ks + (c & 1) * KS_BUF;
        const float* Vb = Vs + (c & 1) * VS_BUF;

#pragma unroll
        for (int ks = 0; ks < 4; ++ks) {
            const int k0 = ks * 8;
            uint32_t a[4][4];
#pragma unroll
            for (int mi = 0; mi < 4; ++mi) {
                int m = wm * 64 + mi * 16 + grp;
                a[mi][0] = __float_as_uint(Kb[(k0 + tig) * KS_PITCH + m]);
                a[mi][1] = __float_as_uint(Kb[(k0 + tig) * KS_PITCH + m + 8]);
                a[mi][2] = __float_as_uint(Kb[(k0 + tig + 4) * KS_PITCH + m]);
                a[mi][3] = __float_as_uint(Kb[(k0 + tig + 4) * KS_PITCH + m + 8]);
            }
            uint32_t b[4][2];
#pragma unroll
            for (int ni = 0; ni < 4; ++ni) {
                int e = we * 32 + ni * 8 + grp;
                b[ni][0] = to_tf32_u(Vb[(k0 + tig) * VS_PITCH + e]);
                b[ni][1] = to_tf32_u(Vb[(k0 + tig + 4) * VS_PITCH + e]);
            }
#pragma unroll
            for (int mi = 0; mi < 4; ++mi)
#pragma unroll
                for (int ni = 0; ni < 4; ++ni)
                    mma_tf32_16x8x8(acc[mi][ni], a[mi], b[ni]);
        }
    }

#pragma unroll
    for (int mi = 0; mi < 4; ++mi) {
        int m = wm * 64 + mi * 16 + grp;
#pragma unroll
        for (int ni = 0; ni < 4; ++ni) {
            int e = we * 32 + ni * 8 + tig * 2;
            float* p0 = &ctx[((long)h * MM + m) * DD + e];
            float* p1 = &ctx[((long)h * MM + m + 8) * DD + e];
            atomicAdd(p0,     acc[mi][ni][0]);
            atomicAdd(p0 + 1, acc[mi][ni][1]);
            atomicAdd(p1,     acc[mi][ni][2]);
            atomicAdd(p1 + 1, acc[mi][ni][3]);
        }
    }
}

// ======= out[h][n][e] = dinv[n] * sum_m qp[h][n][m] * ctx[h][m][e]  (mma) =====
#define OQ_PITCH 36
#define OC_PITCH 68
#define OQ_BUF   (128 * OQ_PITCH)
#define OC_BUF   (32 * OC_PITCH)
#define OUT_SMEM ((2 * OQ_BUF + 2 * OC_BUF) * 4)

__global__ __launch_bounds__(256) void out_mma(
    const float* __restrict__ qp, const float* __restrict__ ctx,
    const float* __restrict__ dinv, float* __restrict__ out)
{
    extern __shared__ float sm[];
    float* Qs = sm;
    float* Cs = sm + 2 * OQ_BUF;

    const int t    = threadIdx.x;
    const int lane = t & 31;
    const int w    = t >> 5;
    const int wn   = w & 3;
    const int we   = w >> 2;
    const int grp  = lane >> 2;
    const int tig  = lane & 3;

    const int h  = blockIdx.y;
    const long n0 = (long)blockIdx.x * 128;

    const float* Qg = qp  + ((long)h * NN + n0) * MM;
    const float* Cg = ctx + (long)h * MM * DD;

    const int lrow = t >> 3;
    const int lcol = (t & 7) * 4;
    const int crow = t >> 3;
    const int cc4  = t & 7;

    float acc[2][4][4];
#pragma unroll
    for (int mi = 0; mi < 2; ++mi)
#pragma unroll
        for (int ni = 0; ni < 4; ++ni)
#pragma unroll
            for (int r = 0; r < 4; ++r) acc[mi][ni][r] = 0.f;

    uint32_t Qs_u = smem_u32(Qs);
    uint32_t Cs_u = smem_u32(Cs);

#pragma unroll
    for (int i = 0; i < 4; ++i) {
        int row = i * 32 + lrow;
        cp_async16(Qs_u + (row * OQ_PITCH + lcol) * 4, Qg + (long)row * MM + lcol);
    }
#pragma unroll
    for (int i = 0; i < 2; ++i)
        cp_async16(Cs_u + (crow * OC_PITCH + (cc4 + i * 8) * 4) * 4,
                   Cg + (long)crow * DD + (cc4 + i * 8) * 4);
    cp_commit();

#pragma unroll 1
    for (int c = 0; c < 8; ++c) {
        cp_wait<0>();
        __syncthreads();
        if (c < 7) {
            const int kof = (c + 1) * 32;
            const uint32_t qb = ((c + 1) & 1) * OQ_BUF * 4;
            const uint32_t cb = ((c + 1) & 1) * OC_BUF * 4;
#pragma unroll
            for (int i = 0; i < 4; ++i) {
                int row = i * 32 + lrow;
                cp_async16(Qs_u + qb + (row * OQ_PITCH + lcol) * 4,
                           Qg + (long)row * MM + kof + lcol);
            }
#pragma unroll
            for (int i = 0; i < 2; ++i)
                cp_async16(Cs_u + cb + (crow * OC_PITCH + (cc4 + i * 8) * 4) * 4,
                           Cg + (long)(kof + crow) * DD + (cc4 + i * 8) * 4);
            cp_commit();
        }

        const float* Qb = Qs + (c & 1) * OQ_BUF;
        const float* Cb = Cs + (c & 1) * OC_BUF;

#pragma unroll
        for (int ks = 0; ks < 4; ++ks) {
            const int k0 = ks * 8;
            uint32_t a[2][4];
#pragma unroll
            for (int mi = 0; mi < 2; ++mi) {
                int n = wn * 32 + mi * 16 + grp;
                a[mi][0] = __float_as_uint(Qb[n * OQ_PITCH + k0 + tig]);
                a[mi][1] = __float_as_uint(Qb[(n + 8) * OQ_PITCH + k0 + tig]);
                a[mi][2] = __float_as_uint(Qb[n * OQ_PITCH + k0 + tig + 4]);
                a[mi][3] = __float_as_uint(Qb[(n + 8) * OQ_PITCH + k0 + tig + 4]);
            }
            uint32_t b[4][2];
#pragma unroll
            for (int ni = 0; ni < 4; ++ni) {
                int e = we * 32 + ni * 8 + grp;
                b[ni][0] = to_tf32_u(Cb[(k0 + tig) * OC_PITCH + e]);
                b[ni][1] = to_tf32_u(Cb[(k0 + tig + 4) * OC_PITCH + e]);
            }
#pragma unroll
            for (int mi = 0; mi < 2; ++mi)
#pragma unroll
                for (int ni = 0; ni < 4; ++ni)
                    mma_tf32_16x8x8(acc[mi][ni], a[mi], b[ni]);
        }
    }

#pragma unroll
    for (int mi = 0; mi < 2; ++mi) {
        long n = n0 + wn * 32 + mi * 16 + grp;
        float dv0 = dinv[(long)h * NN + n];
        float dv1 = dinv[(long)h * NN + n + 8];
#pragma unroll
        for (int ni = 0; ni < 4; ++ni) {
            int e = we * 32 + ni * 8 + tig * 2;
            *(float2*)(out + ((long)h * NN + n) * DD + e) =
                make_float2(acc[mi][ni][0] * dv0, acc[mi][ni][1] * dv0);
            *(float2*)(out + ((long)h * NN + n + 8) * DD + e) =
                make_float2(acc[mi][ni][2] * dv1, acc[mi][ni][3] * dv1);
        }
    }
}

// ---------------- diag / exp / dinv --------------------------------------------
__global__ void diag_kernel(const float* __restrict__ x, float* __restrict__ out) {
    int row  = blockIdx.x * 8 + (threadIdx.x >> 5);
    int lane = threadIdx.x & 31;
    const float* p = x + (long)row * DD;
    float a = p[lane], b = p[lane + 32];
    float s = a * a + b * b;
#pragma unroll
    for (int o = 16; o; o >>= 1) s += __shfl_xor_sync(0xffffffffu, s, o);
    if (!lane) out[row] = s * DIAG_COEF;
}

// warp-per-row: per-row max, fast exp, tf32 + scaled-fp16 stores
__global__ void expq_kernel(float* __restrict__ dash, const float* __restrict__ diag,
                            __half* __restrict__ dash_h) {
    int row  = blockIdx.x * 8 + (threadIdx.x >> 5);
    int lane = threadIdx.x & 31;
    long base = (long)row * MM;
    float4 a = *(float4*)(dash + base + lane * 4);
    float4 b = *(float4*)(dash + base + 128 + lane * 4);
    float m = fmaxf(fmaxf(fmaxf(a.x, a.y), fmaxf(a.z, a.w)),
                    fmaxf(fmaxf(b.x, b.y), fmaxf(b.z, b.w)));
#pragma unroll
    for (int o = 16; o; o >>= 1) m = fmaxf(m, __shfl_xor_sync(0xffffffffu, m, o));
    float s = diag[row] + m;
    float4 ea, eb;
    ea.x = RATIO * (__expf(a.x - s) + FEPS);
    ea.y = RATIO * (__expf(a.y - s) + FEPS);
    ea.z = RATIO * (__expf(a.z - s) + FEPS);
    ea.w = RATIO * (__expf(a.w - s) + FEPS);
    eb.x = RATIO * (__expf(b.x - s) + FEPS);
    eb.y = RATIO * (__expf(b.y - s) + FEPS);
    eb.z = RATIO * (__expf(b.z - s) + FEPS);
    eb.w = RATIO * (__expf(b.w - s) + FEPS);
    float4 ta = make_float4(to_tf32(ea.x), to_tf32(ea.y), to_tf32(ea.z), to_tf32(ea.w));
    float4 tb = make_float4(to_tf32(eb.x), to_tf32(eb.y), to_tf32(eb.z), to_tf32(eb.w));
    *(float4*)(dash + base + lane * 4)       = ta;
    *(float4*)(dash + base + 128 + lane * 4) = tb;
    __half2* hp0 = (__half2*)(dash_h + base + lane * 4);
    __half2* hp1 = (__half2*)(dash_h + base + 128 + lane * 4);
    hp0[0] = __floats2half2_rn(ea.x * HSCALE, ea.y * HSCALE);
    hp0[1] = __floats2half2_rn(ea.z * HSCALE, ea.w * HSCALE);
    hp1[0] = __floats2half2_rn(eb.x * HSCALE, eb.y * HSCALE);
    hp1[1] = __floats2half2_rn(eb.z * HSCALE, eb.w * HSCALE);
}

__global__ void expk_kernel(float* __restrict__ dash, const float* __restrict__ diag,
                            const unsigned* __restrict__ kmax_enc, float* __restrict__ ksum,
                            __half* __restrict__ dash_h) {
    int t    = threadIdx.x;
    int row0 = blockIdx.x * 64;
    int h    = row0 >> 12;
    float stab  = dec_f(kmax_enc[0]);
    float local = 0.f;
    for (int r = 0; r < 64; ++r) {
        long idx = (long)(row0 + r) * MM + t;
        float vfull = RATIO * (__expf(dash[idx] - diag[row0 + r] - stab) + FEPS);
        float vv = to_tf32(vfull);
        dash[idx]   = vv;
        dash_h[idx] = __float2half_rn(vfull * HSCALE);
        local += vv;
    }
    atomicAdd(&ksum[h * MM + t], local);
}

__global__ void dinv_kernel(const float* __restrict__ qp, const float* __restrict__ ksum,
                            float* __restrict__ dinv) {
    int row  = blockIdx.x * 8 + (threadIdx.x >> 5);
    int lane = threadIdx.x & 31;
    int h    = row >> 12;
    const float* qr = qp + (long)row * MM;
    const float* ks = ksum + h * MM;
    float s = 0.f;
#pragma unroll
    for (int i = 0; i < 8; ++i) {
        int m = lane + i * 32;
        s += qr[m] * ks[m];
    }
#pragma unroll
    for (int o = 16; o; o >>= 1) s += __shfl_xor_sync(0xffffffffu, s, o);
    if (!lane) dinv[row] = 1.f / s;
}

// -------------------------------------------------------------------------------
extern "C" void kernel_launch(void* const* d_in, const int* in_sizes, int n_in,
                              void* d_out, int out_size)
{
    const float* q    = (const float*)d_in[0];
    const float* k    = (const float*)d_in[1];
    const float* v    = (const float*)d_in[2];
    const float* proj = (const float*)d_in[3];

    float* out_align = (float*)d_out;                       // [H,N,D]
    float* out_w     = out_align + (long)HH * NN * DD;      // [H,N,N]

    float *qp, *kp, *qdiag, *kdiag, *ksum, *dinv, *ctx;
    __half *qph, *kph;
    unsigned *kmaxe;
    cudaGetSymbolAddress((void**)&qp,    g_qp);
    cudaGetSymbolAddress((void**)&kp,    g_kp);
    cudaGetSymbolAddress((void**)&qph,   g_qph);
    cudaGetSymbolAddress((void**)&kph,   g_kph);
    cudaGetSymbolAddress((void**)&qdiag, g_qdiag);
    cudaGetSymbolAddress((void**)&kdiag, g_kdiag);
    cudaGetSymbolAddress((void**)&ksum,  g_ksum);
    cudaGetSymbolAddress((void**)&dinv,  g_dinv);
    cudaGetSymbolAddress((void**)&ctx,   g_ctx);
    cudaGetSymbolAddress((void**)&kmaxe, g_kmax_enc);

    static cudaStream_t s2 = nullptr;
    static cudaEvent_t  ev1, ev2;
    static bool attr_done = false;
    if (!attr_done) {
        cudaFuncSetAttribute(weights_mma, cudaFuncAttributeMaxDynamicSharedMemorySize, WF_SMEM);
        cudaFuncSetAttribute(proj_mma,    cudaFuncAttributeMaxDynamicSharedMemorySize, PJ_SMEM);
        cudaFuncSetAttribute(ctx_mma,     cudaFuncAttributeMaxDynamicSharedMemorySize, CTX_SMEM);
        cudaFuncSetAttribute(out_mma,     cudaFuncAttributeMaxDynamicSharedMemorySize, OUT_SMEM);
        cudaStreamCreateWithFlags(&s2, cudaStreamNonBlocking);
        cudaEventCreateWithFlags(&ev1, cudaEventDisableTiming);
        cudaEventCreateWithFlags(&ev2, cudaEventDisableTiming);
        attr_done = true;
    }

    zero_kernel<<<HH * MM * DD / 256, 256>>>();

    proj_mma<<<dim3(ROWS / 128, MM / 128), 256, PJ_SMEM>>>(q, proj, qp, nullptr);
    proj_mma<<<dim3(ROWS / 128, MM / 128), 256, PJ_SMEM>>>(k, proj, kp, kmaxe);

    diag_kernel<<<ROWS / 8, 256>>>(q, qdiag);
    diag_kernel<<<ROWS / 8, 256>>>(k, kdiag);

    expq_kernel<<<ROWS / 8, 256>>>(qp, qdiag, qph);
    expk_kernel<<<ROWS / 64, 256>>>(kp, kdiag, kmaxe, ksum, kph);

    // fork: side stream runs the small ctx->dinv->out chain concurrently with
    // the dominant weights GEMM on the main (capture) stream.
    cudaEventRecord(ev1, 0);
    cudaStreamWaitEvent(s2, ev1, 0);

    weights_mma<<<dim3(NN / 128, NN / 256, HH), 256, WF_SMEM>>>(qph, kph, out_w);

    ctx_mma<<<dim3(1, CTX_KSPLIT, HH), 256, CTX_SMEM, s2>>>(kp, v, ctx);
    dinv_kernel<<<ROWS / 8, 256, 0, s2>>>(qp, ksum, dinv);
    out_mma<<<dim3(NN / 128, HH), 256, OUT_SMEM, s2>>>(qp, ctx, dinv, out_align);

    cudaEventRecord(ev2, s2);
    cudaStreamWaitEvent(0, ev2, 0);
}

// round 11
// speedup vs baseline: 1.0921x; 1.0510x over previous
#include <cuda_runtime.h>
#include <cuda_fp16.h>
#include <math.h>
#include <stdint.h>

#define HH 16
#define NN 4096
#define DD 64
#define MM 256
#define ROWS (HH * NN)          // 65536

#define NORMALIZER 0.35355339059327373f  // 64^-0.25
#define DIAG_COEF  0.0625f               // 0.5 * 64^-0.5
#define RATIO      0.0625f               // 256^-0.5
#define FEPS       1e-4f
#define HSCALE     2048.0f               // lift fp16 features out of subnormals
#define HUNSCALE   (1.0f / 4194304.0f)   // 2^-22

// ---------------- scratch (device globals; no allocation allowed) -------------
__device__ float    g_qp[(size_t)ROWS * MM];
__device__ float    g_kp[(size_t)ROWS * MM];
__device__ __half   g_qph[(size_t)ROWS * MM];
__device__ __half   g_kph[(size_t)ROWS * MM];
__device__ float    g_qdiag[ROWS];
__device__ float    g_kdiag[ROWS];
__device__ float    g_ksum[HH * MM];
__device__ float    g_dinv[ROWS];
__device__ float    g_ctx[HH * MM * DD];
__device__ unsigned g_kmax_enc[1];

__device__ __forceinline__ float to_tf32(float x) {
    uint32_t r;
    asm("cvt.rna.tf32.f32 %0, %1;" : "=r"(r) : "f"(x));
    return __uint_as_float(r);
}
__device__ __forceinline__ uint32_t to_tf32_u(float x) {
    uint32_t r;
    asm("cvt.rna.tf32.f32 %0, %1;" : "=r"(r) : "f"(x));
    return r;
}
__device__ __forceinline__ uint32_t smem_u32(const void* p) {
    uint32_t a;
    asm("{ .reg .u64 t; cvta.to.shared.u64 t, %1; cvt.u32.u64 %0, t; }" : "=r"(a) : "l"(p));
    return a;
}
__device__ __forceinline__ void cp_async16(uint32_t dst, const void* src) {
    asm volatile("cp.async.ca.shared.global [%0], [%1], 16;" :: "r"(dst), "l"(src) : "memory");
}
__device__ __forceinline__ void cp_commit() {
    asm volatile("cp.async.commit_group;" ::: "memory");
}
template <int N> __device__ __forceinline__ void cp_wait() {
    asm volatile("cp.async.wait_group %0;" :: "n"(N) : "memory");
}
__device__ __forceinline__ void mma_tf32_16x8x8(float* d, const uint32_t* a, const uint32_t* b) {
    asm volatile(
        "mma.sync.aligned.m16n8k8.row.col.f32.tf32.tf32.f32 "
        "{%0,%1,%2,%3}, {%4,%5,%6,%7}, {%8,%9}, {%0,%1,%2,%3};"
        : "+f"(d[0]), "+f"(d[1]), "+f"(d[2]), "+f"(d[3])
        : "r"(a[0]), "r"(a[1]), "r"(a[2]), "r"(a[3]), "r"(b[0]), "r"(b[1]));
}
__device__ __forceinline__ void mma_f16_16x8x16(float* d, const uint32_t* a, const uint32_t* b) {
    asm volatile(
        "mma.sync.aligned.m16n8k16.row.col.f32.f16.f16.f32 "
        "{%0,%1,%2,%3}, {%4,%5,%6,%7}, {%8,%9}, {%0,%1,%2,%3};"
        : "+f"(d[0]), "+f"(d[1]), "+f"(d[2]), "+f"(d[3])
        : "r"(a[0]), "r"(a[1]), "r"(a[2]), "r"(a[3]), "r"(b[0]), "r"(b[1]));
}
#define LDSM_X4(r0, r1, r2, r3, addr) \
    asm volatile("ldmatrix.sync.aligned.m8n8.x4.shared.b16 {%0,%1,%2,%3}, [%4];" \
                 : "=r"(r0), "=r"(r1), "=r"(r2), "=r"(r3) : "r"(addr))

// monotonic float<->uint encoding for order-invariant atomic max (init = 0)
__device__ __forceinline__ unsigned enc_f(float f) {
    unsigned u = __float_as_uint(f);
    return (u & 0x80000000u) ? ~u : (u | 0x80000000u);
}
__device__ __forceinline__ float dec_f(unsigned u) {
    return (u & 0x80000000u) ? __uint_as_float(u ^ 0x80000000u) : __uint_as_float(~u);
}

// ---------------- zero accumulated scratch -------------------------------------
__global__ void zero_kernel() {
    int i = blockIdx.x * 256 + threadIdx.x;
    if (i < HH * MM) g_ksum[i] = 0.f;
    if (i == 0) g_kmax_enc[0] = 0u;
    g_ctx[i] = 0.f;
}

// ========== projections via 3xTF32 split: dash = alpha * X @ proj^T ===========
// Fused extras: per-row diag (blockIdx.y==0), optional global-max into kmax_enc.
#define PJ_PITCH 36
#define PJ_TILE  (128 * PJ_PITCH)
#define PJ_SMEM  (4 * PJ_TILE * 4)     // Ah, Al, Bh, Bl

__global__ __launch_bounds__(256) void proj_mma(
    const float* __restrict__ X, const float* __restrict__ P, float* __restrict__ C,
    float* __restrict__ diag, unsigned* kmax_enc)
{
    extern __shared__ float sm[];
    float* Ah = sm;
    float* Al = sm + PJ_TILE;
    float* Bh = sm + 2 * PJ_TILE;
    float* Bl = sm + 3 * PJ_TILE;

    const int t    = threadIdx.x;
    const int lane = t & 31;
    const int w    = t >> 5;
    const int wm   = w & 3;
    const int wn   = w >> 2;
    const int grp  = lane >> 2;
    const int tig  = lane & 3;

    const long i0 = (long)blockIdx.x * 128;
    const int  j0 = blockIdx.y * 128;

    const int lrow = t >> 3;
    const int lcol = (t & 7) * 4;

    float acc[2][8][4];
#pragma unroll
    for (int mi = 0; mi < 2; ++mi)
#pragma unroll
        for (int ni = 0; ni < 8; ++ni)
#pragma unroll
            for (int r = 0; r < 4; ++r) acc[mi][ni][r] = 0.f;

    float sq[4] = {0.f, 0.f, 0.f, 0.f};   // fused diag partial sums

#pragma unroll
    for (int c = 0; c < 2; ++c) {
        const int kof = c * 32;
#pragma unroll
        for (int i = 0; i < 4; ++i) {
            int row = i * 32 + lrow;
            float4 va = *(const float4*)(X + (i0 + row) * DD + kof + lcol);
            float4 vb = *(const float4*)(P + (long)(j0 + row) * DD + kof + lcol);
            sq[i] += va.x * va.x + va.y * va.y + va.z * va.z + va.w * va.w;
            float4 ah, al, bh, bl;
            ah.x = to_tf32(va.x); al.x = to_tf32(va.x - ah.x);
            ah.y = to_tf32(va.y); al.y = to_tf32(va.y - ah.y);
            ah.z = to_tf32(va.z); al.z = to_tf32(va.z - ah.z);
            ah.w = to_tf32(va.w); al.w = to_tf32(va.w - ah.w);
            bh.x = to_tf32(vb.x); bl.x = to_tf32(vb.x - bh.x);
            bh.y = to_tf32(vb.y); bl.y = to_tf32(vb.y - bh.y);
            bh.z = to_tf32(vb.z); bl.z = to_tf32(vb.z - bh.z);
            bh.w = to_tf32(vb.w); bl.w = to_tf32(vb.w - bh.w);
            *(float4*)&Ah[row * PJ_PITCH + lcol] = ah;
            *(float4*)&Al[row * PJ_PITCH + lcol] = al;
            *(float4*)&Bh[row * PJ_PITCH + lcol] = bh;
            *(float4*)&Bl[row * PJ_PITCH + lcol] = bl;
        }
        __syncthreads();

#pragma unroll
        for (int ks = 0; ks < 4; ++ks) {
            const int k0 = ks * 8;
            uint32_t ahr[2][4], alr[2][4];
#pragma unroll
            for (int mi = 0; mi < 2; ++mi) {
                int m = wm * 32 + mi * 16 + grp;
                ahr[mi][0] = __float_as_uint(Ah[m * PJ_PITCH + k0 + tig]);
                ahr[mi][1] = __float_as_uint(Ah[(m + 8) * PJ_PITCH + k0 + tig]);
                ahr[mi][2] = __float_as_uint(Ah[m * PJ_PITCH + k0 + tig + 4]);
                ahr[mi][3] = __float_as_uint(Ah[(m + 8) * PJ_PITCH + k0 + tig + 4]);
                alr[mi][0] = __float_as_uint(Al[m * PJ_PITCH + k0 + tig]);
                alr[mi][1] = __float_as_uint(Al[(m + 8) * PJ_PITCH + k0 + tig]);
                alr[mi][2] = __float_as_uint(Al[m * PJ_PITCH + k0 + tig + 4]);
                alr[mi][3] = __float_as_uint(Al[(m + 8) * PJ_PITCH + k0 + tig + 4]);
            }
#pragma unroll
            for (int ni = 0; ni < 8; ++ni) {
                int n = wn * 64 + ni * 8 + grp;
                uint32_t bhr[2], blr[2];
                bhr[0] = __float_as_uint(Bh[n * PJ_PITCH + k0 + tig]);
                bhr[1] = __float_as_uint(Bh[n * PJ_PITCH + k0 + tig + 4]);
                blr[0] = __float_as_uint(Bl[n * PJ_PITCH + k0 + tig]);
                blr[1] = __float_as_uint(Bl[n * PJ_PITCH + k0 + tig + 4]);
#pragma unroll
                for (int mi = 0; mi < 2; ++mi) {
                    mma_tf32_16x8x8(acc[mi][ni], ahr[mi], blr);
                    mma_tf32_16x8x8(acc[mi][ni], alr[mi], bhr);
                    mma_tf32_16x8x8(acc[mi][ni], ahr[mi], bhr);
                }
            }
        }
        __syncthreads();
    }

    // fused diag store (once, from the y==0 tile): reduce across 8 threads/row
    if (blockIdx.y == 0) {
#pragma unroll
        for (int i = 0; i < 4; ++i) {
            float s = sq[i];
            s += __shfl_down_sync(0xffffffffu, s, 4, 8);
            s += __shfl_down_sync(0xffffffffu, s, 2, 8);
            s += __shfl_down_sync(0xffffffffu, s, 1, 8);
            if ((t & 7) == 0) diag[i0 + i * 32 + lrow] = s * DIAG_COEF;
        }
    }

    float lmax = -3.4e38f;
#pragma unroll
    for (int mi = 0; mi < 2; ++mi) {
        long row = i0 + wm * 32 + mi * 16 + grp;
#pragma unroll
        for (int ni = 0; ni < 8; ++ni) {
            long col = j0 + wn * 64 + ni * 8 + tig * 2;
            float2 v0 = make_float2(acc[mi][ni][0] * NORMALIZER, acc[mi][ni][1] * NORMALIZER);
            float2 v1 = make_float2(acc[mi][ni][2] * NORMALIZER, acc[mi][ni][3] * NORMALIZER);
            *(float2*)(C + row * MM + col)       = v0;
            *(float2*)(C + (row + 8) * MM + col) = v1;
            lmax = fmaxf(lmax, fmaxf(fmaxf(v0.x, v0.y), fmaxf(v1.x, v1.y)));
        }
    }
    if (kmax_enc) {
#pragma unroll
        for (int o = 16; o; o >>= 1) lmax = fmaxf(lmax, __shfl_xor_sync(0xffffffffu, lmax, o));
        if (lane == 0) atomicMax(kmax_enc, enc_f(lmax));
    }
}

// ============ weights[h] = qp[h] @ kp[h]^T via mma.sync fp16 + ldmatrix ========
// 3-stage cp.async pipeline (2 groups in flight), 256x128 CTA tile.
#define WF_PITCH  40
#define WF_ABUF   (256 * WF_PITCH)       // halves per A stage
#define WF_BBUF   (128 * WF_PITCH)       // halves per B stage
#define WF_STAGE  (WF_ABUF + WF_BBUF)
#define WF_SMEM   (3 * WF_STAGE * 2)     // 92160 B

__global__ __launch_bounds__(256) void weights_mma(
    const __half* __restrict__ qp, const __half* __restrict__ kp, float* __restrict__ outw)
{
    extern __shared__ __half smh[];
    // stage s: A at smh + s*WF_STAGE, B at smh + s*WF_STAGE + WF_ABUF

    const int t    = threadIdx.x;
    const int lane = t & 31;
    const int w    = t >> 5;
    const int wm   = w & 3;             // 4 warps in M (64 rows each)
    const int wn   = w >> 2;            // 2 warps in N (64 cols each)
    const int grp  = lane >> 2;
    const int tig  = lane & 3;

    const int lr8     = lane & 7;
    const int lg      = lane >> 3;
    const int rowOff  = (lg & 1) * 8 + lr8;
    const int colOff  = (lg >> 1) * 8;

    const int h   = blockIdx.z;
    const long i0 = (long)blockIdx.y * 256;
    const long j0 = (long)blockIdx.x * 128;

    const __half* Ag = qp + ((long)h * NN + i0) * MM;
    const __half* Bg = kp + ((long)h * NN + j0) * MM;

    const int arow = t >> 2;            // 0..63
    const int ac8  = (t & 3) * 8;

    float acc[4][8][4];
#pragma unroll
    for (int mi = 0; mi < 4; ++mi)
#pragma unroll
        for (int ni = 0; ni < 8; ++ni)
#pragma unroll
            for (int r = 0; r < 4; ++r) acc[mi][ni][r] = 0.f;

    uint32_t base_u = smem_u32(smh);

    // prologue: issue chunks 0 and 1 into stages 0, 1
#pragma unroll
    for (int pc = 0; pc < 2; ++pc) {
        const uint32_t su = base_u + pc * WF_STAGE * 2;
        const int kof = pc * 32;
#pragma unroll
        for (int i = 0; i < 4; ++i) {
            int row = i * 64 + arow;
            cp_async16(su + (row * WF_PITCH + ac8) * 2, Ag + (long)row * MM + kof + ac8);
        }
#pragma unroll
        for (int i = 0; i < 2; ++i) {
            int row = i * 64 + arow;
            cp_async16(su + (WF_ABUF + row * WF_PITCH + ac8) * 2, Bg + (long)row * MM + kof + ac8);
        }
        cp_commit();
    }

    int stage = 0, nstage = 2;
#pragma unroll 1
    for (int c = 0; c < 8; ++c) {
        cp_wait<1>();
        __syncthreads();
        if (c < 6) {
            const int kof = (c + 2) * 32;
            const uint32_t su = base_u + nstage * WF_STAGE * 2;
#pragma unroll
            for (int i = 0; i < 4; ++i) {
                int row = i * 64 + arow;
                cp_async16(su + (row * WF_PITCH + ac8) * 2, Ag + (long)row * MM + kof + ac8);
            }
#pragma unroll
            for (int i = 0; i < 2; ++i) {
                int row = i * 64 + arow;
                cp_async16(su + (WF_ABUF + row * WF_PITCH + ac8) * 2,
                           Bg + (long)row * MM + kof + ac8);
            }
            cp_commit();
            nstage = (nstage + 1) % 3;
        } else {
            cp_commit();   // keep group counting uniform for wait<1>
        }

        const uint32_t AbU = base_u + stage * WF_STAGE * 2;
        const uint32_t BbU = AbU + WF_ABUF * 2;
        stage = (stage + 1) % 3;

#pragma unroll
        for (int ks = 0; ks < 2; ++ks) {
            const int k0 = ks * 16;
            uint32_t a[4][4];
#pragma unroll
            for (int mi = 0; mi < 4; ++mi) {
                int m = wm * 64 + mi * 16 + rowOff;
                uint32_t addr = AbU + (uint32_t)(m * WF_PITCH + k0 + colOff) * 2;
                LDSM_X4(a[mi][0], a[mi][1], a[mi][2], a[mi][3], addr);
            }
            uint32_t b[8][2];
#pragma unroll
            for (int p = 0; p < 4; ++p) {
                int n = wn * 64 + p * 16 + rowOff;
                uint32_t addr = BbU + (uint32_t)(n * WF_PITCH + k0 + colOff) * 2;
                uint32_t r0, r1, r2, r3;
                LDSM_X4(r0, r1, r2, r3, addr);
                b[2 * p][0]     = r0;
                b[2 * p + 1][0] = r1;
                b[2 * p][1]     = r2;
                b[2 * p + 1][1] = r3;
            }
#pragma unroll
            for (int mi = 0; mi < 4; ++mi)
#pragma unroll
                for (int ni = 0; ni < 8; ++ni)
                    mma_f16_16x8x16(acc[mi][ni], a[mi], b[ni]);
        }
    }

    float* Cp = outw + (long)h * NN * NN;
#pragma unroll
    for (int mi = 0; mi < 4; ++mi) {
        long row = i0 + wm * 64 + mi * 16 + grp;
#pragma unroll
        for (int ni = 0; ni < 8; ++ni) {
            long col = j0 + wn * 64 + ni * 8 + tig * 2;
            *(float2*)(Cp + row * NN + col) =
                make_float2(acc[mi][ni][0] * HUNSCALE, acc[mi][ni][1] * HUNSCALE);
            *(float2*)(Cp + (row + 8) * NN + col) =
                make_float2(acc[mi][ni][2] * HUNSCALE, acc[mi][ni][3] * HUNSCALE);
        }
    }
}

// ======= ctx[h][m][e] = sum_n kp[h][n][m] * v[h][n][e]  via mma tf32 ==========
#define CTX_KSPLIT 16
#define CTX_KC     32
#define KS_PITCH   260
#define VS_PITCH   68
#define KS_BUF     (CTX_KC * KS_PITCH)
#define VS_BUF     (CTX_KC * VS_PITCH)
#define CTX_SMEM   ((2 * KS_BUF + 2 * VS_BUF) * 4)

__global__ __launch_bounds__(256) void ctx_mma(
    const float* __restrict__ kp, const float* __restrict__ v, float* __restrict__ ctx)
{
    extern __shared__ float sm[];
    float* Ks = sm;
    float* Vs = sm + 2 * KS_BUF;

    const int t    = threadIdx.x;
    const int lane = t & 31;
    const int w    = t >> 5;
    const int wm   = w & 3;
    const int we   = w >> 2;
    const int grp  = lane >> 2;
    const int tig  = lane & 3;

    const int h     = blockIdx.z;
    const int nbase = blockIdx.y * (NN / CTX_KSPLIT);

    const float* Kg = kp + ((long)h * NN + nbase) * MM;
    const float* Vg = v  + ((long)h * NN + nbase) * DD;

    const int krow = t >> 3;
    const int c4   = t & 7;

    float acc[4][4][4];
#pragma unroll
    for (int mi = 0; mi < 4; ++mi)
#pragma unroll
        for (int ni = 0; ni < 4; ++ni)
#pragma unroll
            for (int r = 0; r < 4; ++r) acc[mi][ni][r] = 0.f;

    uint32_t Ks_u = smem_u32(Ks);
    uint32_t Vs_u = smem_u32(Vs);

#pragma unroll
    for (int i = 0; i < 8; ++i)
        cp_async16(Ks_u + (krow * KS_PITCH + (c4 + i * 8) * 4) * 4,
                   Kg + (long)krow * MM + (c4 + i * 8) * 4);
#pragma unroll
    for (int i = 0; i < 2; ++i)
        cp_async16(Vs_u + (krow * VS_PITCH + (c4 + i * 8) * 4) * 4,
                   Vg + (long)krow * DD + (c4 + i * 8) * 4);
    cp_commit();

#pragma unroll 1
    for (int c = 0; c < 8; ++c) {
        cp_wait<0>();
        __syncthreads();
        if (c < 7) {
            const int nof = (c + 1) * CTX_KC;
            const uint32_t kb = ((c + 1) & 1) * KS_BUF * 4;
            const uint32_t vb = ((c + 1) & 1) * VS_BUF * 4;
#pragma unroll
            for (int i = 0; i < 8; ++i)
                cp_async16(Ks_u + kb + (krow * KS_PITCH + (c4 + i * 8) * 4) * 4,
                           Kg + (long)(nof + krow) * MM + (c4 + i * 8) * 4);
#pragma unroll
            for (int i = 0; i < 2; ++i)
                cp_async16(Vs_u + vb + (krow * VS_PITCH + (c4 + i * 8) * 4) * 4,
                           Vg + (long)(nof + krow) * DD + (c4 + i * 8) * 4);
            cp_commit();
        }

        const float* Kb = Ks + (c & 1) * KS_BUF;
        const float* Vb = Vs + (c & 1) * VS_BUF;

#pragma unroll
        for (int ks = 0; ks < 4; ++ks) {
            const int k0 = ks * 8;
            uint32_t a[4][4];
#pragma unroll
            for (int mi = 0; mi < 4; ++mi) {
                int m = wm * 64 + mi * 16 + grp;
                a[mi][0] = __float_as_uint(Kb[(k0 + tig) * KS_PITCH + m]);
                a[mi][1] = __float_as_uint(Kb[(k0 + tig) * KS_PITCH + m + 8]);
                a[mi][2] = __float_as_uint(Kb[(k0 + tig + 4) * KS_PITCH + m]);
                a[mi][3] = __float_as_uint(Kb[(k0 + tig + 4) * KS_PITCH + m + 8]);
            }
            uint32_t b[4][2];
#pragma unroll
            for (int ni = 0; ni < 4; ++ni) {
                int e = we * 32 + ni * 8 + grp;
                b[ni][0] = to_tf32_u(Vb[(k0 + tig) * VS_PITCH + e]);
                b[ni][1] = to_tf32_u(Vb[(k0 + tig + 4) * VS_PITCH + e]);
            }
#pragma unroll
            for (int mi = 0; mi < 4; ++mi)
#pragma unroll
                for (int ni = 0; ni < 4; ++ni)
                    mma_tf32_16x8x8(acc[mi][ni], a[mi], b[ni]);
        }
    }

#pragma unroll
    for (int mi = 0; mi < 4; ++mi) {
        int m = wm * 64 + mi * 16 + grp;
#pragma unroll
        for (int ni = 0; ni < 4; ++ni) {
            int e = we * 32 + ni * 8 + tig * 2;
            float* p0 = &ctx[((long)h * MM + m) * DD + e];
            float* p1 = &ctx[((long)h * MM + m + 8) * DD + e];
            atomicAdd(p0,     acc[mi][ni][0]);
            atomicAdd(p0 + 1, acc[mi][ni][1]);
            atomicAdd(p1,     acc[mi][ni][2]);
            atomicAdd(p1 + 1, acc[mi][ni][3]);
        }
    }
}

// ======= out[h][n][e] = dinv[n] * sum_m qp[h][n][m] * ctx[h][m][e]  (mma) =====
#define OQ_PITCH 36
#define OC_PITCH 68
#define OQ_BUF   (128 * OQ_PITCH)
#define OC_BUF   (32 * OC_PITCH)
#define OUT_SMEM ((2 * OQ_BUF + 2 * OC_BUF) * 4)

__global__ __launch_bounds__(256) void out_mma(
    const float* __restrict__ qp, const float* __restrict__ ctx,
    const float* __restrict__ dinv, float* __restrict__ out)
{
    extern __shared__ float sm[];
    float* Qs = sm;
    float* Cs = sm + 2 * OQ_BUF;

    const int t    = threadIdx.x;
    const int lane = t & 31;
    const int w    = t >> 5;
    const int wn   = w & 3;
    const int we   = w >> 2;
    const int grp  = lane >> 2;
    const int tig  = lane & 3;

    const int h  = blockIdx.y;
    const long n0 = (long)blockIdx.x * 128;

    const float* Qg = qp  + ((long)h * NN + n0) * MM;
    const float* Cg = ctx + (long)h * MM * DD;

    const int lrow = t >> 3;
    const int lcol = (t & 7) * 4;
    const int crow = t >> 3;
    const int cc4  = t & 7;

    float acc[2][4][4];
#pragma unroll
    for (int mi = 0; mi < 2; ++mi)
#pragma unroll
        for (int ni = 0; ni < 4; ++ni)
#pragma unroll
            for (int r = 0; r < 4; ++r) acc[mi][ni][r] = 0.f;

    uint32_t Qs_u = smem_u32(Qs);
    uint32_t Cs_u = smem_u32(Cs);

#pragma unroll
    for (int i = 0; i < 4; ++i) {
        int row = i * 32 + lrow;
        cp_async16(Qs_u + (row * OQ_PITCH + lcol) * 4, Qg + (long)row * MM + lcol);
    }
#pragma unroll
    for (int i = 0; i < 2; ++i)
        cp_async16(Cs_u + (crow * OC_PITCH + (cc4 + i * 8) * 4) * 4,
                   Cg + (long)crow * DD + (cc4 + i * 8) * 4);
    cp_commit();

#pragma unroll 1
    for (int c = 0; c < 8; ++c) {
        cp_wait<0>();
        __syncthreads();
        if (c < 7) {
            const int kof = (c + 1) * 32;
            const uint32_t qb = ((c + 1) & 1) * OQ_BUF * 4;
            const uint32_t cb = ((c + 1) & 1) * OC_BUF * 4;
#pragma unroll
            for (int i = 0; i < 4; ++i) {
                int row = i * 32 + lrow;
                cp_async16(Qs_u + qb + (row * OQ_PITCH + lcol) * 4,
                           Qg + (long)row * MM + kof + lcol);
            }
#pragma unroll
            for (int i = 0; i < 2; ++i)
                cp_async16(Cs_u + cb + (crow * OC_PITCH + (cc4 + i * 8) * 4) * 4,
                           Cg + (long)(kof + crow) * DD + (cc4 + i * 8) * 4);
            cp_commit();
        }

        const float* Qb = Qs + (c & 1) * OQ_BUF;
        const float* Cb = Cs + (c & 1) * OC_BUF;

#pragma unroll
        for (int ks = 0; ks < 4; ++ks) {
            const int k0 = ks * 8;
            uint32_t a[2][4];
#pragma unroll
            for (int mi = 0; mi < 2; ++mi) {
                int n = wn * 32 + mi * 16 + grp;
                a[mi][0] = __float_as_uint(Qb[n * OQ_PITCH + k0 + tig]);
                a[mi][1] = __float_as_uint(Qb[(n + 8) * OQ_PITCH + k0 + tig]);
                a[mi][2] = __float_as_uint(Qb[n * OQ_PITCH + k0 + tig + 4]);
                a[mi][3] = __float_as_uint(Qb[(n + 8) * OQ_PITCH + k0 + tig + 4]);
            }
            uint32_t b[4][2];
#pragma unroll
            for (int ni = 0; ni < 4; ++ni) {
                int e = we * 32 + ni * 8 + grp;
                b[ni][0] = to_tf32_u(Cb[(k0 + tig) * OC_PITCH + e]);
                b[ni][1] = to_tf32_u(Cb[(k0 + tig + 4) * OC_PITCH + e]);
            }
#pragma unroll
            for (int mi = 0; mi < 2; ++mi)
#pragma unroll
                for (int ni = 0; ni < 4; ++ni)
                    mma_tf32_16x8x8(acc[mi][ni], a[mi], b[ni]);
        }
    }

#pragma unroll
    for (int mi = 0; mi < 2; ++mi) {
        long n = n0 + wn * 32 + mi * 16 + grp;
        float dv0 = dinv[(long)h * NN + n];
        float dv1 = dinv[(long)h * NN + n + 8];
#pragma unroll
        for (int ni = 0; ni < 4; ++ni) {
            int e = we * 32 + ni * 8 + tig * 2;
            *(float2*)(out + ((long)h * NN + n) * DD + e) =
                make_float2(acc[mi][ni][0] * dv0, acc[mi][ni][1] * dv0);
            *(float2*)(out + ((long)h * NN + n + 8) * DD + e) =
                make_float2(acc[mi][ni][2] * dv1, acc[mi][ni][3] * dv1);
        }
    }
}

// ---------------- exp / dinv ----------------------------------------------------
// warp-per-row: per-row max, fast exp, tf32 + scaled-fp16 stores
__global__ void expq_kernel(float* __restrict__ dash, const float* __restrict__ diag,
                            __half* __restrict__ dash_h) {
    int row  = blockIdx.x * 8 + (threadIdx.x >> 5);
    int lane = threadIdx.x & 31;
    long base = (long)row * MM;
    float4 a = *(float4*)(dash + base + lane * 4);
    float4 b = *(float4*)(dash + base + 128 + lane * 4);
    float m = fmaxf(fmaxf(fmaxf(a.x, a.y), fmaxf(a.z, a.w)),
                    fmaxf(fmaxf(b.x, b.y), fmaxf(b.z, b.w)));
#pragma unroll
    for (int o = 16; o; o >>= 1) m = fmaxf(m, __shfl_xor_sync(0xffffffffu, m, o));
    float s = diag[row] + m;
    float4 ea, eb;
    ea.x = RATIO * (__expf(a.x - s) + FEPS);
    ea.y = RATIO * (__expf(a.y - s) + FEPS);
    ea.z = RATIO * (__expf(a.z - s) + FEPS);
    ea.w = RATIO * (__expf(a.w - s) + FEPS);
    eb.x = RATIO * (__expf(b.x - s) + FEPS);
    eb.y = RATIO * (__expf(b.y - s) + FEPS);
    eb.z = RATIO * (__expf(b.z - s) + FEPS);
    eb.w = RATIO * (__expf(b.w - s) + FEPS);
    float4 ta = make_float4(to_tf32(ea.x), to_tf32(ea.y), to_tf32(ea.z), to_tf32(ea.w));
    float4 tb = make_float4(to_tf32(eb.x), to_tf32(eb.y), to_tf32(eb.z), to_tf32(eb.w));
    *(float4*)(dash + base + lane * 4)       = ta;
    *(float4*)(dash + base + 128 + lane * 4) = tb;
    __half2* hp0 = (__half2*)(dash_h + base + lane * 4);
    __half2* hp1 = (__half2*)(dash_h + base + 128 + lane * 4);
    hp0[0] = __floats2half2_rn(ea.x * HSCALE, ea.y * HSCALE);
    hp0[1] = __floats2half2_rn(ea.z * HSCALE, ea.w * HSCALE);
    hp1[0] = __floats2half2_rn(eb.x * HSCALE, eb.y * HSCALE);
    hp1[1] = __floats2half2_rn(eb.z * HSCALE, eb.w * HSCALE);
}

__global__ void expk_kernel(float* __restrict__ dash, const float* __restrict__ diag,
                            const unsigned* __restrict__ kmax_enc, float* __restrict__ ksum,
                            __half* __restrict__ dash_h) {
    int t    = threadIdx.x;
    int row0 = blockIdx.x * 64;
    int h    = row0 >> 12;
    float stab  = dec_f(kmax_enc[0]);
    float local = 0.f;
    for (int r = 0; r < 64; ++r) {
        long idx = (long)(row0 + r) * MM + t;
        float vfull = RATIO * (__expf(dash[idx] - diag[row0 + r] - stab) + FEPS);
        float vv = to_tf32(vfull);
        dash[idx]   = vv;
        dash_h[idx] = __float2half_rn(vfull * HSCALE);
        local += vv;
    }
    atomicAdd(&ksum[h * MM + t], local);
}

__global__ void dinv_kernel(const float* __restrict__ qp, const float* __restrict__ ksum,
                            float* __restrict__ dinv) {
    int row  = blockIdx.x * 8 + (threadIdx.x >> 5);
    int lane = threadIdx.x & 31;
    int h    = row >> 12;
    const float* qr = qp + (long)row * MM;
    const float* ks = ksum + h * MM;
    float s = 0.f;
#pragma unroll
    for (int i = 0; i < 8; ++i) {
        int m = lane + i * 32;
        s += qr[m] * ks[m];
    }
#pragma unroll
    for (int o = 16; o; o >>= 1) s += __shfl_xor_sync(0xffffffffu, s, o);
    if (!lane) dinv[row] = 1.f / s;
}

// -------------------------------------------------------------------------------
extern "C" void kernel_launch(void* const* d_in, const int* in_sizes, int n_in,
                              void* d_out, int out_size)
{
    const float* q    = (const float*)d_in[0];
    const float* k    = (const float*)d_in[1];
    const float* v    = (const float*)d_in[2];
    const float* proj = (const float*)d_in[3];

    float* out_align = (float*)d_out;                       // [H,N,D]
    float* out_w     = out_align + (long)HH * NN * DD;      // [H,N,N]

    float *qp, *kp, *qdiag, *kdiag, *ksum, *dinv, *ctx;
    __half *qph, *kph;
    unsigned *kmaxe;
    cudaGetSymbolAddress((void**)&qp,    g_qp);
    cudaGetSymbolAddress((void**)&kp,    g_kp);
    cudaGetSymbolAddress((void**)&qph,   g_qph);
    cudaGetSymbolAddress((void**)&kph,   g_kph);
    cudaGetSymbolAddress((void**)&qdiag, g_qdiag);
    cudaGetSymbolAddress((void**)&kdiag, g_kdiag);
    cudaGetSymbolAddress((void**)&ksum,  g_ksum);
    cudaGetSymbolAddress((void**)&dinv,  g_dinv);
    cudaGetSymbolAddress((void**)&ctx,   g_ctx);
    cudaGetSymbolAddress((void**)&kmaxe, g_kmax_enc);

    static cudaStream_t s2 = nullptr;
    static cudaEvent_t  ev1, ev2;
    static bool attr_done = false;
    if (!attr_done) {
        cudaFuncSetAttribute(weights_mma, cudaFuncAttributeMaxDynamicSharedMemorySize, WF_SMEM);
        cudaFuncSetAttribute(proj_mma,    cudaFuncAttributeMaxDynamicSharedMemorySize, PJ_SMEM);
        cudaFuncSetAttribute(ctx_mma,     cudaFuncAttributeMaxDynamicSharedMemorySize, CTX_SMEM);
        cudaFuncSetAttribute(out_mma,     cudaFuncAttributeMaxDynamicSharedMemorySize, OUT_SMEM);
        cudaStreamCreateWithFlags(&s2, cudaStreamNonBlocking);
        cudaEventCreateWithFlags(&ev1, cudaEventDisableTiming);
        cudaEventCreateWithFlags(&ev2, cudaEventDisableTiming);
        attr_done = true;
    }

    zero_kernel<<<HH * MM * DD / 256, 256>>>();

    proj_mma<<<dim3(ROWS / 128, MM / 128), 256, PJ_SMEM>>>(q, proj, qp, qdiag, nullptr);
    proj_mma<<<dim3(ROWS / 128, MM / 128), 256, PJ_SMEM>>>(k, proj, kp, kdiag, kmaxe);

    expq_kernel<<<ROWS / 8, 256>>>(qp, qdiag, qph);
    expk_kernel<<<ROWS / 64, 256>>>(kp, kdiag, kmaxe, ksum, kph);

    // fork: side stream runs the small ctx->dinv->out chain concurrently with
    // the dominant weights GEMM on the main (capture) stream.
    cudaEventRecord(ev1, 0);
    cudaStreamWaitEvent(s2, ev1, 0);

    weights_mma<<<dim3(NN / 128, NN / 256, HH), 256, WF_SMEM>>>(qph, kph, out_w);

    ctx_mma<<<dim3(1, CTX_KSPLIT, HH), 256, CTX_SMEM, s2>>>(kp, v, ctx);
    dinv_kernel<<<ROWS / 8, 256, 0, s2>>>(qp, ksum, dinv);
    out_mma<<<dim3(NN / 128, HH), 256, OUT_SMEM, s2>>>(qp, ctx, dinv, out_align);

    cudaEventRecord(ev2, s2);
    cudaStreamWaitEvent(0, ev2, 0);
}

// round 12
// speedup vs baseline: 1.1195x; 1.0251x over previous
#include <cuda_runtime.h>
#include <cuda_fp16.h>
#include <math.h>
#include <stdint.h>

#define HH 16
#define NN 4096
#define DD 64
#define MM 256
#define ROWS (HH * NN)          // 65536

#define NORMALIZER 0.35355339059327373f  // 64^-0.25
#define DIAG_COEF  0.0625f               // 0.5 * 64^-0.5
#define RATIO      0.0625f               // 256^-0.5
#define FEPS       1e-4f
#define HSCALE     2048.0f               // lift fp16 features out of subnormals
#define HUNSCALE   (1.0f / 4194304.0f)   // 2^-22

// ---------------- scratch (device globals; no allocation allowed) -------------
__device__ float    g_qp[(size_t)ROWS * MM];
__device__ float    g_kp[(size_t)ROWS * MM];
__device__ __half   g_qph[(size_t)ROWS * MM];
__device__ __half   g_kph[(size_t)ROWS * MM];
__device__ float    g_qdiag[ROWS];
__device__ float    g_kdiag[ROWS];
__device__ float    g_ksum[HH * MM];
__device__ float    g_dinv[ROWS];
__device__ float    g_ctx[HH * MM * DD];
__device__ unsigned g_kmax_enc[1];

__device__ __forceinline__ float to_tf32(float x) {
    uint32_t r;
    asm("cvt.rna.tf32.f32 %0, %1;" : "=r"(r) : "f"(x));
    return __uint_as_float(r);
}
__device__ __forceinline__ uint32_t to_tf32_u(float x) {
    uint32_t r;
    asm("cvt.rna.tf32.f32 %0, %1;" : "=r"(r) : "f"(x));
    return r;
}
__device__ __forceinline__ uint32_t smem_u32(const void* p) {
    uint32_t a;
    asm("{ .reg .u64 t; cvta.to.shared.u64 t, %1; cvt.u32.u64 %0, t; }" : "=r"(a) : "l"(p));
    return a;
}
__device__ __forceinline__ void cp_async16(uint32_t dst, const void* src) {
    asm volatile("cp.async.ca.shared.global [%0], [%1], 16;" :: "r"(dst), "l"(src) : "memory");
}
__device__ __forceinline__ void cp_commit() {
    asm volatile("cp.async.commit_group;" ::: "memory");
}
template <int N> __device__ __forceinline__ void cp_wait() {
    asm volatile("cp.async.wait_group %0;" :: "n"(N) : "memory");
}
__device__ __forceinline__ void mma_tf32_16x8x8(float* d, const uint32_t* a, const uint32_t* b) {
    asm volatile(
        "mma.sync.aligned.m16n8k8.row.col.f32.tf32.tf32.f32 "
        "{%0,%1,%2,%3}, {%4,%5,%6,%7}, {%8,%9}, {%0,%1,%2,%3};"
        : "+f"(d[0]), "+f"(d[1]), "+f"(d[2]), "+f"(d[3])
        : "r"(a[0]), "r"(a[1]), "r"(a[2]), "r"(a[3]), "r"(b[0]), "r"(b[1]));
}
__device__ __forceinline__ void mma_f16_16x8x16(float* d, const uint32_t* a, const uint32_t* b) {
    asm volatile(
        "mma.sync.aligned.m16n8k16.row.col.f32.f16.f16.f32 "
        "{%0,%1,%2,%3}, {%4,%5,%6,%7}, {%8,%9}, {%0,%1,%2,%3};"
        : "+f"(d[0]), "+f"(d[1]), "+f"(d[2]), "+f"(d[3])
        : "r"(a[0]), "r"(a[1]), "r"(a[2]), "r"(a[3]), "r"(b[0]), "r"(b[1]));
}
#define LDSM_X4(r0, r1, r2, r3, addr) \
    asm volatile("ldmatrix.sync.aligned.m8n8.x4.shared.b16 {%0,%1,%2,%3}, [%4];" \
                 : "=r"(r0), "=r"(r1), "=r"(r2), "=r"(r3) : "r"(addr))

// monotonic float<->uint encoding for order-invariant atomic max (init = 0)
__device__ __forceinline__ unsigned enc_f(float f) {
    unsigned u = __float_as_uint(f);
    return (u & 0x80000000u) ? ~u : (u | 0x80000000u);
}
__device__ __forceinline__ float dec_f(unsigned u) {
    return (u & 0x80000000u) ? __uint_as_float(u ^ 0x80000000u) : __uint_as_float(~u);
}

// ---------------- zero accumulated scratch -------------------------------------
__global__ void zero_kernel() {
    int i = blockIdx.x * 256 + threadIdx.x;
    if (i < HH * MM) g_ksum[i] = 0.f;
    if (i == 0) g_kmax_enc[0] = 0u;
    g_ctx[i] = 0.f;
}

// ========== projections via 3xTF32 split: dash = alpha * X @ proj^T ===========
// Fused extras: per-row diag (blockIdx.y==0), optional global-max into kmax_enc.
#define PJ_PITCH 36
#define PJ_TILE  (128 * PJ_PITCH)
#define PJ_SMEM  (4 * PJ_TILE * 4)     // Ah, Al, Bh, Bl

__global__ __launch_bounds__(256) void proj_mma(
    const float* __restrict__ X, const float* __restrict__ P, float* __restrict__ C,
    float* __restrict__ diag, unsigned* kmax_enc)
{
    extern __shared__ float sm[];
    float* Ah = sm;
    float* Al = sm + PJ_TILE;
    float* Bh = sm + 2 * PJ_TILE;
    float* Bl = sm + 3 * PJ_TILE;

    const int t    = threadIdx.x;
    const int lane = t & 31;
    const int w    = t >> 5;
    const int wm   = w & 3;
    const int wn   = w >> 2;
    const int grp  = lane >> 2;
    const int tig  = lane & 3;

    const long i0 = (long)blockIdx.x * 128;
    const int  j0 = blockIdx.y * 128;

    const int lrow = t >> 3;
    const int lcol = (t & 7) * 4;

    float acc[2][8][4];
#pragma unroll
    for (int mi = 0; mi < 2; ++mi)
#pragma unroll
        for (int ni = 0; ni < 8; ++ni)
#pragma unroll
            for (int r = 0; r < 4; ++r) acc[mi][ni][r] = 0.f;

    float sq[4] = {0.f, 0.f, 0.f, 0.f};   // fused diag partial sums

#pragma unroll
    for (int c = 0; c < 2; ++c) {
        const int kof = c * 32;
#pragma unroll
        for (int i = 0; i < 4; ++i) {
            int row = i * 32 + lrow;
            float4 va = *(const float4*)(X + (i0 + row) * DD + kof + lcol);
            float4 vb = *(const float4*)(P + (long)(j0 + row) * DD + kof + lcol);
            sq[i] += va.x * va.x + va.y * va.y + va.z * va.z + va.w * va.w;
            float4 ah, al, bh, bl;
            ah.x = to_tf32(va.x); al.x = to_tf32(va.x - ah.x);
            ah.y = to_tf32(va.y); al.y = to_tf32(va.y - ah.y);
            ah.z = to_tf32(va.z); al.z = to_tf32(va.z - ah.z);
            ah.w = to_tf32(va.w); al.w = to_tf32(va.w - ah.w);
            bh.x = to_tf32(vb.x); bl.x = to_tf32(vb.x - bh.x);
            bh.y = to_tf32(vb.y); bl.y = to_tf32(vb.y - bh.y);
            bh.z = to_tf32(vb.z); bl.z = to_tf32(vb.z - bh.z);
            bh.w = to_tf32(vb.w); bl.w = to_tf32(vb.w - bh.w);
            *(float4*)&Ah[row * PJ_PITCH + lcol] = ah;
            *(float4*)&Al[row * PJ_PITCH + lcol] = al;
            *(float4*)&Bh[row * PJ_PITCH + lcol] = bh;
            *(float4*)&Bl[row * PJ_PITCH + lcol] = bl;
        }
        __syncthreads();

#pragma unroll
        for (int ks = 0; ks < 4; ++ks) {
            const int k0 = ks * 8;
            uint32_t ahr[2][4], alr[2][4];
#pragma unroll
            for (int mi = 0; mi < 2; ++mi) {
                int m = wm * 32 + mi * 16 + grp;
                ahr[mi][0] = __float_as_uint(Ah[m * PJ_PITCH + k0 + tig]);
                ahr[mi][1] = __float_as_uint(Ah[(m + 8) * PJ_PITCH + k0 + tig]);
                ahr[mi][2] = __float_as_uint(Ah[m * PJ_PITCH + k0 + tig + 4]);
                ahr[mi][3] = __float_as_uint(Ah[(m + 8) * PJ_PITCH + k0 + tig + 4]);
                alr[mi][0] = __float_as_uint(Al[m * PJ_PITCH + k0 + tig]);
                alr[mi][1] = __float_as_uint(Al[(m + 8) * PJ_PITCH + k0 + tig]);
                alr[mi][2] = __float_as_uint(Al[m * PJ_PITCH + k0 + tig + 4]);
                alr[mi][3] = __float_as_uint(Al[(m + 8) * PJ_PITCH + k0 + tig + 4]);
            }
#pragma unroll
            for (int ni = 0; ni < 8; ++ni) {
                int n = wn * 64 + ni * 8 + grp;
                uint32_t bhr[2], blr[2];
                bhr[0] = __float_as_uint(Bh[n * PJ_PITCH + k0 + tig]);
                bhr[1] = __float_as_uint(Bh[n * PJ_PITCH + k0 + tig + 4]);
                blr[0] = __float_as_uint(Bl[n * PJ_PITCH + k0 + tig]);
                blr[1] = __float_as_uint(Bl[n * PJ_PITCH + k0 + tig + 4]);
#pragma unroll
                for (int mi = 0; mi < 2; ++mi) {
                    mma_tf32_16x8x8(acc[mi][ni], ahr[mi], blr);
                    mma_tf32_16x8x8(acc[mi][ni], alr[mi], bhr);
                    mma_tf32_16x8x8(acc[mi][ni], ahr[mi], bhr);
                }
            }
        }
        __syncthreads();
    }

    if (blockIdx.y == 0) {
#pragma unroll
        for (int i = 0; i < 4; ++i) {
            float s = sq[i];
            s += __shfl_down_sync(0xffffffffu, s, 4, 8);
            s += __shfl_down_sync(0xffffffffu, s, 2, 8);
            s += __shfl_down_sync(0xffffffffu, s, 1, 8);
            if ((t & 7) == 0) diag[i0 + i * 32 + lrow] = s * DIAG_COEF;
        }
    }

    float lmax = -3.4e38f;
#pragma unroll
    for (int mi = 0; mi < 2; ++mi) {
        long row = i0 + wm * 32 + mi * 16 + grp;
#pragma unroll
        for (int ni = 0; ni < 8; ++ni) {
            long col = j0 + wn * 64 + ni * 8 + tig * 2;
            float2 v0 = make_float2(acc[mi][ni][0] * NORMALIZER, acc[mi][ni][1] * NORMALIZER);
            float2 v1 = make_float2(acc[mi][ni][2] * NORMALIZER, acc[mi][ni][3] * NORMALIZER);
            *(float2*)(C + row * MM + col)       = v0;
            *(float2*)(C + (row + 8) * MM + col) = v1;
            lmax = fmaxf(lmax, fmaxf(fmaxf(v0.x, v0.y), fmaxf(v1.x, v1.y)));
        }
    }
    if (kmax_enc) {
#pragma unroll
        for (int o = 16; o; o >>= 1) lmax = fmaxf(lmax, __shfl_xor_sync(0xffffffffu, lmax, o));
        if (lane == 0) atomicMax(kmax_enc, enc_f(lmax));
    }
}

// ============ weights[h] = qp[h] @ kp[h]^T via mma.sync fp16 + ldmatrix ========
// 4-stage cp.async pipeline (prefetch distance 2 chunks), 256x128 CTA tile.
#define WF_PITCH  40
#define WF_ABUF   (256 * WF_PITCH)       // halves per A stage
#define WF_BBUF   (128 * WF_PITCH)       // halves per B stage
#define WF_STAGE  (WF_ABUF + WF_BBUF)
#define WF_SMEM   (4 * WF_STAGE * 2)     // 122880 B

__global__ __launch_bounds__(256) void weights_mma(
    const __half* __restrict__ qp, const __half* __restrict__ kp, float* __restrict__ outw)
{
    extern __shared__ __half smh[];

    const int t    = threadIdx.x;
    const int lane = t & 31;
    const int w    = t >> 5;
    const int wm   = w & 3;             // 4 warps in M (64 rows each)
    const int wn   = w >> 2;            // 2 warps in N (64 cols each)
    const int grp  = lane >> 2;
    const int tig  = lane & 3;

    const int lr8     = lane & 7;
    const int lg      = lane >> 3;
    const int rowOff  = (lg & 1) * 8 + lr8;
    const int colOff  = (lg >> 1) * 8;

    const int h   = blockIdx.z;
    const long i0 = (long)blockIdx.y * 256;
    const long j0 = (long)blockIdx.x * 128;

    const __half* Ag = qp + ((long)h * NN + i0) * MM;
    const __half* Bg = kp + ((long)h * NN + j0) * MM;

    const int arow = t >> 2;            // 0..63
    const int ac8  = (t & 3) * 8;

    float acc[4][8][4];
#pragma unroll
    for (int mi = 0; mi < 4; ++mi)
#pragma unroll
        for (int ni = 0; ni < 8; ++ni)
#pragma unroll
            for (int r = 0; r < 4; ++r) acc[mi][ni][r] = 0.f;

    uint32_t base_u = smem_u32(smh);

    // prologue: issue chunks 0,1,2 into stages 0,1,2
#pragma unroll
    for (int pc = 0; pc < 3; ++pc) {
        const uint32_t su = base_u + pc * WF_STAGE * 2;
        const int kof = pc * 32;
#pragma unroll
        for (int i = 0; i < 4; ++i) {
            int row = i * 64 + arow;
            cp_async16(su + (row * WF_PITCH + ac8) * 2, Ag + (long)row * MM + kof + ac8);
        }
#pragma unroll
        for (int i = 0; i < 2; ++i) {
            int row = i * 64 + arow;
            cp_async16(su + (WF_ABUF + row * WF_PITCH + ac8) * 2, Bg + (long)row * MM + kof + ac8);
        }
        cp_commit();
    }

#pragma unroll 1
    for (int c = 0; c < 8; ++c) {
        cp_wait<2>();
        __syncthreads();
        if (c < 5) {
            const int kof = (c + 3) * 32;
            const uint32_t su = base_u + ((c + 3) & 3) * WF_STAGE * 2;
#pragma unroll
            for (int i = 0; i < 4; ++i) {
                int row = i * 64 + arow;
                cp_async16(su + (row * WF_PITCH + ac8) * 2, Ag + (long)row * MM + kof + ac8);
            }
#pragma unroll
            for (int i = 0; i < 2; ++i) {
                int row = i * 64 + arow;
                cp_async16(su + (WF_ABUF + row * WF_PITCH + ac8) * 2,
                           Bg + (long)row * MM + kof + ac8);
            }
            cp_commit();
        } else {
            cp_commit();   // keep group counting uniform for wait<2>
        }

        const uint32_t AbU = base_u + (c & 3) * WF_STAGE * 2;
        const uint32_t BbU = AbU + WF_ABUF * 2;

#pragma unroll
        for (int ks = 0; ks < 2; ++ks) {
            const int k0 = ks * 16;
            uint32_t a[4][4];
#pragma unroll
            for (int mi = 0; mi < 4; ++mi) {
                int m = wm * 64 + mi * 16 + rowOff;
                uint32_t addr = AbU + (uint32_t)(m * WF_PITCH + k0 + colOff) * 2;
                LDSM_X4(a[mi][0], a[mi][1], a[mi][2], a[mi][3], addr);
            }
            uint32_t b[8][2];
#pragma unroll
            for (int p = 0; p < 4; ++p) {
                int n = wn * 64 + p * 16 + rowOff;
                uint32_t addr = BbU + (uint32_t)(n * WF_PITCH + k0 + colOff) * 2;
                uint32_t r0, r1, r2, r3;
                LDSM_X4(r0, r1, r2, r3, addr);
                b[2 * p][0]     = r0;
                b[2 * p + 1][0] = r1;
                b[2 * p][1]     = r2;
                b[2 * p + 1][1] = r3;
            }
#pragma unroll
            for (int mi = 0; mi < 4; ++mi)
#pragma unroll
                for (int ni = 0; ni < 8; ++ni)
                    mma_f16_16x8x16(acc[mi][ni], a[mi], b[ni]);
        }
    }

    float* Cp = outw + (long)h * NN * NN;
#pragma unroll
    for (int mi = 0; mi < 4; ++mi) {
        long row = i0 + wm * 64 + mi * 16 + grp;
#pragma unroll
        for (int ni = 0; ni < 8; ++ni) {
            long col = j0 + wn * 64 + ni * 8 + tig * 2;
            *(float2*)(Cp + row * NN + col) =
                make_float2(acc[mi][ni][0] * HUNSCALE, acc[mi][ni][1] * HUNSCALE);
            *(float2*)(Cp + (row + 8) * NN + col) =
                make_float2(acc[mi][ni][2] * HUNSCALE, acc[mi][ni][3] * HUNSCALE);
        }
    }
}

// ======= ctx[h][m][e] = sum_n kp[h][n][m] * v[h][n][e]  via mma tf32 ==========
#define CTX_KSPLIT 16
#define CTX_KC     32
#define KS_PITCH   260
#define VS_PITCH   68
#define KS_BUF     (CTX_KC * KS_PITCH)
#define VS_BUF     (CTX_KC * VS_PITCH)
#define CTX_SMEM   ((2 * KS_BUF + 2 * VS_BUF) * 4)

__global__ __launch_bounds__(256) void ctx_mma(
    const float* __restrict__ kp, const float* __restrict__ v, float* __restrict__ ctx)
{
    extern __shared__ float sm[];
    float* Ks = sm;
    float* Vs = sm + 2 * KS_BUF;

    const int t    = threadIdx.x;
    const int lane = t & 31;
    const int w    = t >> 5;
    const int wm   = w & 3;
    const int we   = w >> 2;
    const int grp  = lane >> 2;
    const int tig  = lane & 3;

    const int h     = blockIdx.z;
    const int nbase = blockIdx.y * (NN / CTX_KSPLIT);

    const float* Kg = kp + ((long)h * NN + nbase) * MM;
    const float* Vg = v  + ((long)h * NN + nbase) * DD;

    const int krow = t >> 3;
    const int c4   = t & 7;

    float acc[4][4][4];
#pragma unroll
    for (int mi = 0; mi < 4; ++mi)
#pragma unroll
        for (int ni = 0; ni < 4; ++ni)
#pragma unroll
            for (int r = 0; r < 4; ++r) acc[mi][ni][r] = 0.f;

    uint32_t Ks_u = smem_u32(Ks);
    uint32_t Vs_u = smem_u32(Vs);

#pragma unroll
    for (int i = 0; i < 8; ++i)
        cp_async16(Ks_u + (krow * KS_PITCH + (c4 + i * 8) * 4) * 4,
                   Kg + (long)krow * MM + (c4 + i * 8) * 4);
#pragma unroll
    for (int i = 0; i < 2; ++i)
        cp_async16(Vs_u + (krow * VS_PITCH + (c4 + i * 8) * 4) * 4,
                   Vg + (long)krow * DD + (c4 + i * 8) * 4);
    cp_commit();

#pragma unroll 1
    for (int c = 0; c < 8; ++c) {
        cp_wait<0>();
        __syncthreads();
        if (c < 7) {
            const int nof = (c + 1) * CTX_KC;
            const uint32_t kb = ((c + 1) & 1) * KS_BUF * 4;
            const uint32_t vb = ((c + 1) & 1) * VS_BUF * 4;
#pragma unroll
            for (int i = 0; i < 8; ++i)
                cp_async16(Ks_u + kb + (krow * KS_PITCH + (c4 + i * 8) * 4) * 4,
                           Kg + (long)(nof + krow) * MM + (c4 + i * 8) * 4);
#pragma unroll
            for (int i = 0; i < 2; ++i)
                cp_async16(Vs_u + vb + (krow * VS_PITCH + (c4 + i * 8) * 4) * 4,
                           Vg + (long)(nof + krow) * DD + (c4 + i * 8) * 4);
            cp_commit();
        }

        const float* Kb = Ks + (c & 1) * KS_BUF;
        const float* Vb = Vs + (c & 1) * VS_BUF;

#pragma unroll
        for (int ks = 0; ks < 4; ++ks) {
            const int k0 = ks * 8;
            uint32_t a[4][4];
#pragma unroll
            for (int mi = 0; mi < 4; ++mi) {
                int m = wm * 64 + mi * 16 + grp;
                a[mi][0] = __float_as_uint(Kb[(k0 + tig) * KS_PITCH + m]);
                a[mi][1] = __float_as_uint(Kb[(k0 + tig) * KS_PITCH + m + 8]);
                a[mi][2] = __float_as_uint(Kb[(k0 + tig + 4) * KS_PITCH + m]);
                a[mi][3] = __float_as_uint(Kb[(k0 + tig + 4) * KS_PITCH + m + 8]);
            }
            uint32_t b[4][2];
#pragma unroll
            for (int ni = 0; ni < 4; ++ni) {
                int e = we * 32 + ni * 8 + grp;
                b[ni][0] = to_tf32_u(Vb[(k0 + tig) * VS_PITCH + e]);
                b[ni][1] = to_tf32_u(Vb[(k0 + tig + 4) * VS_PITCH + e]);
            }
#pragma unroll
            for (int mi = 0; mi < 4; ++mi)
#pragma unroll
                for (int ni = 0; ni < 4; ++ni)
                    mma_tf32_16x8x8(acc[mi][ni], a[mi], b[ni]);
        }
    }

#pragma unroll
    for (int mi = 0; mi < 4; ++mi) {
        int m = wm * 64 + mi * 16 + grp;
#pragma unroll
        for (int ni = 0; ni < 4; ++ni) {
            int e = we * 32 + ni * 8 + tig * 2;
            float* p0 = &ctx[((long)h * MM + m) * DD + e];
            float* p1 = &ctx[((long)h * MM + m + 8) * DD + e];
            atomicAdd(p0,     acc[mi][ni][0]);
            atomicAdd(p0 + 1, acc[mi][ni][1]);
            atomicAdd(p1,     acc[mi][ni][2]);
            atomicAdd(p1 + 1, acc[mi][ni][3]);
        }
    }
}

// ======= out[h][n][e] = dinv[n] * sum_m qp[h][n][m] * ctx[h][m][e]  (mma) =====
#define OQ_PITCH 36
#define OC_PITCH 68
#define OQ_BUF   (128 * OQ_PITCH)
#define OC_BUF   (32 * OC_PITCH)
#define OUT_SMEM ((2 * OQ_BUF + 2 * OC_BUF) * 4)

__global__ __launch_bounds__(256) void out_mma(
    const float* __restrict__ qp, const float* __restrict__ ctx,
    const float* __restrict__ dinv, float* __restrict__ out)
{
    extern __shared__ float sm[];
    float* Qs = sm;
    float* Cs = sm + 2 * OQ_BUF;

    const int t    = threadIdx.x;
    const int lane = t & 31;
    const int w    = t >> 5;
    const int wn   = w & 3;
    const int we   = w >> 2;
    const int grp  = lane >> 2;
    const int tig  = lane & 3;

    const int h  = blockIdx.y;
    const long n0 = (long)blockIdx.x * 128;

    const float* Qg = qp  + ((long)h * NN + n0) * MM;
    const float* Cg = ctx + (long)h * MM * DD;

    const int lrow = t >> 3;
    const int lcol = (t & 7) * 4;
    const int crow = t >> 3;
    const int cc4  = t & 7;

    float acc[2][4][4];
#pragma unroll
    for (int mi = 0; mi < 2; ++mi)
#pragma unroll
        for (int ni = 0; ni < 4; ++ni)
#pragma unroll
            for (int r = 0; r < 4; ++r) acc[mi][ni][r] = 0.f;

    uint32_t Qs_u = smem_u32(Qs);
    uint32_t Cs_u = smem_u32(Cs);

#pragma unroll
    for (int i = 0; i < 4; ++i) {
        int row = i * 32 + lrow;
        cp_async16(Qs_u + (row * OQ_PITCH + lcol) * 4, Qg + (long)row * MM + lcol);
    }
#pragma unroll
    for (int i = 0; i < 2; ++i)
        cp_async16(Cs_u + (crow * OC_PITCH + (cc4 + i * 8) * 4) * 4,
                   Cg + (long)crow * DD + (cc4 + i * 8) * 4);
    cp_commit();

#pragma unroll 1
    for (int c = 0; c < 8; ++c) {
        cp_wait<0>();
        __syncthreads();
        if (c < 7) {
            const int kof = (c + 1) * 32;
            const uint32_t qb = ((c + 1) & 1) * OQ_BUF * 4;
            const uint32_t cb = ((c + 1) & 1) * OC_BUF * 4;
#pragma unroll
            for (int i = 0; i < 4; ++i) {
                int row = i * 32 + lrow;
                cp_async16(Qs_u + qb + (row * OQ_PITCH + lcol) * 4,
                           Qg + (long)row * MM + kof + lcol);
            }
#pragma unroll
            for (int i = 0; i < 2; ++i)
                cp_async16(Cs_u + cb + (crow * OC_PITCH + (cc4 + i * 8) * 4) * 4,
                           Cg + (long)(kof + crow) * DD + (cc4 + i * 8) * 4);
            cp_commit();
        }

        const float* Qb = Qs + (c & 1) * OQ_BUF;
        const float* Cb = Cs + (c & 1) * OC_BUF;

#pragma unroll
        for (int ks = 0; ks < 4; ++ks) {
            const int k0 = ks * 8;
            uint32_t a[2][4];
#pragma unroll
            for (int mi = 0; mi < 2; ++mi) {
                int n = wn * 32 + mi * 16 + grp;
                a[mi][0] = __float_as_uint(Qb[n * OQ_PITCH + k0 + tig]);
                a[mi][1] = __float_as_uint(Qb[(n + 8) * OQ_PITCH + k0 + tig]);
                a[mi][2] = __float_as_uint(Qb[n * OQ_PITCH + k0 + tig + 4]);
                a[mi][3] = __float_as_uint(Qb[(n + 8) * OQ_PITCH + k0 + tig + 4]);
            }
            uint32_t b[4][2];
#pragma unroll
            for (int ni = 0; ni < 4; ++ni) {
                int e = we * 32 + ni * 8 + grp;
                b[ni][0] = to_tf32_u(Cb[(k0 + tig) * OC_PITCH + e]);
                b[ni][1] = to_tf32_u(Cb[(k0 + tig + 4) * OC_PITCH + e]);
            }
#pragma unroll
            for (int mi = 0; mi < 2; ++mi)
#pragma unroll
                for (int ni = 0; ni < 4; ++ni)
                    mma_tf32_16x8x8(acc[mi][ni], a[mi], b[ni]);
        }
    }

#pragma unroll
    for (int mi = 0; mi < 2; ++mi) {
        long n = n0 + wn * 32 + mi * 16 + grp;
        float dv0 = dinv[(long)h * NN + n];
        float dv1 = dinv[(long)h * NN + n + 8];
#pragma unroll
        for (int ni = 0; ni < 4; ++ni) {
            int e = we * 32 + ni * 8 + tig * 2;
            *(float2*)(out + ((long)h * NN + n) * DD + e) =
                make_float2(acc[mi][ni][0] * dv0, acc[mi][ni][1] * dv0);
            *(float2*)(out + ((long)h * NN + n + 8) * DD + e) =
                make_float2(acc[mi][ni][2] * dv1, acc[mi][ni][3] * dv1);
        }
    }
}

// ---------------- exp / dinv ----------------------------------------------------
__global__ void expq_kernel(float* __restrict__ dash, const float* __restrict__ diag,
                            __half* __restrict__ dash_h) {
    int row  = blockIdx.x * 8 + (threadIdx.x >> 5);
    int lane = threadIdx.x & 31;
    long base = (long)row * MM;
    float4 a = *(float4*)(dash + base + lane * 4);
    float4 b = *(float4*)(dash + base + 128 + lane * 4);
    float m = fmaxf(fmaxf(fmaxf(a.x, a.y), fmaxf(a.z, a.w)),
                    fmaxf(fmaxf(b.x, b.y), fmaxf(b.z, b.w)));
#pragma unroll
    for (int o = 16; o; o >>= 1) m = fmaxf(m, __shfl_xor_sync(0xffffffffu, m, o));
    float s = diag[row] + m;
    float4 ea, eb;
    ea.x = RATIO * (__expf(a.x - s) + FEPS);
    ea.y = RATIO * (__expf(a.y - s) + FEPS);
    ea.z = RATIO * (__expf(a.z - s) + FEPS);
    ea.w = RATIO * (__expf(a.w - s) + FEPS);
    eb.x = RATIO * (__expf(b.x - s) + FEPS);
    eb.y = RATIO * (__expf(b.y - s) + FEPS);
    eb.z = RATIO * (__expf(b.z - s) + FEPS);
    eb.w = RATIO * (__expf(b.w - s) + FEPS);
    float4 ta = make_float4(to_tf32(ea.x), to_tf32(ea.y), to_tf32(ea.z), to_tf32(ea.w));
    float4 tb = make_float4(to_tf32(eb.x), to_tf32(eb.y), to_tf32(eb.z), to_tf32(eb.w));
    *(float4*)(dash + base + lane * 4)       = ta;
    *(float4*)(dash + base + 128 + lane * 4) = tb;
    __half2* hp0 = (__half2*)(dash_h + base + lane * 4);
    __half2* hp1 = (__half2*)(dash_h + base + 128 + lane * 4);
    hp0[0] = __floats2half2_rn(ea.x * HSCALE, ea.y * HSCALE);
    hp0[1] = __floats2half2_rn(ea.z * HSCALE, ea.w * HSCALE);
    hp1[0] = __floats2half2_rn(eb.x * HSCALE, eb.y * HSCALE);
    hp1[1] = __floats2half2_rn(eb.z * HSCALE, eb.w * HSCALE);
}

__global__ void expk_kernel(float* __restrict__ dash, const float* __restrict__ diag,
                            const unsigned* __restrict__ kmax_enc, float* __restrict__ ksum,
                            __half* __restrict__ dash_h) {
    int t    = threadIdx.x;
    int row0 = blockIdx.x * 64;
    int h    = row0 >> 12;
    float stab  = dec_f(kmax_enc[0]);
    float local = 0.f;
    for (int r = 0; r < 64; ++r) {
        long idx = (long)(row0 + r) * MM + t;
        float vfull = RATIO * (__expf(dash[idx] - diag[row0 + r] - stab) + FEPS);
        float vv = to_tf32(vfull);
        dash[idx]   = vv;
        dash_h[idx] = __float2half_rn(vfull * HSCALE);
        local += vv;
    }
    atomicAdd(&ksum[h * MM + t], local);
}

__global__ void dinv_kernel(const float* __restrict__ qp, const float* __restrict__ ksum,
                            float* __restrict__ dinv) {
    int row  = blockIdx.x * 8 + (threadIdx.x >> 5);
    int lane = threadIdx.x & 31;
    int h    = row >> 12;
    const float* qr = qp + (long)row * MM;
    const float* ks = ksum + h * MM;
    float s = 0.f;
#pragma unroll
    for (int i = 0; i < 8; ++i) {
        int m = lane + i * 32;
        s += qr[m] * ks[m];
    }
#pragma unroll
    for (int o = 16; o; o >>= 1) s += __shfl_xor_sync(0xffffffffu, s, o);
    if (!lane) dinv[row] = 1.f / s;
}

// -------------------------------------------------------------------------------
extern "C" void kernel_launch(void* const* d_in, const int* in_sizes, int n_in,
                              void* d_out, int out_size)
{
    const float* q    = (const float*)d_in[0];
    const float* k    = (const float*)d_in[1];
    const float* v    = (const float*)d_in[2];
    const float* proj = (const float*)d_in[3];

    float* out_align = (float*)d_out;                       // [H,N,D]
    float* out_w     = out_align + (long)HH * NN * DD;      // [H,N,N]

    float *qp, *kp, *qdiag, *kdiag, *ksum, *dinv, *ctx;
    __half *qph, *kph;
    unsigned *kmaxe;
    cudaGetSymbolAddress((void**)&qp,    g_qp);
    cudaGetSymbolAddress((void**)&kp,    g_kp);
    cudaGetSymbolAddress((void**)&qph,   g_qph);
    cudaGetSymbolAddress((void**)&kph,   g_kph);
    cudaGetSymbolAddress((void**)&qdiag, g_qdiag);
    cudaGetSymbolAddress((void**)&kdiag, g_kdiag);
    cudaGetSymbolAddress((void**)&ksum,  g_ksum);
    cudaGetSymbolAddress((void**)&dinv,  g_dinv);
    cudaGetSymbolAddress((void**)&ctx,   g_ctx);
    cudaGetSymbolAddress((void**)&kmaxe, g_kmax_enc);

    static cudaStream_t s2 = nullptr;
    static cudaEvent_t  ev1, ev2, ev3, ev4;
    static bool attr_done = false;
    if (!attr_done) {
        cudaFuncSetAttribute(weights_mma, cudaFuncAttributeMaxDynamicSharedMemorySize, WF_SMEM);
        cudaFuncSetAttribute(proj_mma,    cudaFuncAttributeMaxDynamicSharedMemorySize, PJ_SMEM);
        cudaFuncSetAttribute(ctx_mma,     cudaFuncAttributeMaxDynamicSharedMemorySize, CTX_SMEM);
        cudaFuncSetAttribute(out_mma,     cudaFuncAttributeMaxDynamicSharedMemorySize, OUT_SMEM);
        cudaStreamCreateWithFlags(&s2, cudaStreamNonBlocking);
        cudaEventCreateWithFlags(&ev1, cudaEventDisableTiming);
        cudaEventCreateWithFlags(&ev2, cudaEventDisableTiming);
        cudaEventCreateWithFlags(&ev3, cudaEventDisableTiming);
        cudaEventCreateWithFlags(&ev4, cudaEventDisableTiming);
        attr_done = true;
    }

    zero_kernel<<<HH * MM * DD / 256, 256>>>();

    // fork: q-chain on s2, k-chain on main, running concurrently
    cudaEventRecord(ev1, 0);
    cudaStreamWaitEvent(s2, ev1, 0);

    proj_mma<<<dim3(ROWS / 128, MM / 128), 256, PJ_SMEM, s2>>>(q, proj, qp, qdiag, nullptr);
    expq_kernel<<<ROWS / 8, 256, 0, s2>>>(qp, qdiag, qph);
    cudaEventRecord(ev3, s2);

    proj_mma<<<dim3(ROWS / 128, MM / 128), 256, PJ_SMEM>>>(k, proj, kp, kdiag, kmaxe);
    expk_kernel<<<ROWS / 64, 256>>>(kp, kdiag, kmaxe, ksum, kph);
    cudaEventRecord(ev4, 0);

    // join: weights needs qph (s2) + kph (main)
    cudaStreamWaitEvent(0, ev3, 0);
    weights_mma<<<dim3(NN / 128, NN / 256, HH), 256, WF_SMEM>>>(qph, kph, out_w);

    // side chain on s2: needs both chains (ev4 covers k-chain; s2 already ran q-chain)
    cudaStreamWaitEvent(s2, ev4, 0);
    ctx_mma<<<dim3(1, CTX_KSPLIT, HH), 256, CTX_SMEM, s2>>>(kp, v, ctx);
    dinv_kernel<<<ROWS / 8, 256, 0, s2>>>(qp, ksum, dinv);
    out_mma<<<dim3(NN / 128, HH), 256, OUT_SMEM, s2>>>(qp, ctx, dinv, out_align);

    cudaEventRecord(ev2, s2);
    cudaStreamWaitEvent(0, ev2, 0);
}

// round 13
// speedup vs baseline: 1.1726x; 1.0475x over previous
#include <cuda_runtime.h>
#include <cuda_fp16.h>
#include <math.h>
#include <stdint.h>

#define HH 16
#define NN 4096
#define DD 64
#define MM 256
#define ROWS (HH * NN)          // 65536

#define NORMALIZER 0.35355339059327373f  // 64^-0.25
#define DIAG_COEF  0.0625f               // 0.5 * 64^-0.5
#define RATIO      0.0625f               // 256^-0.5
#define FEPS       1e-4f
#define HSCALE     2048.0f               // lift fp16 features out of subnormals
#define HUNSCALE   (1.0f / 4194304.0f)   // 2^-22

// ---------------- scratch (device globals; no allocation allowed) -------------
__device__ float    g_qp[(size_t)ROWS * MM];
__device__ float    g_kp[(size_t)ROWS * MM];
__device__ __half   g_qph[(size_t)ROWS * MM];
__device__ __half   g_kph[(size_t)ROWS * MM];
__device__ float    g_qdiag[ROWS];
__device__ float    g_kdiag[ROWS];
__device__ float    g_ksum[HH * MM];
__device__ float    g_dinv[ROWS];
__device__ float    g_ctx[HH * MM * DD];
__device__ unsigned g_kmax_enc[1];

__device__ __forceinline__ float to_tf32(float x) {
    uint32_t r;
    asm("cvt.rna.tf32.f32 %0, %1;" : "=r"(r) : "f"(x));
    return __uint_as_float(r);
}
__device__ __forceinline__ uint32_t to_tf32_u(float x) {
    uint32_t r;
    asm("cvt.rna.tf32.f32 %0, %1;" : "=r"(r) : "f"(x));
    return r;
}
__device__ __forceinline__ uint32_t smem_u32(const void* p) {
    uint32_t a;
    asm("{ .reg .u64 t; cvta.to.shared.u64 t, %1; cvt.u32.u64 %0, t; }" : "=r"(a) : "l"(p));
    return a;
}
__device__ __forceinline__ void cp_async16(uint32_t dst, const void* src) {
    asm volatile("cp.async.ca.shared.global [%0], [%1], 16;" :: "r"(dst), "l"(src) : "memory");
}
__device__ __forceinline__ void cp_commit() {
    asm volatile("cp.async.commit_group;" ::: "memory");
}
template <int N> __device__ __forceinline__ void cp_wait() {
    asm volatile("cp.async.wait_group %0;" :: "n"(N) : "memory");
}
__device__ __forceinline__ void mma_tf32_16x8x8(float* d, const uint32_t* a, const uint32_t* b) {
    asm volatile(
        "mma.sync.aligned.m16n8k8.row.col.f32.tf32.tf32.f32 "
        "{%0,%1,%2,%3}, {%4,%5,%6,%7}, {%8,%9}, {%0,%1,%2,%3};"
        : "+f"(d[0]), "+f"(d[1]), "+f"(d[2]), "+f"(d[3])
        : "r"(a[0]), "r"(a[1]), "r"(a[2]), "r"(a[3]), "r"(b[0]), "r"(b[1]));
}
__device__ __forceinline__ void mma_f16_16x8x16(float* d, const uint32_t* a, const uint32_t* b) {
    asm volatile(
        "mma.sync.aligned.m16n8k16.row.col.f32.f16.f16.f32 "
        "{%0,%1,%2,%3}, {%4,%5,%6,%7}, {%8,%9}, {%0,%1,%2,%3};"
        : "+f"(d[0]), "+f"(d[1]), "+f"(d[2]), "+f"(d[3])
        : "r"(a[0]), "r"(a[1]), "r"(a[2]), "r"(a[3]), "r"(b[0]), "r"(b[1]));
}
#define LDSM_X4(r0, r1, r2, r3, addr) \
    asm volatile("ldmatrix.sync.aligned.m8n8.x4.shared.b16 {%0,%1,%2,%3}, [%4];" \
                 : "=r"(r0), "=r"(r1), "=r"(r2), "=r"(r3) : "r"(addr))

// monotonic float<->uint encoding for order-invariant atomic max (init = 0)
__device__ __forceinline__ unsigned enc_f(float f) {
    unsigned u = __float_as_uint(f);
    return (u & 0x80000000u) ? ~u : (u | 0x80000000u);
}
__device__ __forceinline__ float dec_f(unsigned u) {
    return (u & 0x80000000u) ? __uint_as_float(u ^ 0x80000000u) : __uint_as_float(~u);
}

// ---------------- zero accumulated scratch -------------------------------------
__global__ void zero_kernel() {
    int i = blockIdx.x * 256 + threadIdx.x;
    if (i < HH * MM) g_ksum[i] = 0.f;
    if (i == 0) g_kmax_enc[0] = 0u;
    g_ctx[i] = 0.f;
}

// ========== projections via 3xTF32 split: dash = alpha * X @ proj^T ===========
#define PJ_PITCH 36
#define PJ_TILE  (128 * PJ_PITCH)
#define PJ_SMEM  (4 * PJ_TILE * 4)     // Ah, Al, Bh, Bl

__global__ __launch_bounds__(256) void proj_mma(
    const float* __restrict__ X, const float* __restrict__ P, float* __restrict__ C,
    float* __restrict__ diag, unsigned* kmax_enc)
{
    extern __shared__ float sm[];
    float* Ah = sm;
    float* Al = sm + PJ_TILE;
    float* Bh = sm + 2 * PJ_TILE;
    float* Bl = sm + 3 * PJ_TILE;

    const int t    = threadIdx.x;
    const int lane = t & 31;
    const int w    = t >> 5;
    const int wm   = w & 3;
    const int wn   = w >> 2;
    const int grp  = lane >> 2;
    const int tig  = lane & 3;

    const long i0 = (long)blockIdx.x * 128;
    const int  j0 = blockIdx.y * 128;

    const int lrow = t >> 3;
    const int lcol = (t & 7) * 4;

    float acc[2][8][4];
#pragma unroll
    for (int mi = 0; mi < 2; ++mi)
#pragma unroll
        for (int ni = 0; ni < 8; ++ni)
#pragma unroll
            for (int r = 0; r < 4; ++r) acc[mi][ni][r] = 0.f;

    float sq[4] = {0.f, 0.f, 0.f, 0.f};   // fused diag partial sums

#pragma unroll
    for (int c = 0; c < 2; ++c) {
        const int kof = c * 32;
#pragma unroll
        for (int i = 0; i < 4; ++i) {
            int row = i * 32 + lrow;
            float4 va = *(const float4*)(X + (i0 + row) * DD + kof + lcol);
            float4 vb = *(const float4*)(P + (long)(j0 + row) * DD + kof + lcol);
            sq[i] += va.x * va.x + va.y * va.y + va.z * va.z + va.w * va.w;
            float4 ah, al, bh, bl;
            ah.x = to_tf32(va.x); al.x = to_tf32(va.x - ah.x);
            ah.y = to_tf32(va.y); al.y = to_tf32(va.y - ah.y);
            ah.z = to_tf32(va.z); al.z = to_tf32(va.z - ah.z);
            ah.w = to_tf32(va.w); al.w = to_tf32(va.w - ah.w);
            bh.x = to_tf32(vb.x); bl.x = to_tf32(vb.x - bh.x);
            bh.y = to_tf32(vb.y); bl.y = to_tf32(vb.y - bh.y);
            bh.z = to_tf32(vb.z); bl.z = to_tf32(vb.z - bh.z);
            bh.w = to_tf32(vb.w); bl.w = to_tf32(vb.w - bh.w);
            *(float4*)&Ah[row * PJ_PITCH + lcol] = ah;
            *(float4*)&Al[row * PJ_PITCH + lcol] = al;
            *(float4*)&Bh[row * PJ_PITCH + lcol] = bh;
            *(float4*)&Bl[row * PJ_PITCH + lcol] = bl;
        }
        __syncthreads();

#pragma unroll
        for (int ks = 0; ks < 4; ++ks) {
            const int k0 = ks * 8;
            uint32_t ahr[2][4], alr[2][4];
#pragma unroll
            for (int mi = 0; mi < 2; ++mi) {
                int m = wm * 32 + mi * 16 + grp;
                ahr[mi][0] = __float_as_uint(Ah[m * PJ_PITCH + k0 + tig]);
                ahr[mi][1] = __float_as_uint(Ah[(m + 8) * PJ_PITCH + k0 + tig]);
                ahr[mi][2] = __float_as_uint(Ah[m * PJ_PITCH + k0 + tig + 4]);
                ahr[mi][3] = __float_as_uint(Ah[(m + 8) * PJ_PITCH + k0 + tig + 4]);
                alr[mi][0] = __float_as_uint(Al[m * PJ_PITCH + k0 + tig]);
                alr[mi][1] = __float_as_uint(Al[(m + 8) * PJ_PITCH + k0 + tig]);
                alr[mi][2] = __float_as_uint(Al[m * PJ_PITCH + k0 + tig + 4]);
                alr[mi][3] = __float_as_uint(Al[(m + 8) * PJ_PITCH + k0 + tig + 4]);
            }
#pragma unroll
            for (int ni = 0; ni < 8; ++ni) {
                int n = wn * 64 + ni * 8 + grp;
                uint32_t bhr[2], blr[2];
                bhr[0] = __float_as_uint(Bh[n * PJ_PITCH + k0 + tig]);
                bhr[1] = __float_as_uint(Bh[n * PJ_PITCH + k0 + tig + 4]);
                blr[0] = __float_as_uint(Bl[n * PJ_PITCH + k0 + tig]);
                blr[1] = __float_as_uint(Bl[n * PJ_PITCH + k0 + tig + 4]);
#pragma unroll
                for (int mi = 0; mi < 2; ++mi) {
                    mma_tf32_16x8x8(acc[mi][ni], ahr[mi], blr);
                    mma_tf32_16x8x8(acc[mi][ni], alr[mi], bhr);
                    mma_tf32_16x8x8(acc[mi][ni], ahr[mi], bhr);
                }
            }
        }
        __syncthreads();
    }

    if (blockIdx.y == 0) {
#pragma unroll
        for (int i = 0; i < 4; ++i) {
            float s = sq[i];
            s += __shfl_down_sync(0xffffffffu, s, 4, 8);
            s += __shfl_down_sync(0xffffffffu, s, 2, 8);
            s += __shfl_down_sync(0xffffffffu, s, 1, 8);
            if ((t & 7) == 0) diag[i0 + i * 32 + lrow] = s * DIAG_COEF;
        }
    }

    float lmax = -3.4e38f;
#pragma unroll
    for (int mi = 0; mi < 2; ++mi) {
        long row = i0 + wm * 32 + mi * 16 + grp;
#pragma unroll
        for (int ni = 0; ni < 8; ++ni) {
            long col = j0 + wn * 64 + ni * 8 + tig * 2;
            float2 v0 = make_float2(acc[mi][ni][0] * NORMALIZER, acc[mi][ni][1] * NORMALIZER);
            float2 v1 = make_float2(acc[mi][ni][2] * NORMALIZER, acc[mi][ni][3] * NORMALIZER);
            *(float2*)(C + row * MM + col)       = v0;
            *(float2*)(C + (row + 8) * MM + col) = v1;
            lmax = fmaxf(lmax, fmaxf(fmaxf(v0.x, v0.y), fmaxf(v1.x, v1.y)));
        }
    }
    if (kmax_enc) {
#pragma unroll
        for (int o = 16; o; o >>= 1) lmax = fmaxf(lmax, __shfl_xor_sync(0xffffffffu, lmax, o));
        if (lane == 0) atomicMax(kmax_enc, enc_f(lmax));
    }
}

// ============ weights[h] = qp[h] @ kp[h]^T via mma.sync fp16 + ldmatrix ========
// 128x128 CTA tile, 8 warps (4x2), warp tile 32x64, 3-stage cp.async pipeline.
// __launch_bounds__(256,2) caps regs so 2 CTAs/SM -> 4 warps/SMSP latency cover.
#define WF_PITCH  40
#define WF_ABUF   (128 * WF_PITCH)       // halves per A stage
#define WF_BBUF   (128 * WF_PITCH)       // halves per B stage
#define WF_STAGE  (WF_ABUF + WF_BBUF)
#define WF_SMEM   (3 * WF_STAGE * 2)     // 61440 B per CTA

__global__ __launch_bounds__(256, 2) void weights_mma(
    const __half* __restrict__ qp, const __half* __restrict__ kp, float* __restrict__ outw)
{
    extern __shared__ __half smh[];

    const int t    = threadIdx.x;
    const int lane = t & 31;
    const int w    = t >> 5;
    const int wm   = w & 3;             // 4 warps in M (32 rows each)
    const int wn   = w >> 2;            // 2 warps in N (64 cols each)
    const int grp  = lane >> 2;
    const int tig  = lane & 3;

    const int lr8     = lane & 7;
    const int lg      = lane >> 3;
    const int rowOff  = (lg & 1) * 8 + lr8;
    const int colOff  = (lg >> 1) * 8;

    const int h   = blockIdx.z;
    const long i0 = (long)blockIdx.y * 128;
    const long j0 = (long)blockIdx.x * 128;

    const __half* Ag = qp + ((long)h * NN + i0) * MM;
    const __half* Bg = kp + ((long)h * NN + j0) * MM;

    const int arow = t >> 2;            // 0..63
    const int ac8  = (t & 3) * 8;

    float acc[2][8][4];
#pragma unroll
    for (int mi = 0; mi < 2; ++mi)
#pragma unroll
        for (int ni = 0; ni < 8; ++ni)
#pragma unroll
            for (int r = 0; r < 4; ++r) acc[mi][ni][r] = 0.f;

    uint32_t base_u = smem_u32(smh);

    // prologue: issue chunks 0,1 into stages 0,1
#pragma unroll
    for (int pc = 0; pc < 2; ++pc) {
        const uint32_t su = base_u + pc * WF_STAGE * 2;
        const int kof = pc * 32;
#pragma unroll
        for (int i = 0; i < 2; ++i) {
            int row = i * 64 + arow;
            cp_async16(su + (row * WF_PITCH + ac8) * 2, Ag + (long)row * MM + kof + ac8);
            cp_async16(su + (WF_ABUF + row * WF_PITCH + ac8) * 2, Bg + (long)row * MM + kof + ac8);
        }
        cp_commit();
    }

    int stage = 0, nstage = 2;
#pragma unroll 1
    for (int c = 0; c < 8; ++c) {
        cp_wait<1>();
        __syncthreads();
        if (c < 6) {
            const int kof = (c + 2) * 32;
            const uint32_t su = base_u + nstage * WF_STAGE * 2;
#pragma unroll
            for (int i = 0; i < 2; ++i) {
                int row = i * 64 + arow;
                cp_async16(su + (row * WF_PITCH + ac8) * 2, Ag + (long)row * MM + kof + ac8);
                cp_async16(su + (WF_ABUF + row * WF_PITCH + ac8) * 2,
                           Bg + (long)row * MM + kof + ac8);
            }
            cp_commit();
            nstage = (nstage + 1) % 3;
        } else {
            cp_commit();   // keep group counting uniform for wait<1>
        }

        const uint32_t AbU = base_u + stage * WF_STAGE * 2;
        const uint32_t BbU = AbU + WF_ABUF * 2;
        stage = (stage + 1) % 3;

#pragma unroll
        for (int ks = 0; ks < 2; ++ks) {
            const int k0 = ks * 16;
            uint32_t a[2][4];
#pragma unroll
            for (int mi = 0; mi < 2; ++mi) {
                int m = wm * 32 + mi * 16 + rowOff;
                uint32_t addr = AbU + (uint32_t)(m * WF_PITCH + k0 + colOff) * 2;
                LDSM_X4(a[mi][0], a[mi][1], a[mi][2], a[mi][3], addr);
            }
            uint32_t b[8][2];
#pragma unroll
            for (int p = 0; p < 4; ++p) {
                int n = wn * 64 + p * 16 + rowOff;
                uint32_t addr = BbU + (uint32_t)(n * WF_PITCH + k0 + colOff) * 2;
                uint32_t r0, r1, r2, r3;
                LDSM_X4(r0, r1, r2, r3, addr);
                b[2 * p][0]     = r0;
                b[2 * p + 1][0] = r1;
                b[2 * p][1]     = r2;
                b[2 * p + 1][1] = r3;
            }
#pragma unroll
            for (int mi = 0; mi < 2; ++mi)
#pragma unroll
                for (int ni = 0; ni < 8; ++ni)
                    mma_f16_16x8x16(acc[mi][ni], a[mi], b[ni]);
        }
    }

    float* Cp = outw + (long)h * NN * NN;
#pragma unroll
    for (int mi = 0; mi < 2; ++mi) {
        long row = i0 + wm * 32 + mi * 16 + grp;
#pragma unroll
        for (int ni = 0; ni < 8; ++ni) {
            long col = j0 + wn * 64 + ni * 8 + tig * 2;
            *(float2*)(Cp + row * NN + col) =
                make_float2(acc[mi][ni][0] * HUNSCALE, acc[mi][ni][1] * HUNSCALE);
            *(float2*)(Cp + (row + 8) * NN + col) =
                make_float2(acc[mi][ni][2] * HUNSCALE, acc[mi][ni][3] * HUNSCALE);
        }
    }
}

// ======= ctx[h][m][e] = sum_n kp[h][n][m] * v[h][n][e]  via mma tf32 ==========
#define CTX_KSPLIT 16
#define CTX_KC     32
#define KS_PITCH   260
#define VS_PITCH   68
#define KS_BUF     (CTX_KC * KS_PITCH)
#define VS_BUF     (CTX_KC * VS_PITCH)
#define CTX_SMEM   ((2 * KS_BUF + 2 * VS_BUF) * 4)

__global__ __launch_bounds__(256) void ctx_mma(
    const float* __restrict__ kp, const float* __restrict__ v, float* __restrict__ ctx)
{
    extern __shared__ float sm[];
    float* Ks = sm;
    float* Vs = sm + 2 * KS_BUF;

    const int t    = threadIdx.x;
    const int lane = t & 31;
    const int w    = t >> 5;
    const int wm   = w & 3;
    const int we   = w >> 2;
    const int grp  = lane >> 2;
    const int tig  = lane & 3;

    const int h     = blockIdx.z;
    const int nbase = blockIdx.y * (NN / CTX_KSPLIT);

    const float* Kg = kp + ((long)h * NN + nbase) * MM;
    const float* Vg = v  + ((long)h * NN + nbase) * DD;

    const int krow = t >> 3;
    const int c4   = t & 7;

    float acc[4][4][4];
#pragma unroll
    for (int mi = 0; mi < 4; ++mi)
#pragma unroll
        for (int ni = 0; ni < 4; ++ni)
#pragma unroll
            for (int r = 0; r < 4; ++r) acc[mi][ni][r] = 0.f;

    uint32_t Ks_u = smem_u32(Ks);
    uint32_t Vs_u = smem_u32(Vs);

#pragma unroll
    for (int i = 0; i < 8; ++i)
        cp_async16(Ks_u + (krow * KS_PITCH + (c4 + i * 8) * 4) * 4,
                   Kg + (long)krow * MM + (c4 + i * 8) * 4);
#pragma unroll
    for (int i = 0; i < 2; ++i)
        cp_async16(Vs_u + (krow * VS_PITCH + (c4 + i * 8) * 4) * 4,
                   Vg + (long)krow * DD + (c4 + i * 8) * 4);
    cp_commit();

#pragma unroll 1
    for (int c = 0; c < 8; ++c) {
        cp_wait<0>();
        __syncthreads();
        if (c < 7) {
            const int nof = (c + 1) * CTX_KC;
            const uint32_t kb = ((c + 1) & 1) * KS_BUF * 4;
            const uint32_t vb = ((c + 1) & 1) * VS_BUF * 4;
#pragma unroll
            for (int i = 0; i < 8; ++i)
                cp_async16(Ks_u + kb + (krow * KS_PITCH + (c4 + i * 8) * 4) * 4,
                           Kg + (long)(nof + krow) * MM + (c4 + i * 8) * 4);
#pragma unroll
            for (int i = 0; i < 2; ++i)
                cp_async16(Vs_u + vb + (krow * VS_PITCH + (c4 + i * 8) * 4) * 4,
                           Vg + (long)(nof + krow) * DD + (c4 + i * 8) * 4);
            cp_commit();
        }

        const float* Kb = Ks + (c & 1) * KS_BUF;
        const float* Vb = Vs + (c & 1) * VS_BUF;

#pragma unroll
        for (int ks = 0; ks < 4; ++ks) {
            const int k0 = ks * 8;
            uint32_t a[4][4];
#pragma unroll
            for (int mi = 0; mi < 4; ++mi) {
                int m = wm * 64 + mi * 16 + grp;
                a[mi][0] = __float_as_uint(Kb[(k0 + tig) * KS_PITCH + m]);
                a[mi][1] = __float_as_uint(Kb[(k0 + tig) * KS_PITCH + m + 8]);
                a[mi][2] = __float_as_uint(Kb[(k0 + tig + 4) * KS_PITCH + m]);
                a[mi][3] = __float_as_uint(Kb[(k0 + tig + 4) * KS_PITCH + m + 8]);
            }
            uint32_t b[4][2];
#pragma unroll
            for (int ni = 0; ni < 4; ++ni) {
                int e = we * 32 + ni * 8 + grp;
                b[ni][0] = to_tf32_u(Vb[(k0 + tig) * VS_PITCH + e]);
                b[ni][1] = to_tf32_u(Vb[(k0 + tig + 4) * VS_PITCH + e]);
            }
#pragma unroll
            for (int mi = 0; mi < 4; ++mi)
#pragma unroll
                for (int ni = 0; ni < 4; ++ni)
                    mma_tf32_16x8x8(acc[mi][ni], a[mi], b[ni]);
        }
    }

#pragma unroll
    for (int mi = 0; mi < 4; ++mi) {
        int m = wm * 64 + mi * 16 + grp;
#pragma unroll
        for (int ni = 0; ni < 4; ++ni) {
            int e = we * 32 + ni * 8 + tig * 2;
            float* p0 = &ctx[((long)h * MM + m) * DD + e];
            float* p1 = &ctx[((long)h * MM + m + 8) * DD + e];
            atomicAdd(p0,     acc[mi][ni][0]);
            atomicAdd(p0 + 1, acc[mi][ni][1]);
            atomicAdd(p1,     acc[mi][ni][2]);
            atomicAdd(p1 + 1, acc[mi][ni][3]);
        }
    }
}

// ======= out[h][n][e] = dinv[n] * sum_m qp[h][n][m] * ctx[h][m][e]  (mma) =====
#define OQ_PITCH 36
#define OC_PITCH 68
#define OQ_BUF   (128 * OQ_PITCH)
#define OC_BUF   (32 * OC_PITCH)
#define OUT_SMEM ((2 * OQ_BUF + 2 * OC_BUF) * 4)

__global__ __launch_bounds__(256) void out_mma(
    const float* __restrict__ qp, const float* __restrict__ ctx,
    const float* __restrict__ dinv, float* __restrict__ out)
{
    extern __shared__ float sm[];
    float* Qs = sm;
    float* Cs = sm + 2 * OQ_BUF;

    const int t    = threadIdx.x;
    const int lane = t & 31;
    const int w    = t >> 5;
    const int wn   = w & 3;
    const int we   = w >> 2;
    const int grp  = lane >> 2;
    const int tig  = lane & 3;

    const int h  = blockIdx.y;
    const long n0 = (long)blockIdx.x * 128;

    const float* Qg = qp  + ((long)h * NN + n0) * MM;
    const float* Cg = ctx + (long)h * MM * DD;

    const int lrow = t >> 3;
    const int lcol = (t & 7) * 4;
    const int crow = t >> 3;
    const int cc4  = t & 7;

    float acc[2][4][4];
#pragma unroll
    for (int mi = 0; mi < 2; ++mi)
#pragma unroll
        for (int ni = 0; ni < 4; ++ni)
#pragma unroll
            for (int r = 0; r < 4; ++r) acc[mi][ni][r] = 0.f;

    uint32_t Qs_u = smem_u32(Qs);
    uint32_t Cs_u = smem_u32(Cs);

#pragma unroll
    for (int i = 0; i < 4; ++i) {
        int row = i * 32 + lrow;
        cp_async16(Qs_u + (row * OQ_PITCH + lcol) * 4, Qg + (long)row * MM + lcol);
    }
#pragma unroll
    for (int i = 0; i < 2; ++i)
        cp_async16(Cs_u + (crow * OC_PITCH + (cc4 + i * 8) * 4) * 4,
                   Cg + (long)crow * DD + (cc4 + i * 8) * 4);
    cp_commit();

#pragma unroll 1
    for (int c = 0; c < 8; ++c) {
        cp_wait<0>();
        __syncthreads();
        if (c < 7) {
            const int kof = (c + 1) * 32;
            const uint32_t qb = ((c + 1) & 1) * OQ_BUF * 4;
            const uint32_t cb = ((c + 1) & 1) * OC_BUF * 4;
#pragma unroll
            for (int i = 0; i < 4; ++i) {
                int row = i * 32 + lrow;
                cp_async16(Qs_u + qb + (row * OQ_PITCH + lcol) * 4,
                           Qg + (long)row * MM + kof + lcol);
            }
#pragma unroll
            for (int i = 0; i < 2; ++i)
                cp_async16(Cs_u + cb + (crow * OC_PITCH + (cc4 + i * 8) * 4) * 4,
                           Cg + (long)(kof + crow) * DD + (cc4 + i * 8) * 4);
            cp_commit();
        }

        const float* Qb = Qs + (c & 1) * OQ_BUF;
        const float* Cb = Cs + (c & 1) * OC_BUF;

#pragma unroll
        for (int ks = 0; ks < 4; ++ks) {
            const int k0 = ks * 8;
            uint32_t a[2][4];
#pragma unroll
            for (int mi = 0; mi < 2; ++mi) {
                int n = wn * 32 + mi * 16 + grp;
                a[mi][0] = __float_as_uint(Qb[n * OQ_PITCH + k0 + tig]);
                a[mi][1] = __float_as_uint(Qb[(n + 8) * OQ_PITCH + k0 + tig]);
                a[mi][2] = __float_as_uint(Qb[n * OQ_PITCH + k0 + tig + 4]);
                a[mi][3] = __float_as_uint(Qb[(n + 8) * OQ_PITCH + k0 + tig + 4]);
            }
            uint32_t b[4][2];
#pragma unroll
            for (int ni = 0; ni < 4; ++ni) {
                int e = we * 32 + ni * 8 + grp;
                b[ni][0] = to_tf32_u(Cb[(k0 + tig) * OC_PITCH + e]);
                b[ni][1] = to_tf32_u(Cb[(k0 + tig + 4) * OC_PITCH + e]);
            }
#pragma unroll
            for (int mi = 0; mi < 2; ++mi)
#pragma unroll
                for (int ni = 0; ni < 4; ++ni)
                    mma_tf32_16x8x8(acc[mi][ni], a[mi], b[ni]);
        }
    }

#pragma unroll
    for (int mi = 0; mi < 2; ++mi) {
        long n = n0 + wn * 32 + mi * 16 + grp;
        float dv0 = dinv[(long)h * NN + n];
        float dv1 = dinv[(long)h * NN + n + 8];
#pragma unroll
        for (int ni = 0; ni < 4; ++ni) {
            int e = we * 32 + ni * 8 + tig * 2;
            *(float2*)(out + ((long)h * NN + n) * DD + e) =
                make_float2(acc[mi][ni][0] * dv0, acc[mi][ni][1] * dv0);
            *(float2*)(out + ((long)h * NN + n + 8) * DD + e) =
                make_float2(acc[mi][ni][2] * dv1, acc[mi][ni][3] * dv1);
        }
    }
}

// ---------------- exp / dinv ----------------------------------------------------
__global__ void expq_kernel(float* __restrict__ dash, const float* __restrict__ diag,
                            __half* __restrict__ dash_h) {
    int row  = blockIdx.x * 8 + (threadIdx.x >> 5);
    int lane = threadIdx.x & 31;
    long base = (long)row * MM;
    float4 a = *(float4*)(dash + base + lane * 4);
    float4 b = *(float4*)(dash + base + 128 + lane * 4);
    float m = fmaxf(fmaxf(fmaxf(a.x, a.y), fmaxf(a.z, a.w)),
                    fmaxf(fmaxf(b.x, b.y), fmaxf(b.z, b.w)));
#pragma unroll
    for (int o = 16; o; o >>= 1) m = fmaxf(m, __shfl_xor_sync(0xffffffffu, m, o));
    float s = diag[row] + m;
    float4 ea, eb;
    ea.x = RATIO * (__expf(a.x - s) + FEPS);
    ea.y = RATIO * (__expf(a.y - s) + FEPS);
    ea.z = RATIO * (__expf(a.z - s) + FEPS);
    ea.w = RATIO * (__expf(a.w - s) + FEPS);
    eb.x = RATIO * (__expf(b.x - s) + FEPS);
    eb.y = RATIO * (__expf(b.y - s) + FEPS);
    eb.z = RATIO * (__expf(b.z - s) + FEPS);
    eb.w = RATIO * (__expf(b.w - s) + FEPS);
    float4 ta = make_float4(to_tf32(ea.x), to_tf32(ea.y), to_tf32(ea.z), to_tf32(ea.w));
    float4 tb = make_float4(to_tf32(eb.x), to_tf32(eb.y), to_tf32(eb.z), to_tf32(eb.w));
    *(float4*)(dash + base + lane * 4)       = ta;
    *(float4*)(dash + base + 128 + lane * 4) = tb;
    __half2* hp0 = (__half2*)(dash_h + base + lane * 4);
    __half2* hp1 = (__half2*)(dash_h + base + 128 + lane * 4);
    hp0[0] = __floats2half2_rn(ea.x * HSCALE, ea.y * HSCALE);
    hp0[1] = __floats2half2_rn(ea.z * HSCALE, ea.w * HSCALE);
    hp1[0] = __floats2half2_rn(eb.x * HSCALE, eb.y * HSCALE);
    hp1[1] = __floats2half2_rn(eb.z * HSCALE, eb.w * HSCALE);
}

__global__ void expk_kernel(float* __restrict__ dash, const float* __restrict__ diag,
                            const unsigned* __restrict__ kmax_enc, float* __restrict__ ksum,
                            __half* __restrict__ dash_h) {
    int t    = threadIdx.x;
    int row0 = blockIdx.x * 64;
    int h    = row0 >> 12;
    float stab  = dec_f(kmax_enc[0]);
    float local = 0.f;
    for (int r = 0; r < 64; ++r) {
        long idx = (long)(row0 + r) * MM + t;
        float vfull = RATIO * (__expf(dash[idx] - diag[row0 + r] - stab) + FEPS);
        float vv = to_tf32(vfull);
        dash[idx]   = vv;
        dash_h[idx] = __float2half_rn(vfull * HSCALE);
        local += vv;
    }
    atomicAdd(&ksum[h * MM + t], local);
}

__global__ void dinv_kernel(const float* __restrict__ qp, const float* __restrict__ ksum,
                            float* __restrict__ dinv) {
    int row  = blockIdx.x * 8 + (threadIdx.x >> 5);
    int lane = threadIdx.x & 31;
    int h    = row >> 12;
    const float* qr = qp + (long)row * MM;
    const float* ks = ksum + h * MM;
    float s = 0.f;
#pragma unroll
    for (int i = 0; i < 8; ++i) {
        int m = lane + i * 32;
        s += qr[m] * ks[m];
    }
#pragma unroll
    for (int o = 16; o; o >>= 1) s += __shfl_xor_sync(0xffffffffu, s, o);
    if (!lane) dinv[row] = 1.f / s;
}

// -------------------------------------------------------------------------------
extern "C" void kernel_launch(void* const* d_in, const int* in_sizes, int n_in,
                              void* d_out, int out_size)
{
    const float* q    = (const float*)d_in[0];
    const float* k    = (const float*)d_in[1];
    const float* v    = (const float*)d_in[2];
    const float* proj = (const float*)d_in[3];

    float* out_align = (float*)d_out;                       // [H,N,D]
    float* out_w     = out_align + (long)HH * NN * DD;      // [H,N,N]

    float *qp, *kp, *qdiag, *kdiag, *ksum, *dinv, *ctx;
    __half *qph, *kph;
    unsigned *kmaxe;
    cudaGetSymbolAddress((void**)&qp,    g_qp);
    cudaGetSymbolAddress((void**)&kp,    g_kp);
    cudaGetSymbolAddress((void**)&qph,   g_qph);
    cudaGetSymbolAddress((void**)&kph,   g_kph);
    cudaGetSymbolAddress((void**)&qdiag, g_qdiag);
    cudaGetSymbolAddress((void**)&kdiag, g_kdiag);
    cudaGetSymbolAddress((void**)&ksum,  g_ksum);
    cudaGetSymbolAddress((void**)&dinv,  g_dinv);
    cudaGetSymbolAddress((void**)&ctx,   g_ctx);
    cudaGetSymbolAddress((void**)&kmaxe, g_kmax_enc);

    static cudaStream_t s2 = nullptr;
    static cudaEvent_t  ev1, ev2, ev3, ev4;
    static bool attr_done = false;
    if (!attr_done) {
        cudaFuncSetAttribute(weights_mma, cudaFuncAttributeMaxDynamicSharedMemorySize, WF_SMEM);
        cudaFuncSetAttribute(proj_mma,    cudaFuncAttributeMaxDynamicSharedMemorySize, PJ_SMEM);
        cudaFuncSetAttribute(ctx_mma,     cudaFuncAttributeMaxDynamicSharedMemorySize, CTX_SMEM);
        cudaFuncSetAttribute(out_mma,     cudaFuncAttributeMaxDynamicSharedMemorySize, OUT_SMEM);
        cudaStreamCreateWithFlags(&s2, cudaStreamNonBlocking);
        cudaEventCreateWithFlags(&ev1, cudaEventDisableTiming);
        cudaEventCreateWithFlags(&ev2, cudaEventDisableTiming);
        cudaEventCreateWithFlags(&ev3, cudaEventDisableTiming);
        cudaEventCreateWithFlags(&ev4, cudaEventDisableTiming);
        attr_done = true;
    }

    zero_kernel<<<HH * MM * DD / 256, 256>>>();

    // fork: q-chain on s2, k-chain on main, running concurrently
    cudaEventRecord(ev1, 0);
    cudaStreamWaitEvent(s2, ev1, 0);

    proj_mma<<<dim3(ROWS / 128, MM / 128), 256, PJ_SMEM, s2>>>(q, proj, qp, qdiag, nullptr);
    expq_kernel<<<ROWS / 8, 256, 0, s2>>>(qp, qdiag, qph);
    cudaEventRecord(ev3, s2);

    proj_mma<<<dim3(ROWS / 128, MM / 128), 256, PJ_SMEM>>>(k, proj, kp, kdiag, kmaxe);
    expk_kernel<<<ROWS / 64, 256>>>(kp, kdiag, kmaxe, ksum, kph);
    cudaEventRecord(ev4, 0);

    // join: weights needs qph (s2) + kph (main)
    cudaStreamWaitEvent(0, ev3, 0);
    weights_mma<<<dim3(NN / 128, NN / 128, HH), 256, WF_SMEM>>>(qph, kph, out_w);

    // side chain on s2: needs both chains (ev4 covers k-chain; s2 already ran q-chain)
    cudaStreamWaitEvent(s2, ev4, 0);
    ctx_mma<<<dim3(1, CTX_KSPLIT, HH), 256, CTX_SMEM, s2>>>(kp, v, ctx);
    dinv_kernel<<<ROWS / 8, 256, 0, s2>>>(qp, ksum, dinv);
    out_mma<<<dim3(NN / 128, HH), 256, OUT_SMEM, s2>>>(qp, ctx, dinv, out_align);

    cudaEventRecord(ev2, s2);
    cudaStreamWaitEvent(0, ev2, 0);
}

// round 14
// speedup vs baseline: 1.2047x; 1.0274x over previous
#include <cuda_runtime.h>
#include <cuda_fp16.h>
#include <math.h>
#include <stdint.h>

#define HH 16
#define NN 4096
#define DD 64
#define MM 256
#define ROWS (HH * NN)          // 65536

#define NORMALIZER 0.35355339059327373f  // 64^-0.25
#define DIAG_COEF  0.0625f               // 0.5 * 64^-0.5
#define RATIO      0.0625f               // 256^-0.5
#define FEPS       1e-4f
#define HSCALE     2048.0f               // lift fp16 features out of subnormals
#define HUNSCALE   (1.0f / 4194304.0f)   // 2^-22

// ---------------- scratch (device globals; no allocation allowed) -------------
__device__ float    g_qp[(size_t)ROWS * MM];
__device__ float    g_kp[(size_t)ROWS * MM];
__device__ __half   g_qph[(size_t)ROWS * MM];
__device__ __half   g_kph[(size_t)ROWS * MM];
__device__ float    g_qdiag[ROWS];
__device__ float    g_kdiag[ROWS];
__device__ float    g_ksum[HH * MM];
__device__ float    g_dinv[ROWS];
__device__ float    g_ctx[HH * MM * DD];
__device__ unsigned g_kmax_enc[1];

__device__ __forceinline__ float to_tf32(float x) {
    uint32_t r;
    asm("cvt.rna.tf32.f32 %0, %1;" : "=r"(r) : "f"(x));
    return __uint_as_float(r);
}
__device__ __forceinline__ uint32_t to_tf32_u(float x) {
    uint32_t r;
    asm("cvt.rna.tf32.f32 %0, %1;" : "=r"(r) : "f"(x));
    return r;
}
__device__ __forceinline__ uint32_t smem_u32(const void* p) {
    uint32_t a;
    asm("{ .reg .u64 t; cvta.to.shared.u64 t, %1; cvt.u32.u64 %0, t; }" : "=r"(a) : "l"(p));
    return a;
}
__device__ __forceinline__ void cp_async16(uint32_t dst, const void* src) {
    asm volatile("cp.async.ca.shared.global [%0], [%1], 16;" :: "r"(dst), "l"(src) : "memory");
}
__device__ __forceinline__ void cp_commit() {
    asm volatile("cp.async.commit_group;" ::: "memory");
}
template <int N> __device__ __forceinline__ void cp_wait() {
    asm volatile("cp.async.wait_group %0;" :: "n"(N) : "memory");
}
__device__ __forceinline__ void mma_tf32_16x8x8(float* d, const uint32_t* a, const uint32_t* b) {
    asm volatile(
        "mma.sync.aligned.m16n8k8.row.col.f32.tf32.tf32.f32 "
        "{%0,%1,%2,%3}, {%4,%5,%6,%7}, {%8,%9}, {%0,%1,%2,%3};"
        : "+f"(d[0]), "+f"(d[1]), "+f"(d[2]), "+f"(d[3])
        : "r"(a[0]), "r"(a[1]), "r"(a[2]), "r"(a[3]), "r"(b[0]), "r"(b[1]));
}
__device__ __forceinline__ void mma_f16_16x8x16(float* d, const uint32_t* a, const uint32_t* b) {
    asm volatile(
        "mma.sync.aligned.m16n8k16.row.col.f32.f16.f16.f32 "
        "{%0,%1,%2,%3}, {%4,%5,%6,%7}, {%8,%9}, {%0,%1,%2,%3};"
        : "+f"(d[0]), "+f"(d[1]), "+f"(d[2]), "+f"(d[3])
        : "r"(a[0]), "r"(a[1]), "r"(a[2]), "r"(a[3]), "r"(b[0]), "r"(b[1]));
}
#define LDSM_X4(r0, r1, r2, r3, addr) \
    asm volatile("ldmatrix.sync.aligned.m8n8.x4.shared.b16 {%0,%1,%2,%3}, [%4];" \
                 : "=r"(r0), "=r"(r1), "=r"(r2), "=r"(r3) : "r"(addr))

// monotonic float<->uint encoding for order-invariant atomic max (init = 0)
__device__ __forceinline__ unsigned enc_f(float f) {
    unsigned u = __float_as_uint(f);
    return (u & 0x80000000u) ? ~u : (u | 0x80000000u);
}
__device__ __forceinline__ float dec_f(unsigned u) {
    return (u & 0x80000000u) ? __uint_as_float(u ^ 0x80000000u) : __uint_as_float(~u);
}

// ---------------- zero accumulated scratch -------------------------------------
__global__ void zero_kernel() {
    int i = blockIdx.x * 256 + threadIdx.x;
    if (i < HH * MM) g_ksum[i] = 0.f;
    if (i == 0) g_kmax_enc[0] = 0u;
    g_ctx[i] = 0.f;
}

// ========== projections via 3xTF32 split: dash = alpha * X @ proj^T ===========
// 128x64 tile (grid.y=4), warp tile 32x32, 2 CTAs/SM. Fused diag (y==0) + kmax.
#define PJ_PITCH 36
#define PJ_ATILE (128 * PJ_PITCH)
#define PJ_BTILE (64 * PJ_PITCH)
#define PJ_SMEM  ((2 * PJ_ATILE + 2 * PJ_BTILE) * 4)   // 55296 B

__global__ __launch_bounds__(256, 2) void proj_mma(
    const float* __restrict__ X, const float* __restrict__ P, float* __restrict__ C,
    float* __restrict__ diag, unsigned* kmax_enc)
{
    extern __shared__ float sm[];
    float* Ah = sm;
    float* Al = sm + PJ_ATILE;
    float* Bh = sm + 2 * PJ_ATILE;
    float* Bl = sm + 2 * PJ_ATILE + PJ_BTILE;

    const int t    = threadIdx.x;
    const int lane = t & 31;
    const int w    = t >> 5;
    const int wm   = w & 3;            // 4 warps in M (32 rows each)
    const int wn   = w >> 2;           // 2 warps in N (32 cols each)
    const int grp  = lane >> 2;
    const int tig  = lane & 3;

    const long i0 = (long)blockIdx.x * 128;
    const int  j0 = blockIdx.y * 64;

    const int lrow = t >> 3;           // 0..31
    const int lcol = (t & 7) * 4;      // 0..28

    float acc[2][4][4];
#pragma unroll
    for (int mi = 0; mi < 2; ++mi)
#pragma unroll
        for (int ni = 0; ni < 4; ++ni)
#pragma unroll
            for (int r = 0; r < 4; ++r) acc[mi][ni][r] = 0.f;

    float sq[4] = {0.f, 0.f, 0.f, 0.f};   // fused diag partial sums

#pragma unroll
    for (int c = 0; c < 2; ++c) {
        const int kof = c * 32;
        // A: 128 rows x 32 k
#pragma unroll
        for (int i = 0; i < 4; ++i) {
            int row = i * 32 + lrow;
            float4 va = *(const float4*)(X + (i0 + row) * DD + kof + lcol);
            sq[i] += va.x * va.x + va.y * va.y + va.z * va.z + va.w * va.w;
            float4 ah, al;
            ah.x = to_tf32(va.x); al.x = to_tf32(va.x - ah.x);
            ah.y = to_tf32(va.y); al.y = to_tf32(va.y - ah.y);
            ah.z = to_tf32(va.z); al.z = to_tf32(va.z - ah.z);
            ah.w = to_tf32(va.w); al.w = to_tf32(va.w - ah.w);
            *(float4*)&Ah[row * PJ_PITCH + lcol] = ah;
            *(float4*)&Al[row * PJ_PITCH + lcol] = al;
        }
        // B: 64 rows x 32 k
#pragma unroll
        for (int i = 0; i < 2; ++i) {
            int row = i * 32 + lrow;
            float4 vb = *(const float4*)(P + (long)(j0 + row) * DD + kof + lcol);
            float4 bh, bl;
            bh.x = to_tf32(vb.x); bl.x = to_tf32(vb.x - bh.x);
            bh.y = to_tf32(vb.y); bl.y = to_tf32(vb.y - bh.y);
            bh.z = to_tf32(vb.z); bl.z = to_tf32(vb.z - bh.z);
            bh.w = to_tf32(vb.w); bl.w = to_tf32(vb.w - bh.w);
            *(float4*)&Bh[row * PJ_PITCH + lcol] = bh;
            *(float4*)&Bl[row * PJ_PITCH + lcol] = bl;
        }
        __syncthreads();

#pragma unroll
        for (int ks = 0; ks < 4; ++ks) {
            const int k0 = ks * 8;
            uint32_t ahr[2][4], alr[2][4];
#pragma unroll
            for (int mi = 0; mi < 2; ++mi) {
                int m = wm * 32 + mi * 16 + grp;
                ahr[mi][0] = __float_as_uint(Ah[m * PJ_PITCH + k0 + tig]);
                ahr[mi][1] = __float_as_uint(Ah[(m + 8) * PJ_PITCH + k0 + tig]);
                ahr[mi][2] = __float_as_uint(Ah[m * PJ_PITCH + k0 + tig + 4]);
                ahr[mi][3] = __float_as_uint(Ah[(m + 8) * PJ_PITCH + k0 + tig + 4]);
                alr[mi][0] = __float_as_uint(Al[m * PJ_PITCH + k0 + tig]);
                alr[mi][1] = __float_as_uint(Al[(m + 8) * PJ_PITCH + k0 + tig]);
                alr[mi][2] = __float_as_uint(Al[m * PJ_PITCH + k0 + tig + 4]);
                alr[mi][3] = __float_as_uint(Al[(m + 8) * PJ_PITCH + k0 + tig + 4]);
            }
#pragma unroll
            for (int ni = 0; ni < 4; ++ni) {
                int n = wn * 32 + ni * 8 + grp;
                uint32_t bhr[2], blr[2];
                bhr[0] = __float_as_uint(Bh[n * PJ_PITCH + k0 + tig]);
                bhr[1] = __float_as_uint(Bh[n * PJ_PITCH + k0 + tig + 4]);
                blr[0] = __float_as_uint(Bl[n * PJ_PITCH + k0 + tig]);
                blr[1] = __float_as_uint(Bl[n * PJ_PITCH + k0 + tig + 4]);
#pragma unroll
                for (int mi = 0; mi < 2; ++mi) {
                    mma_tf32_16x8x8(acc[mi][ni], ahr[mi], blr);
                    mma_tf32_16x8x8(acc[mi][ni], alr[mi], bhr);
                    mma_tf32_16x8x8(acc[mi][ni], ahr[mi], bhr);
                }
            }
        }
        __syncthreads();
    }

    if (blockIdx.y == 0) {
#pragma unroll
        for (int i = 0; i < 4; ++i) {
            float s = sq[i];
            s += __shfl_down_sync(0xffffffffu, s, 4, 8);
            s += __shfl_down_sync(0xffffffffu, s, 2, 8);
            s += __shfl_down_sync(0xffffffffu, s, 1, 8);
            if ((t & 7) == 0) diag[i0 + i * 32 + lrow] = s * DIAG_COEF;
        }
    }

    float lmax = -3.4e38f;
#pragma unroll
    for (int mi = 0; mi < 2; ++mi) {
        long row = i0 + wm * 32 + mi * 16 + grp;
#pragma unroll
        for (int ni = 0; ni < 4; ++ni) {
            long col = j0 + wn * 32 + ni * 8 + tig * 2;
            float2 v0 = make_float2(acc[mi][ni][0] * NORMALIZER, acc[mi][ni][1] * NORMALIZER);
            float2 v1 = make_float2(acc[mi][ni][2] * NORMALIZER, acc[mi][ni][3] * NORMALIZER);
            *(float2*)(C + row * MM + col)       = v0;
            *(float2*)(C + (row + 8) * MM + col) = v1;
            lmax = fmaxf(lmax, fmaxf(fmaxf(v0.x, v0.y), fmaxf(v1.x, v1.y)));
        }
    }
    if (kmax_enc) {
#pragma unroll
        for (int o = 16; o; o >>= 1) lmax = fmaxf(lmax, __shfl_xor_sync(0xffffffffu, lmax, o));
        if (lane == 0) atomicMax(kmax_enc, enc_f(lmax));
    }
}

// ============ weights[h] = qp[h] @ kp[h]^T via mma.sync fp16 + ldmatrix ========
// 128x128 CTA tile, warp tile 32x64, 3-stage cp.async pipeline, 2 CTAs/SM.
#define WF_PITCH  40
#define WF_ABUF   (128 * WF_PITCH)
#define WF_BBUF   (128 * WF_PITCH)
#define WF_STAGE  (WF_ABUF + WF_BBUF)
#define WF_SMEM   (3 * WF_STAGE * 2)     // 61440 B per CTA

__global__ __launch_bounds__(256, 2) void weights_mma(
    const __half* __restrict__ qp, const __half* __restrict__ kp, float* __restrict__ outw)
{
    extern __shared__ __half smh[];

    const int t    = threadIdx.x;
    const int lane = t & 31;
    const int w    = t >> 5;
    const int wm   = w & 3;
    const int wn   = w >> 2;
    const int grp  = lane >> 2;
    const int tig  = lane & 3;

    const int lr8     = lane & 7;
    const int lg      = lane >> 3;
    const int rowOff  = (lg & 1) * 8 + lr8;
    const int colOff  = (lg >> 1) * 8;

    const int h   = blockIdx.z;
    const long i0 = (long)blockIdx.y * 128;
    const long j0 = (long)blockIdx.x * 128;

    const __half* Ag = qp + ((long)h * NN + i0) * MM;
    const __half* Bg = kp + ((long)h * NN + j0) * MM;

    const int arow = t >> 2;
    const int ac8  = (t & 3) * 8;

    float acc[2][8][4];
#pragma unroll
    for (int mi = 0; mi < 2; ++mi)
#pragma unroll
        for (int ni = 0; ni < 8; ++ni)
#pragma unroll
            for (int r = 0; r < 4; ++r) acc[mi][ni][r] = 0.f;

    uint32_t base_u = smem_u32(smh);

#pragma unroll
    for (int pc = 0; pc < 2; ++pc) {
        const uint32_t su = base_u + pc * WF_STAGE * 2;
        const int kof = pc * 32;
#pragma unroll
        for (int i = 0; i < 2; ++i) {
            int row = i * 64 + arow;
            cp_async16(su + (row * WF_PITCH + ac8) * 2, Ag + (long)row * MM + kof + ac8);
            cp_async16(su + (WF_ABUF + row * WF_PITCH + ac8) * 2, Bg + (long)row * MM + kof + ac8);
        }
        cp_commit();
    }

    int stage = 0, nstage = 2;
#pragma unroll 1
    for (int c = 0; c < 8; ++c) {
        cp_wait<1>();
        __syncthreads();
        if (c < 6) {
            const int kof = (c + 2) * 32;
            const uint32_t su = base_u + nstage * WF_STAGE * 2;
#pragma unroll
            for (int i = 0; i < 2; ++i) {
                int row = i * 64 + arow;
                cp_async16(su + (row * WF_PITCH + ac8) * 2, Ag + (long)row * MM + kof + ac8);
                cp_async16(su + (WF_ABUF + row * WF_PITCH + ac8) * 2,
                           Bg + (long)row * MM + kof + ac8);
            }
            cp_commit();
            nstage = (nstage + 1) % 3;
        } else {
            cp_commit();
        }

        const uint32_t AbU = base_u + stage * WF_STAGE * 2;
        const uint32_t BbU = AbU + WF_ABUF * 2;
        stage = (stage + 1) % 3;

#pragma unroll
        for (int ks = 0; ks < 2; ++ks) {
            const int k0 = ks * 16;
            uint32_t a[2][4];
#pragma unroll
            for (int mi = 0; mi < 2; ++mi) {
                int m = wm * 32 + mi * 16 + rowOff;
                uint32_t addr = AbU + (uint32_t)(m * WF_PITCH + k0 + colOff) * 2;
                LDSM_X4(a[mi][0], a[mi][1], a[mi][2], a[mi][3], addr);
            }
            uint32_t b[8][2];
#pragma unroll
            for (int p = 0; p < 4; ++p) {
                int n = wn * 64 + p * 16 + rowOff;
                uint32_t addr = BbU + (uint32_t)(n * WF_PITCH + k0 + colOff) * 2;
                uint32_t r0, r1, r2, r3;
                LDSM_X4(r0, r1, r2, r3, addr);
                b[2 * p][0]     = r0;
                b[2 * p + 1][0] = r1;
                b[2 * p][1]     = r2;
                b[2 * p + 1][1] = r3;
            }
#pragma unroll
            for (int mi = 0; mi < 2; ++mi)
#pragma unroll
                for (int ni = 0; ni < 8; ++ni)
                    mma_f16_16x8x16(acc[mi][ni], a[mi], b[ni]);
        }
    }

    float* Cp = outw + (long)h * NN * NN;
#pragma unroll
    for (int mi = 0; mi < 2; ++mi) {
        long row = i0 + wm * 32 + mi * 16 + grp;
#pragma unroll
        for (int ni = 0; ni < 8; ++ni) {
            long col = j0 + wn * 64 + ni * 8 + tig * 2;
            *(float2*)(Cp + row * NN + col) =
                make_float2(acc[mi][ni][0] * HUNSCALE, acc[mi][ni][1] * HUNSCALE);
            *(float2*)(Cp + (row + 8) * NN + col) =
                make_float2(acc[mi][ni][2] * HUNSCALE, acc[mi][ni][3] * HUNSCALE);
        }
    }
}

// ======= ctx[h][m][e] = sum_n kp[h][n][m] * v[h][n][e]  via mma tf32 ==========
#define CTX_KSPLIT 16
#define CTX_KC     32
#define KS_PITCH   260
#define VS_PITCH   68
#define KS_BUF     (CTX_KC * KS_PITCH)
#define VS_BUF     (CTX_KC * VS_PITCH)
#define CTX_SMEM   ((2 * KS_BUF + 2 * VS_BUF) * 4)

__global__ __launch_bounds__(256) void ctx_mma(
    const float* __restrict__ kp, const float* __restrict__ v, float* __restrict__ ctx)
{
    extern __shared__ float sm[];
    float* Ks = sm;
    float* Vs = sm + 2 * KS_BUF;

    const int t    = threadIdx.x;
    const int lane = t & 31;
    const int w    = t >> 5;
    const int wm   = w & 3;
    const int we   = w >> 2;
    const int grp  = lane >> 2;
    const int tig  = lane & 3;

    const int h     = blockIdx.z;
    const int nbase = blockIdx.y * (NN / CTX_KSPLIT);

    const float* Kg = kp + ((long)h * NN + nbase) * MM;
    const float* Vg = v  + ((long)h * NN + nbase) * DD;

    const int krow = t >> 3;
    const int c4   = t & 7;

    float acc[4][4][4];
#pragma unroll
    for (int mi = 0; mi < 4; ++mi)
#pragma unroll
        for (int ni = 0; ni < 4; ++ni)
#pragma unroll
            for (int r = 0; r < 4; ++r) acc[mi][ni][r] = 0.f;

    uint32_t Ks_u = smem_u32(Ks);
    uint32_t Vs_u = smem_u32(Vs);

#pragma unroll
    for (int i = 0; i < 8; ++i)
        cp_async16(Ks_u + (krow * KS_PITCH + (c4 + i * 8) * 4) * 4,
                   Kg + (long)krow * MM + (c4 + i * 8) * 4);
#pragma unroll
    for (int i = 0; i < 2; ++i)
        cp_async16(Vs_u + (krow * VS_PITCH + (c4 + i * 8) * 4) * 4,
                   Vg + (long)krow * DD + (c4 + i * 8) * 4);
    cp_commit();

#pragma unroll 1
    for (int c = 0; c < 8; ++c) {
        cp_wait<0>();
        __syncthreads();
        if (c < 7) {
            const int nof = (c + 1) * CTX_KC;
            const uint32_t kb = ((c + 1) & 1) * KS_BUF * 4;
            const uint32_t vb = ((c + 1) & 1) * VS_BUF * 4;
#pragma unroll
            for (int i = 0; i < 8; ++i)
                cp_async16(Ks_u + kb + (krow * KS_PITCH + (c4 + i * 8) * 4) * 4,
                           Kg + (long)(nof + krow) * MM + (c4 + i * 8) * 4);
#pragma unroll
            for (int i = 0; i < 2; ++i)
                cp_async16(Vs_u + vb + (krow * VS_PITCH + (c4 + i * 8) * 4) * 4,
                           Vg + (long)(nof + krow) * DD + (c4 + i * 8) * 4);
            cp_commit();
        }

        const float* Kb = Ks + (c & 1) * KS_BUF;
        const float* Vb = Vs + (c & 1) * VS_BUF;

#pragma unroll
        for (int ks = 0; ks < 4; ++ks) {
            const int k0 = ks * 8;
            uint32_t a[4][4];
#pragma unroll
            for (int mi = 0; mi < 4; ++mi) {
                int m = wm * 64 + mi * 16 + grp;
                a[mi][0] = __float_as_uint(Kb[(k0 + tig) * KS_PITCH + m]);
                a[mi][1] = __float_as_uint(Kb[(k0 + tig) * KS_PITCH + m + 8]);
                a[mi][2] = __float_as_uint(Kb[(k0 + tig + 4) * KS_PITCH + m]);
                a[mi][3] = __float_as_uint(Kb[(k0 + tig + 4) * KS_PITCH + m + 8]);
            }
            uint32_t b[4][2];
#pragma unroll
            for (int ni = 0; ni < 4; ++ni) {
                int e = we * 32 + ni * 8 + grp;
                b[ni][0] = to_tf32_u(Vb[(k0 + tig) * VS_PITCH + e]);
                b[ni][1] = to_tf32_u(Vb[(k0 + tig + 4) * VS_PITCH + e]);
            }
#pragma unroll
            for (int mi = 0; mi < 4; ++mi)
#pragma unroll
                for (int ni = 0; ni < 4; ++ni)
                    mma_tf32_16x8x8(acc[mi][ni], a[mi], b[ni]);
        }
    }

#pragma unroll
    for (int mi = 0; mi < 4; ++mi) {
        int m = wm * 64 + mi * 16 + grp;
#pragma unroll
        for (int ni = 0; ni < 4; ++ni) {
            int e = we * 32 + ni * 8 + tig * 2;
            float* p0 = &ctx[((long)h * MM + m) * DD + e];
            float* p1 = &ctx[((long)h * MM + m + 8) * DD + e];
            atomicAdd(p0,     acc[mi][ni][0]);
            atomicAdd(p0 + 1, acc[mi][ni][1]);
            atomicAdd(p1,     acc[mi][ni][2]);
            atomicAdd(p1 + 1, acc[mi][ni][3]);
        }
    }
}

// ======= out[h][n][e] = dinv[n] * sum_m qp[h][n][m] * ctx[h][m][e]  (mma) =====
#define OQ_PITCH 36
#define OC_PITCH 68
#define OQ_BUF   (128 * OQ_PITCH)
#define OC_BUF   (32 * OC_PITCH)
#define OUT_SMEM ((2 * OQ_BUF + 2 * OC_BUF) * 4)

__global__ __launch_bounds__(256) void out_mma(
    const float* __restrict__ qp, const float* __restrict__ ctx,
    const float* __restrict__ dinv, float* __restrict__ out)
{
    extern __shared__ float sm[];
    float* Qs = sm;
    float* Cs = sm + 2 * OQ_BUF;

    const int t    = threadIdx.x;
    const int lane = t & 31;
    const int w    = t >> 5;
    const int wn   = w & 3;
    const int we   = w >> 2;
    const int grp  = lane >> 2;
    const int tig  = lane & 3;

    const int h  = blockIdx.y;
    const long n0 = (long)blockIdx.x * 128;

    const float* Qg = qp  + ((long)h * NN + n0) * MM;
    const float* Cg = ctx + (long)h * MM * DD;

    const int lrow = t >> 3;
    const int lcol = (t & 7) * 4;
    const int crow = t >> 3;
    const int cc4  = t & 7;

    float acc[2][4][4];
#pragma unroll
    for (int mi = 0; mi < 2; ++mi)
#pragma unroll
        for (int ni = 0; ni < 4; ++ni)
#pragma unroll
            for (int r = 0; r < 4; ++r) acc[mi][ni][r] = 0.f;

    uint32_t Qs_u = smem_u32(Qs);
    uint32_t Cs_u = smem_u32(Cs);

#pragma unroll
    for (int i = 0; i < 4; ++i) {
        int row = i * 32 + lrow;
        cp_async16(Qs_u + (row * OQ_PITCH + lcol) * 4, Qg + (long)row * MM + lcol);
    }
#pragma unroll
    for (int i = 0; i < 2; ++i)
        cp_async16(Cs_u + (crow * OC_PITCH + (cc4 + i * 8) * 4) * 4,
                   Cg + (long)crow * DD + (cc4 + i * 8) * 4);
    cp_commit();

#pragma unroll 1
    for (int c = 0; c < 8; ++c) {
        cp_wait<0>();
        __syncthreads();
        if (c < 7) {
            const int kof = (c + 1) * 32;
            const uint32_t qb = ((c + 1) & 1) * OQ_BUF * 4;
            const uint32_t cb = ((c + 1) & 1) * OC_BUF * 4;
#pragma unroll
            for (int i = 0; i < 4; ++i) {
                int row = i * 32 + lrow;
                cp_async16(Qs_u + qb + (row * OQ_PITCH + lcol) * 4,
                           Qg + (long)row * MM + kof + lcol);
            }
#pragma unroll
            for (int i = 0; i < 2; ++i)
                cp_async16(Cs_u + cb + (crow * OC_PITCH + (cc4 + i * 8) * 4) * 4,
                           Cg + (long)(kof + crow) * DD + (cc4 + i * 8) * 4);
            cp_commit();
        }

        const float* Qb = Qs + (c & 1) * OQ_BUF;
        const float* Cb = Cs + (c & 1) * OC_BUF;

#pragma unroll
        for (int ks = 0; ks < 4; ++ks) {
            const int k0 = ks * 8;
            uint32_t a[2][4];
#pragma unroll
            for (int mi = 0; mi < 2; ++mi) {
                int n = wn * 32 + mi * 16 + grp;
                a[mi][0] = __float_as_uint(Qb[n * OQ_PITCH + k0 + tig]);
                a[mi][1] = __float_as_uint(Qb[(n + 8) * OQ_PITCH + k0 + tig]);
                a[mi][2] = __float_as_uint(Qb[n * OQ_PITCH + k0 + tig + 4]);
                a[mi][3] = __float_as_uint(Qb[(n + 8) * OQ_PITCH + k0 + tig + 4]);
            }
            uint32_t b[4][2];
#pragma unroll
            for (int ni = 0; ni < 4; ++ni) {
                int e = we * 32 + ni * 8 + grp;
                b[ni][0] = to_tf32_u(Cb[(k0 + tig) * OC_PITCH + e]);
                b[ni][1] = to_tf32_u(Cb[(k0 + tig + 4) * OC_PITCH + e]);
            }
#pragma unroll
            for (int mi = 0; mi < 2; ++mi)
#pragma unroll
                for (int ni = 0; ni < 4; ++ni)
                    mma_tf32_16x8x8(acc[mi][ni], a[mi], b[ni]);
        }
    }

#pragma unroll
    for (int mi = 0; mi < 2; ++mi) {
        long n = n0 + wn * 32 + mi * 16 + grp;
        float dv0 = dinv[(long)h * NN + n];
        float dv1 = dinv[(long)h * NN + n + 8];
#pragma unroll
        for (int ni = 0; ni < 4; ++ni) {
            int e = we * 32 + ni * 8 + tig * 2;
            *(float2*)(out + ((long)h * NN + n) * DD + e) =
                make_float2(acc[mi][ni][0] * dv0, acc[mi][ni][1] * dv0);
            *(float2*)(out + ((long)h * NN + n + 8) * DD + e) =
                make_float2(acc[mi][ni][2] * dv1, acc[mi][ni][3] * dv1);
        }
    }
}

// ---------------- exp / dinv ----------------------------------------------------
__global__ void expq_kernel(float* __restrict__ dash, const float* __restrict__ diag,
                            __half* __restrict__ dash_h) {
    int row  = blockIdx.x * 8 + (threadIdx.x >> 5);
    int lane = threadIdx.x & 31;
    long base = (long)row * MM;
    float4 a = *(float4*)(dash + base + lane * 4);
    float4 b = *(float4*)(dash + base + 128 + lane * 4);
    float m = fmaxf(fmaxf(fmaxf(a.x, a.y), fmaxf(a.z, a.w)),
                    fmaxf(fmaxf(b.x, b.y), fmaxf(b.z, b.w)));
#pragma unroll
    for (int o = 16; o; o >>= 1) m = fmaxf(m, __shfl_xor_sync(0xffffffffu, m, o));
    float s = diag[row] + m;
    float4 ea, eb;
    ea.x = RATIO * (__expf(a.x - s) + FEPS);
    ea.y = RATIO * (__expf(a.y - s) + FEPS);
    ea.z = RATIO * (__expf(a.z - s) + FEPS);
    ea.w = RATIO * (__expf(a.w - s) + FEPS);
    eb.x = RATIO * (__expf(b.x - s) + FEPS);
    eb.y = RATIO * (__expf(b.y - s) + FEPS);
    eb.z = RATIO * (__expf(b.z - s) + FEPS);
    eb.w = RATIO * (__expf(b.w - s) + FEPS);
    float4 ta = make_float4(to_tf32(ea.x), to_tf32(ea.y), to_tf32(ea.z), to_tf32(ea.w));
    float4 tb = make_float4(to_tf32(eb.x), to_tf32(eb.y), to_tf32(eb.z), to_tf32(eb.w));
    *(float4*)(dash + base + lane * 4)       = ta;
    *(float4*)(dash + base + 128 + lane * 4) = tb;
    __half2* hp0 = (__half2*)(dash_h + base + lane * 4);
    __half2* hp1 = (__half2*)(dash_h + base + 128 + lane * 4);
    hp0[0] = __floats2half2_rn(ea.x * HSCALE, ea.y * HSCALE);
    hp0[1] = __floats2half2_rn(ea.z * HSCALE, ea.w * HSCALE);
    hp1[0] = __floats2half2_rn(eb.x * HSCALE, eb.y * HSCALE);
    hp1[1] = __floats2half2_rn(eb.z * HSCALE, eb.w * HSCALE);
}

__global__ void expk_kernel(float* __restrict__ dash, const float* __restrict__ diag,
                            const unsigned* __restrict__ kmax_enc, float* __restrict__ ksum,
                            __half* __restrict__ dash_h) {
    int t    = threadIdx.x;
    int row0 = blockIdx.x * 32;
    int h    = row0 >> 12;
    float stab  = dec_f(kmax_enc[0]);
    float local = 0.f;
    for (int r = 0; r < 32; ++r) {
        long idx = (long)(row0 + r) * MM + t;
        float vfull = RATIO * (__expf(dash[idx] - diag[row0 + r] - stab) + FEPS);
        float vv = to_tf32(vfull);
        dash[idx]   = vv;
        dash_h[idx] = __float2half_rn(vfull * HSCALE);
        local += vv;
    }
    atomicAdd(&ksum[h * MM + t], local);
}

__global__ void dinv_kernel(const float* __restrict__ qp, const float* __restrict__ ksum,
                            float* __restrict__ dinv) {
    int row  = blockIdx.x * 8 + (threadIdx.x >> 5);
    int lane = threadIdx.x & 31;
    int h    = row >> 12;
    const float* qr = qp + (long)row * MM;
    const float* ks = ksum + h * MM;
    float s = 0.f;
#pragma unroll
    for (int i = 0; i < 8; ++i) {
        int m = lane + i * 32;
        s += qr[m] * ks[m];
    }
#pragma unroll
    for (int o = 16; o; o >>= 1) s += __shfl_xor_sync(0xffffffffu, s, o);
    if (!lane) dinv[row] = 1.f / s;
}

// -------------------------------------------------------------------------------
extern "C" void kernel_launch(void* const* d_in, const int* in_sizes, int n_in,
                              void* d_out, int out_size)
{
    const float* q    = (const float*)d_in[0];
    const float* k    = (const float*)d_in[1];
    const float* v    = (const float*)d_in[2];
    const float* proj = (const float*)d_in[3];

    float* out_align = (float*)d_out;                       // [H,N,D]
    float* out_w     = out_align + (long)HH * NN * DD;      // [H,N,N]

    float *qp, *kp, *qdiag, *kdiag, *ksum, *dinv, *ctx;
    __half *qph, *kph;
    unsigned *kmaxe;
    cudaGetSymbolAddress((void**)&qp,    g_qp);
    cudaGetSymbolAddress((void**)&kp,    g_kp);
    cudaGetSymbolAddress((void**)&qph,   g_qph);
    cudaGetSymbolAddress((void**)&kph,   g_kph);
    cudaGetSymbolAddress((void**)&qdiag, g_qdiag);
    cudaGetSymbolAddress((void**)&kdiag, g_kdiag);
    cudaGetSymbolAddress((void**)&ksum,  g_ksum);
    cudaGetSymbolAddress((void**)&dinv,  g_dinv);
    cudaGetSymbolAddress((void**)&ctx,   g_ctx);
    cudaGetSymbolAddress((void**)&kmaxe, g_kmax_enc);

    static cudaStream_t s2 = nullptr;
    static cudaEvent_t  ev1, ev2, ev3, ev4;
    static bool attr_done = false;
    if (!attr_done) {
        cudaFuncSetAttribute(weights_mma, cudaFuncAttributeMaxDynamicSharedMemorySize, WF_SMEM);
        cudaFuncSetAttribute(proj_mma,    cudaFuncAttributeMaxDynamicSharedMemorySize, PJ_SMEM);
        cudaFuncSetAttribute(ctx_mma,     cudaFuncAttributeMaxDynamicSharedMemorySize, CTX_SMEM);
        cudaFuncSetAttribute(out_mma,     cudaFuncAttributeMaxDynamicSharedMemorySize, OUT_SMEM);
        cudaStreamCreateWithFlags(&s2, cudaStreamNonBlocking);
        cudaEventCreateWithFlags(&ev1, cudaEventDisableTiming);
        cudaEventCreateWithFlags(&ev2, cudaEventDisableTiming);
        cudaEventCreateWithFlags(&ev3, cudaEventDisableTiming);
        cudaEventCreateWithFlags(&ev4, cudaEventDisableTiming);
        attr_done = true;
    }

    zero_kernel<<<HH * MM * DD / 256, 256>>>();

    // fork: q-chain on s2, k-chain on main, running concurrently
    cudaEventRecord(ev1, 0);
    cudaStreamWaitEvent(s2, ev1, 0);

    proj_mma<<<dim3(ROWS / 128, MM / 64), 256, PJ_SMEM, s2>>>(q, proj, qp, qdiag, nullptr);
    expq_kernel<<<ROWS / 8, 256, 0, s2>>>(qp, qdiag, qph);
    cudaEventRecord(ev3, s2);

    proj_mma<<<dim3(ROWS / 128, MM / 64), 256, PJ_SMEM>>>(k, proj, kp, kdiag, kmaxe);
    expk_kernel<<<ROWS / 32, 256>>>(kp, kdiag, kmaxe, ksum, kph);
    cudaEventRecord(ev4, 0);

    // join: weights needs qph (s2) + kph (main)
    cudaStreamWaitEvent(0, ev3, 0);
    weights_mma<<<dim3(NN / 128, NN / 128, HH), 256, WF_SMEM>>>(qph, kph, out_w);

    // side chain on s2: needs both chains (ev4 covers k-chain; s2 already ran q-chain)
    cudaStreamWaitEvent(s2, ev4, 0);
    ctx_mma<<<dim3(1, CTX_KSPLIT, HH), 256, CTX_SMEM, s2>>>(kp, v, ctx);
    dinv_kernel<<<ROWS / 8, 256, 0, s2>>>(qp, ksum, dinv);
    out_mma<<<dim3(NN / 128, HH), 256, OUT_SMEM, s2>>>(qp, ctx, dinv, out_align);

    cudaEventRecord(ev2, s2);
    cudaStreamWaitEvent(0, ev2, 0);
}